// round 10
// baseline (speedup 1.0000x reference)
#include <cuda_runtime.h>
#include <cuda_bf16.h>
#include <math.h>
#include <stdint.h>

#define SEQ   1024
#define DM    1024
#define HN    16
#define HDIM  64
#define NSAMP 8
#define INTER 768
#define BATCH 4
#define EPS   1e-5f

typedef __nv_bfloat16 bf16;

// ---------------- scratch (device globals; no allocations allowed) ----------
__device__ float g_hsmean[BATCH * DM];
__device__ float g_partial[BATCH * 16 * DM];
__device__ int   g_expert[NSAMP];
__device__ int   g_need[8];
__device__ float g_w[NSAMP];
__device__ bf16  g_hb[(size_t)BATCH * SEQ * DM];
__device__ bf16  g_qkvb[(size_t)NSAMP * SEQ * 3 * DM];       // 48 MB
__device__ bf16  g_ctxb[(size_t)NSAMP * SEQ * DM];           // 16 MB
__device__ float g_ao[(size_t)NSAMP * SEQ * DM];             // 32 MB (holds x+ao)
__device__ float g_x1[(size_t)NSAMP * SEQ * DM];             // 32 MB
__device__ bf16  g_x1b[(size_t)NSAMP * SEQ * DM];            // 16 MB
__device__ bf16  g_actb[(size_t)NSAMP * SEQ * INTER];        // 12 MB
__device__ float g_mlp[(size_t)NSAMP * SEQ * DM];            // 32 MB (holds x1+mlp)
// all-expert bf16 weights (gu stored column-interleaved: 2i=gate_i, 2i+1=up_i)
#define WB_QKV 0LL
#define WB_WO  25165824LL
#define WB_GU  33554432LL
#define WB_WD  46137344LL
#define WB_TOTAL 52428800LL
__device__ bf16 g_wb[WB_TOTAL];                              // 105 MB

// ---------------- small helpers ----------------------------------------------
__device__ __forceinline__ float block_reduce_sum(float v, float* sh) {
    int tid = threadIdx.x;
    #pragma unroll
    for (int o = 16; o; o >>= 1) v += __shfl_down_sync(0xFFFFFFFFu, v, o);
    if ((tid & 31) == 0) sh[tid >> 5] = v;
    __syncthreads();
    float r = 0.f;
    if (tid < 32) {
        float x = (tid < (int)(blockDim.x >> 5)) ? sh[tid] : 0.f;
        #pragma unroll
        for (int o = 16; o; o >>= 1) x += __shfl_down_sync(0xFFFFFFFFu, x, o);
        if (tid == 0) sh[0] = x;
    }
    __syncthreads();
    r = sh[0];
    __syncthreads();
    return r;
}

__device__ __forceinline__ void mma_bf16(float* d, const uint32_t* a, const uint32_t* b) {
    asm volatile(
        "mma.sync.aligned.m16n8k16.row.col.f32.bf16.bf16.f32 "
        "{%0,%1,%2,%3},{%4,%5,%6,%7},{%8,%9},{%0,%1,%2,%3};"
        : "+f"(d[0]), "+f"(d[1]), "+f"(d[2]), "+f"(d[3])
        : "r"(a[0]), "r"(a[1]), "r"(a[2]), "r"(a[3]), "r"(b[0]), "r"(b[1]));
}

__device__ __forceinline__ void ldsm_x4(uint32_t* r, uint32_t addr) {
    asm volatile(
        "ldmatrix.sync.aligned.m8n8.x4.shared.b16 {%0,%1,%2,%3}, [%4];"
        : "=r"(r[0]), "=r"(r[1]), "=r"(r[2]), "=r"(r[3]) : "r"(addr));
}
__device__ __forceinline__ void ldsm_x2t(uint32_t* r, uint32_t addr) {
    asm volatile(
        "ldmatrix.sync.aligned.m8n8.x2.trans.shared.b16 {%0,%1}, [%2];"
        : "=r"(r[0]), "=r"(r[1]) : "r"(addr));
}
__device__ __forceinline__ uint32_t lds32(uint32_t a) {
    uint32_t v;
    asm volatile("ld.shared.b32 %0, [%1];" : "=r"(v) : "r"(a));
    return v;
}
__device__ __forceinline__ uint32_t packbf(float hi, float lo) {
    uint32_t r;
    asm("cvt.rn.bf16x2.f32 %0, %1, %2;" : "=r"(r) : "f"(hi), "f"(lo));
    return r;
}

__device__ __forceinline__ void cp16(uint32_t s, const void* g) {
    asm volatile("cp.async.cg.shared.global [%0], [%1], 16;" :: "r"(s), "l"(g));
}
__device__ __forceinline__ void cp_commit() {
    asm volatile("cp.async.commit_group;" ::: "memory");
}
__device__ __forceinline__ void cp_wait0() {
    asm volatile("cp.async.wait_group 0;" ::: "memory");
}
__device__ __forceinline__ void cp_wait1() {
    asm volatile("cp.async.wait_group 1;" ::: "memory");
}

// ---------------- fp32 -> bf16 conversion ------------------------------------
__global__ void cvt_bf16(const float4* __restrict__ s, uint2* __restrict__ d, int n4) {
    int i = blockIdx.x * blockDim.x + threadIdx.x;
    if (i < n4) {
        float4 v = s[i];
        uint2 o;
        o.x = packbf(v.y, v.x);
        o.y = packbf(v.w, v.z);
        d[i] = o;
    }
}

// convert expert weights only if routed (g_need flag)
__global__ void cvt_w(const float4* __restrict__ s, uint2* __restrict__ d,
                      int n4, int perExp4) {
    int i = blockIdx.x * blockDim.x + threadIdx.x;
    if (i >= n4) return;
    if (!g_need[i / perExp4]) return;
    float4 v = s[i];
    uint2 o;
    o.x = packbf(v.y, v.x);
    o.y = packbf(v.w, v.z);
    d[i] = o;
}

// Wgu: convert + interleave columns (dst col 2i = gate_i, 2i+1 = up_i)
__global__ void cvt_wgu(const float* __restrict__ W, bf16* __restrict__ dst, int total) {
    int i = blockIdx.x * blockDim.x + threadIdx.x;
    if (i >= total) return;
    const int perE = DM * (INTER / 4);
    int e = i / perE;
    if (!g_need[e]) return;
    int rem = i % perE;
    int k = rem / (INTER / 4);
    int nq = rem % (INTER / 4);
    const float* row = W + ((size_t)e * DM + k) * (2 * INTER);
    float4 gv = *(const float4*)(row + nq * 4);
    float4 uv = *(const float4*)(row + INTER + nq * 4);
    uint4 o;
    o.x = packbf(uv.x, gv.x);
    o.y = packbf(uv.y, gv.y);
    o.z = packbf(uv.z, gv.z);
    o.w = packbf(uv.w, gv.w);
    *(uint4*)(dst + ((size_t)e * DM + k) * (2 * INTER) + nq * 8) = o;
}

// ---------------- routing ----------------------------------------------------
__global__ void mean1_kernel(const float* __restrict__ hidden) {
    int b = blockIdx.x, c = blockIdx.y;
    int tid = threadIdx.x;
    float acc[4] = {0.f, 0.f, 0.f, 0.f};
    for (int s = c * 64; s < c * 64 + 64; s++) {
        const float* row = hidden + ((size_t)b * SEQ + s) * DM;
        #pragma unroll
        for (int i = 0; i < 4; i++) acc[i] += row[tid + i * 256];
    }
    #pragma unroll
    for (int i = 0; i < 4; i++)
        g_partial[((size_t)b * 16 + c) * DM + tid + i * 256] = acc[i];
}

__global__ void mean2_kernel() {
    int b = blockIdx.x;
    int tid = threadIdx.x;
    #pragma unroll
    for (int i = 0; i < 4; i++) {
        int d = tid + i * 256;
        float s = 0.f;
        for (int c = 0; c < 16; c++) s += g_partial[((size_t)b * 16 + c) * DM + d];
        g_hsmean[b * DM + d] = s * (1.0f / (float)SEQ);
    }
}

__global__ void routing_kernel(const float* __restrict__ Wr,
                               const float* __restrict__ temperature,
                               float* __restrict__ out_logits) {
    int tid = threadIdx.x;          // 1024
    int w = tid >> 5, lane = tid & 31;
    int b = w >> 3, c = w & 7;
    float s = 0.f;
    for (int d = lane; d < DM; d += 32)
        s += g_hsmean[b * DM + d] * Wr[c * DM + d];
    #pragma unroll
    for (int o = 16; o; o >>= 1) s += __shfl_down_sync(0xFFFFFFFFu, s, o);
    __shared__ float logits[32];
    if (lane == 0) logits[w] = s;
    if (tid < 8) g_need[tid] = 0;
    __syncthreads();
    if (tid < BATCH) {
        float t = fminf(fmaxf(temperature[0], 0.1f), 10.0f);
        float lv[8];
        #pragma unroll
        for (int cc = 0; cc < 8; cc++) {
            lv[cc] = logits[tid * 8 + cc] / t;
            out_logits[tid * 8 + cc] = lv[cc];
        }
        int i0 = 0;
        #pragma unroll
        for (int cc = 1; cc < 8; cc++) if (lv[cc] > lv[i0]) i0 = cc;
        int i1 = -1;
        #pragma unroll
        for (int cc = 0; cc < 8; cc++) {
            if (cc == i0) continue;
            if (i1 < 0 || lv[cc] > lv[i1]) i1 = cc;
        }
        float e = expf(lv[i1] - lv[i0]);
        g_expert[2 * tid]     = i0;
        g_expert[2 * tid + 1] = i1;
        g_w[2 * tid]     = 1.0f / (1.0f + e);
        g_w[2 * tid + 1] = e / (1.0f + e);
        g_need[i0] = 1;
        g_need[i1] = 1;
    }
}

// ---------------- bf16 tensor-core GEMM ----------------------------------------
// BM=BN=128, BK=64, 3-stage cp.async, 2 CTA/SM.
// MODE 1: bf16 out. MODE 2: fused silu(gate)*up, interleaved cols -> bf16 act.
// MODE 3: fp32 out + fp32 residual add.
#define ASTG 144
#define BSTG 272
#define ABYTES (128 * ASTG)
#define BBYTES (64 * BSTG)
#define STGB (ABYTES + BBYTES)
#define GEMM_SMEM (3 * STGB)

template<int MODE>
__global__ __launch_bounds__(256, 2) void gemm_bf(
    const bf16* __restrict__ Ab, const bf16* __restrict__ Bb, void* __restrict__ Cb,
    int N, int K, int lda, long long strideA, int a_div2, long long strideC,
    const float* __restrict__ Res, int r_div2)
{
    extern __shared__ char smraw[];
    uint32_t sb = (uint32_t)__cvta_generic_to_shared(smraw);
    int z = blockIdx.z;
    const bf16* A = Ab + (size_t)(a_div2 ? (z >> 1) : z) * strideA;
    const bf16* B = Bb + (long long)g_expert[z] * ((long long)K * N);
    int m0 = blockIdx.y * 128;
    int n0 = blockIdx.x * 128;
    int tid = threadIdx.x, lane = tid & 31, wid = tid >> 5;
    int wm0 = (wid & 1) * 64;
    int wn0 = (wid >> 1) * 32;
    int g = lane >> 2, t = lane & 3;

    auto load_tile = [&](int k0, int buf) {
        uint32_t base = sb + (uint32_t)(buf * STGB);
        #pragma unroll
        for (int p = 0; p < 4; p++) {
            int i = tid + p * 256;
            int row = i >> 3, ch = i & 7;
            cp16(base + (uint32_t)(row * ASTG + ch * 16),
                 A + (size_t)(m0 + row) * lda + k0 + ch * 8);
        }
        #pragma unroll
        for (int p = 0; p < 4; p++) {
            int i = tid + p * 256;
            int row = i >> 4, ch = i & 15;
            cp16(base + (uint32_t)(ABYTES + row * BSTG + ch * 16),
                 B + (size_t)(k0 + row) * N + n0 + ch * 8);
        }
    };

    int NT = K / 64;
    load_tile(0, 0);
    cp_commit();
    load_tile(64, 1);
    cp_commit();

    float acc[4][4][4];
    #pragma unroll
    for (int i = 0; i < 4; i++)
        #pragma unroll
        for (int j = 0; j < 4; j++)
            #pragma unroll
            for (int q = 0; q < 4; q++) acc[i][j][q] = 0.f;

    uint32_t af[2][4][4];
    uint32_t bfr[2][4][2];

    int buf = 0;
    for (int tI = 0; tI < NT; ++tI) {
        if (tI + 1 < NT) cp_wait1(); else cp_wait0();
        __syncthreads();
        if (tI + 2 < NT) {
            int nb = buf + 2; if (nb >= 3) nb -= 3;
            load_tile((tI + 2) * 64, nb);
            cp_commit();
        }
        uint32_t stage = sb + (uint32_t)(buf * STGB);
        uint32_t aB = stage + (uint32_t)((wm0 + (lane & 15)) * ASTG + (lane >> 4) * 16);
        uint32_t bB = stage + (uint32_t)(ABYTES + (lane & 15) * BSTG + wn0 * 2);

        #pragma unroll
        for (int i = 0; i < 4; i++) ldsm_x4(af[0][i], aB + (uint32_t)(i * 16 * ASTG));
        #pragma unroll
        for (int j = 0; j < 4; j++) ldsm_x2t(bfr[0][j], bB + (uint32_t)(j * 16));

        #pragma unroll
        for (int ks = 0; ks < 4; ks++) {
            int cb = ks & 1, nb2 = cb ^ 1;
            if (ks < 3) {
                #pragma unroll
                for (int i = 0; i < 4; i++)
                    ldsm_x4(af[nb2][i], aB + (uint32_t)(i * 16 * ASTG + (ks + 1) * 32));
                #pragma unroll
                for (int j = 0; j < 4; j++)
                    ldsm_x2t(bfr[nb2][j], bB + (uint32_t)((ks + 1) * 16 * BSTG + j * 16));
            }
            #pragma unroll
            for (int i = 0; i < 4; i++)
                #pragma unroll
                for (int j = 0; j < 4; j++)
                    mma_bf16(acc[i][j], af[cb][i], bfr[cb][j]);
        }
        buf++; if (buf == 3) buf = 0;
    }

    #pragma unroll
    for (int i = 0; i < 4; i++) {
        #pragma unroll
        for (int j = 0; j < 4; j++) {
            int r = m0 + wm0 + i * 16 + g;
            int c = n0 + wn0 + j * 8 + 2 * t;
            if (MODE == 1) {
                bf16* C = (bf16*)Cb + (size_t)z * strideC;
                *(uint32_t*)(C + (size_t)r * N + c) = packbf(acc[i][j][1], acc[i][j][0]);
                *(uint32_t*)(C + (size_t)(r + 8) * N + c) = packbf(acc[i][j][3], acc[i][j][2]);
            } else if (MODE == 2) {
                bf16* C = (bf16*)Cb + (size_t)z * strideC;
                int oc = c >> 1;
                float g0 = acc[i][j][0], u0 = acc[i][j][1];
                float g1 = acc[i][j][2], u1 = acc[i][j][3];
                float s0 = g0 / (1.0f + __expf(-g0)) * u0;
                float s1 = g1 / (1.0f + __expf(-g1)) * u1;
                C[(size_t)r * (N / 2) + oc]       = __float2bfloat16(s0);
                C[(size_t)(r + 8) * (N / 2) + oc] = __float2bfloat16(s1);
            } else {  // MODE 3: fp32 + residual
                float* C = (float*)Cb + (size_t)z * strideC;
                const float* R = Res + (size_t)(r_div2 ? (z >> 1) : z) * strideC;
                float2 r0 = *(const float2*)(R + (size_t)r * N + c);
                float2 r1 = *(const float2*)(R + (size_t)(r + 8) * N + c);
                *(float2*)(C + (size_t)r * N + c) =
                    make_float2(acc[i][j][0] + r0.x, acc[i][j][1] + r0.y);
                *(float2*)(C + (size_t)(r + 8) * N + c) =
                    make_float2(acc[i][j][2] + r1.x, acc[i][j][3] + r1.y);
            }
        }
    }
}

// ---------------- RoPE (in-place on bf16 q,k) ---------------------------------
__global__ void rope_kernel(const float* __restrict__ cosb, const float* __restrict__ sinb) {
    int s = blockIdx.x, n = blockIdx.y;
    int tid = threadIdx.x;            // 512
    int h = tid >> 5, j = tid & 31;
    float c0 = cosb[s * HDIM + j],      s0 = sinb[s * HDIM + j];
    float c1 = cosb[s * HDIM + j + 32], s1 = sinb[s * HDIM + j + 32];
    bf16* row = g_qkvb + ((size_t)n * SEQ + s) * (3 * DM);
    bf16* q = row + h * HDIM;
    float qa = __bfloat162float(q[j]), qb = __bfloat162float(q[j + 32]);
    q[j]      = __float2bfloat16(qa * c0 - qb * s0);
    q[j + 32] = __float2bfloat16(qb * c1 + qa * s1);
    bf16* k = row + DM + h * HDIM;
    float ka = __bfloat162float(k[j]), kb = __bfloat162float(k[j + 32]);
    k[j]      = __float2bfloat16(ka * c0 - kb * s0);
    k[j + 32] = __float2bfloat16(kb * c1 + ka * s1);
}

// ---------------- flash attention (bf16 mma, Q tile 128 rows) -------------------
#define FQ 0
#define FK 18432
#define FV (18432 + 2 * 9216)
#define FLASH_SMEM (18432 + 4 * 9216)

__global__ __launch_bounds__(256) void flash_kernel() {
    extern __shared__ char smraw[];
    uint32_t sb = (uint32_t)__cvta_generic_to_shared(smraw);

    int nh = blockIdx.y;
    int n = nh >> 4, h = nh & 15;
    int q0 = blockIdx.x * 128;
    const bf16* qbase = g_qkvb + (size_t)n * SEQ * (3 * DM) + h * HDIM;
    const bf16* kbase = qbase + DM;
    const bf16* vbase = qbase + 2 * DM;

    int tid = threadIdx.x, lane = tid & 31, wid = tid >> 5;
    int g = lane >> 2, t = lane & 3;
    int wm0 = wid * 16;           // 8 warps x 16 rows = 128

    // initial loads: Q (128 rows) + K/V tile 0 (64 rows each)
    #pragma unroll
    for (int p = 0; p < 4; p++) {
        int i = tid + p * 256;
        int row = i >> 3, ch = i & 7;
        cp16(sb + (uint32_t)(FQ + row * 144 + ch * 16),
             qbase + (size_t)(q0 + row) * (3 * DM) + ch * 8);
    }
    #pragma unroll
    for (int p = 0; p < 2; p++) {
        int i = tid + p * 256;
        int row = i >> 3, ch = i & 7;
        cp16(sb + (uint32_t)(FK + row * 144 + ch * 16),
             kbase + (size_t)row * (3 * DM) + ch * 8);
        cp16(sb + (uint32_t)(FV + row * 144 + ch * 16),
             vbase + (size_t)row * (3 * DM) + ch * 8);
    }
    cp_commit();
    cp_wait0();
    __syncthreads();

    uint32_t qf[4][4];
    uint32_t qA = sb + (uint32_t)(FQ + (wm0 + (lane & 15)) * 144 + (lane >> 4) * 16);
    #pragma unroll
    for (int kc = 0; kc < 4; kc++) ldsm_x4(qf[kc], qA + (uint32_t)(kc * 32));

    float m0 = -INFINITY, m1 = -INFINITY, l0 = 0.f, l1 = 0.f;
    float oa[8][4];
    #pragma unroll
    for (int j = 0; j < 8; j++)
        #pragma unroll
        for (int q = 0; q < 4; q++) oa[j][q] = 0.f;

    const int NT = SEQ / 64;
    for (int it = 0; it < NT; it++) {
        int buf = it & 1;
        if (it + 1 < NT) {
            int kv = (it + 1) * 64;
            int ob = buf ^ 1;
            #pragma unroll
            for (int p = 0; p < 2; p++) {
                int i = tid + p * 256;
                int row = i >> 3, ch = i & 7;
                cp16(sb + (uint32_t)(FK + ob * 9216 + row * 144 + ch * 16),
                     kbase + (size_t)(kv + row) * (3 * DM) + ch * 8);
                cp16(sb + (uint32_t)(FV + ob * 9216 + row * 144 + ch * 16),
                     vbase + (size_t)(kv + row) * (3 * DM) + ch * 8);
            }
            cp_commit();
        }
        uint32_t kB = sb + (uint32_t)(FK + buf * 9216);
        uint32_t vB = sb + (uint32_t)(FV + buf * 9216);

        float sacc[8][4];
        #pragma unroll
        for (int j = 0; j < 8; j++)
            #pragma unroll
            for (int q = 0; q < 4; q++) sacc[j][q] = 0.f;

        #pragma unroll
        for (int kc = 0; kc < 4; kc++) {
            #pragma unroll
            for (int nt = 0; nt < 8; nt++) {
                uint32_t ba = kB + (uint32_t)((nt * 8 + g) * 144 + kc * 32 + t * 4);
                uint32_t bb[2];
                bb[0] = lds32(ba);
                bb[1] = lds32(ba + 16);
                mma_bf16(sacc[nt], qf[kc], bb);
            }
        }

        float rm0 = -INFINITY, rm1 = -INFINITY;
        #pragma unroll
        for (int nt = 0; nt < 8; nt++) {
            #pragma unroll
            for (int q = 0; q < 4; q++) sacc[nt][q] *= 0.125f;
            rm0 = fmaxf(rm0, fmaxf(sacc[nt][0], sacc[nt][1]));
            rm1 = fmaxf(rm1, fmaxf(sacc[nt][2], sacc[nt][3]));
        }
        rm0 = fmaxf(rm0, __shfl_xor_sync(0xFFFFFFFFu, rm0, 1));
        rm0 = fmaxf(rm0, __shfl_xor_sync(0xFFFFFFFFu, rm0, 2));
        rm1 = fmaxf(rm1, __shfl_xor_sync(0xFFFFFFFFu, rm1, 1));
        rm1 = fmaxf(rm1, __shfl_xor_sync(0xFFFFFFFFu, rm1, 2));
        float mn0 = fmaxf(m0, rm0), mn1 = fmaxf(m1, rm1);
        float c0 = __expf(m0 - mn0), c1 = __expf(m1 - mn1);
        float ls0 = 0.f, ls1 = 0.f;
        #pragma unroll
        for (int nt = 0; nt < 8; nt++) {
            sacc[nt][0] = __expf(sacc[nt][0] - mn0);
            sacc[nt][1] = __expf(sacc[nt][1] - mn0);
            sacc[nt][2] = __expf(sacc[nt][2] - mn1);
            sacc[nt][3] = __expf(sacc[nt][3] - mn1);
            ls0 += sacc[nt][0] + sacc[nt][1];
            ls1 += sacc[nt][2] + sacc[nt][3];
        }
        ls0 += __shfl_xor_sync(0xFFFFFFFFu, ls0, 1);
        ls0 += __shfl_xor_sync(0xFFFFFFFFu, ls0, 2);
        ls1 += __shfl_xor_sync(0xFFFFFFFFu, ls1, 1);
        ls1 += __shfl_xor_sync(0xFFFFFFFFu, ls1, 2);
        l0 = l0 * c0 + ls0;
        l1 = l1 * c1 + ls1;
        m0 = mn0; m1 = mn1;
        #pragma unroll
        for (int j = 0; j < 8; j++) {
            oa[j][0] *= c0; oa[j][1] *= c0;
            oa[j][2] *= c1; oa[j][3] *= c1;
        }

        #pragma unroll
        for (int mC = 0; mC < 4; mC++) {
            uint32_t pa[4];
            pa[0] = packbf(sacc[2 * mC][1],     sacc[2 * mC][0]);
            pa[1] = packbf(sacc[2 * mC][3],     sacc[2 * mC][2]);
            pa[2] = packbf(sacc[2 * mC + 1][1], sacc[2 * mC + 1][0]);
            pa[3] = packbf(sacc[2 * mC + 1][3], sacc[2 * mC + 1][2]);
            #pragma unroll
            for (int jn = 0; jn < 8; jn++) {
                uint32_t vb[2];
                ldsm_x2t(vb, vB + (uint32_t)((mC * 16 + (lane & 15)) * 144 + jn * 16));
                mma_bf16(oa[jn], pa, vb);
            }
        }

        cp_wait0();
        __syncthreads();
    }

    float inv0 = 1.0f / l0, inv1 = 1.0f / l1;
    int grow0 = q0 + wm0 + g;
    bf16* cbase = g_ctxb + (size_t)n * SEQ * DM + h * HDIM;
    #pragma unroll
    for (int jn = 0; jn < 8; jn++) {
        int col = jn * 8 + 2 * t;
        *(uint32_t*)(cbase + (size_t)grow0 * DM + col) =
            packbf(oa[jn][1] * inv0, oa[jn][0] * inv0);
        *(uint32_t*)(cbase + (size_t)(grow0 + 8) * DM + col) =
            packbf(oa[jn][3] * inv1, oa[jn][2] * inv1);
    }
}

// ---------------- rmsnorm of (x+ao) (already summed in Wo epilogue) ------------
__global__ void resid_rms_kernel() {
    __shared__ float sh[32];
    int ns = blockIdx.x;
    int n = ns >> 10, s = ns & 1023;
    int tid = threadIdx.x;           // 256
    int d0 = tid * 4;
    size_t base = ((size_t)n * SEQ + s) * DM;
    float4 y = *(const float4*)(g_ao + base + d0);
    float ss = y.x * y.x + y.y * y.y + y.z * y.z + y.w * y.w;
    ss = block_reduce_sum(ss, sh);
    float scale = rsqrtf(ss * (1.0f / (float)DM) + EPS);
    y.x *= scale; y.y *= scale; y.z *= scale; y.w *= scale;
    *(float4*)(g_x1 + base + d0) = y;
    uint2 o;
    o.x = packbf(y.y, y.x);
    o.y = packbf(y.w, y.z);
    *(uint2*)(g_x1b + base + d0) = o;
}

// ---------------- final: rmsnorm(x1+mlp) (sum done in Wd epilogue) --------------
__global__ void final_kernel(float* __restrict__ out) {
    __shared__ float sh[32];
    int bs = blockIdx.x;
    int b = bs >> 10, s = bs & 1023;
    int tid = threadIdx.x;
    int n0 = 2 * b, n1 = 2 * b + 1;
    size_t base0 = ((size_t)n0 * SEQ + s) * DM;
    size_t base1 = ((size_t)n1 * SEQ + s) * DM;
    float y0[4], y1[4];
    float ss0 = 0.f, ss1 = 0.f;
    #pragma unroll
    for (int i = 0; i < 4; i++) {
        int d = tid + i * 256;
        y0[i] = g_mlp[base0 + d];
        y1[i] = g_mlp[base1 + d];
        ss0 = fmaf(y0[i], y0[i], ss0);
        ss1 = fmaf(y1[i], y1[i], ss1);
    }
    ss0 = block_reduce_sum(ss0, sh);
    ss1 = block_reduce_sum(ss1, sh);
    float r0 = rsqrtf(ss0 * (1.0f / (float)DM) + EPS) * g_w[n0];
    float r1 = rsqrtf(ss1 * (1.0f / (float)DM) + EPS) * g_w[n1];
    float* orow = out + ((size_t)b * SEQ + s) * DM;
    #pragma unroll
    for (int i = 0; i < 4; i++) {
        int d = tid + i * 256;
        orow[d] = y0[i] * r0 + y1[i] * r1;
    }
}

// ---------------- host launcher --------------------------------------------------
extern "C" void kernel_launch(void* const* d_in, const int* in_sizes, int n_in,
                              void* d_out, int out_size) {
    const float* hidden = (const float*)d_in[0];
    const float* cosb   = (const float*)d_in[1];
    const float* sinb   = (const float*)d_in[2];
    const float* Wr     = (const float*)d_in[3];
    const float* temp   = (const float*)d_in[4];
    const float* Wqkv   = (const float*)d_in[5];
    const float* Wo     = (const float*)d_in[6];
    const float* Wgu    = (const float*)d_in[7];
    const float* Wd     = (const float*)d_in[8];
    float* out = (float*)d_out;

    bf16 *p_hb, *p_qkvb, *p_ctxb, *p_x1b, *p_actb, *p_wb;
    float *p_ao, *p_x1, *p_mlp;
    cudaGetSymbolAddress((void**)&p_hb,   g_hb);
    cudaGetSymbolAddress((void**)&p_qkvb, g_qkvb);
    cudaGetSymbolAddress((void**)&p_ctxb, g_ctxb);
    cudaGetSymbolAddress((void**)&p_x1b,  g_x1b);
    cudaGetSymbolAddress((void**)&p_actb, g_actb);
    cudaGetSymbolAddress((void**)&p_wb,   g_wb);
    cudaGetSymbolAddress((void**)&p_ao,   g_ao);
    cudaGetSymbolAddress((void**)&p_x1,   g_x1);
    cudaGetSymbolAddress((void**)&p_mlp,  g_mlp);

    cudaFuncSetAttribute(flash_kernel,
                         cudaFuncAttributeMaxDynamicSharedMemorySize, FLASH_SMEM);
    cudaFuncSetAttribute((const void*)gemm_bf<1>,
                         cudaFuncAttributeMaxDynamicSharedMemorySize, GEMM_SMEM);
    cudaFuncSetAttribute((const void*)gemm_bf<2>,
                         cudaFuncAttributeMaxDynamicSharedMemorySize, GEMM_SMEM);
    cudaFuncSetAttribute((const void*)gemm_bf<3>,
                         cudaFuncAttributeMaxDynamicSharedMemorySize, GEMM_SMEM);

    // routing first (sets g_need for routed-only weight conversion)
    mean1_kernel<<<dim3(BATCH, 16), 256>>>(hidden);
    mean2_kernel<<<BATCH, 256>>>();
    routing_kernel<<<1, 1024>>>(Wr, temp, out + (size_t)BATCH * SEQ * DM);

    // bf16 conversions
    {
        int n4 = BATCH * SEQ * DM / 4;
        cvt_bf16<<<(n4 + 255) / 256, 256>>>((const float4*)hidden, (uint2*)p_hb, n4);
        n4 = 8 * DM * 3 * DM / 4;
        cvt_w<<<(n4 + 255) / 256, 256>>>((const float4*)Wqkv, (uint2*)(p_wb + WB_QKV),
                                         n4, DM * 3 * DM / 4);
        n4 = 8 * DM * DM / 4;
        cvt_w<<<(n4 + 255) / 256, 256>>>((const float4*)Wo, (uint2*)(p_wb + WB_WO),
                                         n4, DM * DM / 4);
        int tg = 8 * DM * (INTER / 4);
        cvt_wgu<<<(tg + 255) / 256, 256>>>(Wgu, p_wb + WB_GU, tg);
        n4 = 8 * INTER * DM / 4;
        cvt_w<<<(n4 + 255) / 256, 256>>>((const float4*)Wd, (uint2*)(p_wb + WB_WD),
                                         n4, INTER * DM / 4);
    }

    // qkv = x @ Wqkv[e]   (bf16 out)
    gemm_bf<1><<<dim3(3072 / 128, SEQ / 128, NSAMP), 256, GEMM_SMEM>>>(
        p_hb, p_wb + WB_QKV, p_qkvb, 3 * DM, DM, DM,
        (long long)SEQ * DM, 1, (long long)SEQ * 3 * DM, nullptr, 0);

    // rope in-place (bf16)
    rope_kernel<<<dim3(SEQ, NSAMP), 512>>>(cosb, sinb);

    // fused attention -> g_ctxb (bf16), Q tile 128
    flash_kernel<<<dim3(SEQ / 128, NSAMP * HN), 256, FLASH_SMEM>>>();

    // g_ao = hidden + ctx @ Wo[e]   (fp32 out + residual)
    gemm_bf<3><<<dim3(DM / 128, SEQ / 128, NSAMP), 256, GEMM_SMEM>>>(
        p_ctxb, p_wb + WB_WO, p_ao, DM, DM, DM,
        (long long)SEQ * DM, 0, (long long)SEQ * DM, hidden, 1);

    // x1 = rmsnorm(g_ao)
    resid_rms_kernel<<<NSAMP * SEQ, 256>>>();

    // act = silu(gate)*up fused into Wgu GEMM (interleaved weights)
    gemm_bf<2><<<dim3(2 * INTER / 128, SEQ / 128, NSAMP), 256, GEMM_SMEM>>>(
        p_x1b, p_wb + WB_GU, p_actb, 2 * INTER, DM, DM,
        (long long)SEQ * DM, 0, (long long)SEQ * INTER, nullptr, 0);

    // g_mlp = x1 + act @ Wd[e]   (fp32 out + residual)
    gemm_bf<3><<<dim3(DM / 128, SEQ / 128, NSAMP), 256, GEMM_SMEM>>>(
        p_actb, p_wb + WB_WD, p_mlp, DM, INTER, INTER,
        (long long)SEQ * INTER, 0, (long long)SEQ * DM, p_x1, 0);

    // out = sum of weighted rmsnorm(g_mlp)
    final_kernel<<<BATCH * SEQ, 256>>>(out);
}

// round 11
// speedup vs baseline: 1.0129x; 1.0129x over previous
#include <cuda_runtime.h>
#include <cuda_bf16.h>
#include <math.h>
#include <stdint.h>

#define SEQ   1024
#define DM    1024
#define HN    16
#define HDIM  64
#define NSAMP 8
#define INTER 768
#define BATCH 4
#define EPS   1e-5f

typedef __nv_bfloat16 bf16;

// ---------------- scratch (device globals; no allocations allowed) ----------
__device__ float g_hsmean[BATCH * DM];
__device__ float g_partial[BATCH * 16 * DM];
__device__ int   g_expert[NSAMP];
__device__ int   g_need[8];
__device__ float g_w[NSAMP];
__device__ bf16  g_hb[(size_t)BATCH * SEQ * DM];
__device__ bf16  g_qkvb[(size_t)NSAMP * SEQ * 3 * DM];       // 48 MB
__device__ bf16  g_ctxb[(size_t)NSAMP * SEQ * DM];           // 16 MB
__device__ float g_ao[(size_t)NSAMP * SEQ * DM];             // 32 MB (holds x+ao)
__device__ float g_x1[(size_t)NSAMP * SEQ * DM];             // 32 MB
__device__ bf16  g_x1b[(size_t)NSAMP * SEQ * DM];            // 16 MB
__device__ bf16  g_actb[(size_t)NSAMP * SEQ * INTER];        // 12 MB
__device__ float g_mlp[(size_t)NSAMP * SEQ * DM];            // 32 MB (holds x1+mlp)
// all-expert bf16 weights (gu stored column-interleaved: 2i=gate_i, 2i+1=up_i)
#define WB_QKV 0LL
#define WB_WO  25165824LL
#define WB_GU  33554432LL
#define WB_WD  46137344LL
#define WB_TOTAL 52428800LL
__device__ bf16 g_wb[WB_TOTAL];                              // 105 MB

// ---------------- small helpers ----------------------------------------------
__device__ __forceinline__ float block_reduce_sum(float v, float* sh) {
    int tid = threadIdx.x;
    #pragma unroll
    for (int o = 16; o; o >>= 1) v += __shfl_down_sync(0xFFFFFFFFu, v, o);
    if ((tid & 31) == 0) sh[tid >> 5] = v;
    __syncthreads();
    float r = 0.f;
    if (tid < 32) {
        float x = (tid < (int)(blockDim.x >> 5)) ? sh[tid] : 0.f;
        #pragma unroll
        for (int o = 16; o; o >>= 1) x += __shfl_down_sync(0xFFFFFFFFu, x, o);
        if (tid == 0) sh[0] = x;
    }
    __syncthreads();
    r = sh[0];
    __syncthreads();
    return r;
}

__device__ __forceinline__ void mma_bf16(float* d, const uint32_t* a, const uint32_t* b) {
    asm volatile(
        "mma.sync.aligned.m16n8k16.row.col.f32.bf16.bf16.f32 "
        "{%0,%1,%2,%3},{%4,%5,%6,%7},{%8,%9},{%0,%1,%2,%3};"
        : "+f"(d[0]), "+f"(d[1]), "+f"(d[2]), "+f"(d[3])
        : "r"(a[0]), "r"(a[1]), "r"(a[2]), "r"(a[3]), "r"(b[0]), "r"(b[1]));
}

__device__ __forceinline__ void ldsm_x4(uint32_t* r, uint32_t addr) {
    asm volatile(
        "ldmatrix.sync.aligned.m8n8.x4.shared.b16 {%0,%1,%2,%3}, [%4];"
        : "=r"(r[0]), "=r"(r[1]), "=r"(r[2]), "=r"(r[3]) : "r"(addr));
}
__device__ __forceinline__ void ldsm_x2t(uint32_t* r, uint32_t addr) {
    asm volatile(
        "ldmatrix.sync.aligned.m8n8.x2.trans.shared.b16 {%0,%1}, [%2];"
        : "=r"(r[0]), "=r"(r[1]) : "r"(addr));
}
__device__ __forceinline__ uint32_t lds32(uint32_t a) {
    uint32_t v;
    asm volatile("ld.shared.b32 %0, [%1];" : "=r"(v) : "r"(a));
    return v;
}
__device__ __forceinline__ uint32_t packbf(float hi, float lo) {
    uint32_t r;
    asm("cvt.rn.bf16x2.f32 %0, %1, %2;" : "=r"(r) : "f"(hi), "f"(lo));
    return r;
}

__device__ __forceinline__ void cp16(uint32_t s, const void* g) {
    asm volatile("cp.async.cg.shared.global [%0], [%1], 16;" :: "r"(s), "l"(g));
}
__device__ __forceinline__ void cp_commit() {
    asm volatile("cp.async.commit_group;" ::: "memory");
}
__device__ __forceinline__ void cp_wait0() {
    asm volatile("cp.async.wait_group 0;" ::: "memory");
}
__device__ __forceinline__ void cp_wait1() {
    asm volatile("cp.async.wait_group 1;" ::: "memory");
}

// ---------------- fp32 -> bf16 conversion ------------------------------------
__global__ void cvt_bf16(const float4* __restrict__ s, uint2* __restrict__ d, int n4) {
    int i = blockIdx.x * blockDim.x + threadIdx.x;
    if (i < n4) {
        float4 v = s[i];
        uint2 o;
        o.x = packbf(v.y, v.x);
        o.y = packbf(v.w, v.z);
        d[i] = o;
    }
}

// convert expert weights only if routed (g_need flag)
__global__ void cvt_w(const float4* __restrict__ s, uint2* __restrict__ d,
                      int n4, int perExp4) {
    int i = blockIdx.x * blockDim.x + threadIdx.x;
    if (i >= n4) return;
    if (!g_need[i / perExp4]) return;
    float4 v = s[i];
    uint2 o;
    o.x = packbf(v.y, v.x);
    o.y = packbf(v.w, v.z);
    d[i] = o;
}

// Wgu: convert + interleave columns (dst col 2i = gate_i, 2i+1 = up_i)
__global__ void cvt_wgu(const float* __restrict__ W, bf16* __restrict__ dst, int total) {
    int i = blockIdx.x * blockDim.x + threadIdx.x;
    if (i >= total) return;
    const int perE = DM * (INTER / 4);
    int e = i / perE;
    if (!g_need[e]) return;
    int rem = i % perE;
    int k = rem / (INTER / 4);
    int nq = rem % (INTER / 4);
    const float* row = W + ((size_t)e * DM + k) * (2 * INTER);
    float4 gv = *(const float4*)(row + nq * 4);
    float4 uv = *(const float4*)(row + INTER + nq * 4);
    uint4 o;
    o.x = packbf(uv.x, gv.x);
    o.y = packbf(uv.y, gv.y);
    o.z = packbf(uv.z, gv.z);
    o.w = packbf(uv.w, gv.w);
    *(uint4*)(dst + ((size_t)e * DM + k) * (2 * INTER) + nq * 8) = o;
}

// ---------------- routing ----------------------------------------------------
__global__ void mean1_kernel(const float* __restrict__ hidden) {
    int b = blockIdx.x, c = blockIdx.y;
    int tid = threadIdx.x;
    float acc[4] = {0.f, 0.f, 0.f, 0.f};
    for (int s = c * 64; s < c * 64 + 64; s++) {
        const float* row = hidden + ((size_t)b * SEQ + s) * DM;
        #pragma unroll
        for (int i = 0; i < 4; i++) acc[i] += row[tid + i * 256];
    }
    #pragma unroll
    for (int i = 0; i < 4; i++)
        g_partial[((size_t)b * 16 + c) * DM + tid + i * 256] = acc[i];
}

__global__ void mean2_kernel() {
    int b = blockIdx.x;
    int tid = threadIdx.x;
    #pragma unroll
    for (int i = 0; i < 4; i++) {
        int d = tid + i * 256;
        float s = 0.f;
        for (int c = 0; c < 16; c++) s += g_partial[((size_t)b * 16 + c) * DM + d];
        g_hsmean[b * DM + d] = s * (1.0f / (float)SEQ);
    }
}

__global__ void routing_kernel(const float* __restrict__ Wr,
                               const float* __restrict__ temperature,
                               float* __restrict__ out_logits) {
    int tid = threadIdx.x;          // 1024
    int w = tid >> 5, lane = tid & 31;
    int b = w >> 3, c = w & 7;
    float s = 0.f;
    for (int d = lane; d < DM; d += 32)
        s += g_hsmean[b * DM + d] * Wr[c * DM + d];
    #pragma unroll
    for (int o = 16; o; o >>= 1) s += __shfl_down_sync(0xFFFFFFFFu, s, o);
    __shared__ float logits[32];
    if (lane == 0) logits[w] = s;
    if (tid < 8) g_need[tid] = 0;
    __syncthreads();
    if (tid < BATCH) {
        float t = fminf(fmaxf(temperature[0], 0.1f), 10.0f);
        float lv[8];
        #pragma unroll
        for (int cc = 0; cc < 8; cc++) {
            lv[cc] = logits[tid * 8 + cc] / t;
            out_logits[tid * 8 + cc] = lv[cc];
        }
        int i0 = 0;
        #pragma unroll
        for (int cc = 1; cc < 8; cc++) if (lv[cc] > lv[i0]) i0 = cc;
        int i1 = -1;
        #pragma unroll
        for (int cc = 0; cc < 8; cc++) {
            if (cc == i0) continue;
            if (i1 < 0 || lv[cc] > lv[i1]) i1 = cc;
        }
        float e = expf(lv[i1] - lv[i0]);
        g_expert[2 * tid]     = i0;
        g_expert[2 * tid + 1] = i1;
        g_w[2 * tid]     = 1.0f / (1.0f + e);
        g_w[2 * tid + 1] = e / (1.0f + e);
        g_need[i0] = 1;
        g_need[i1] = 1;
    }
}

// ---------------- bf16 tensor-core GEMM ----------------------------------------
// BM=BN=128, BK=64, 3-stage cp.async, 2 CTA/SM.
// MODE 1: bf16 out. MODE 2: fused silu(gate)*up, interleaved cols -> bf16 act.
// MODE 3: fp32 out + fp32 residual add.
#define ASTG 144
#define BSTG 272
#define ABYTES (128 * ASTG)
#define BBYTES (64 * BSTG)
#define STGB (ABYTES + BBYTES)
#define GEMM_SMEM (3 * STGB)

template<int MODE>
__global__ __launch_bounds__(256, 2) void gemm_bf(
    const bf16* __restrict__ Ab, const bf16* __restrict__ Bb, void* __restrict__ Cb,
    int N, int K, int lda, long long strideA, int a_div2, long long strideC,
    const float* __restrict__ Res, int r_div2)
{
    extern __shared__ char smraw[];
    uint32_t sb = (uint32_t)__cvta_generic_to_shared(smraw);
    int z = blockIdx.z;
    const bf16* A = Ab + (size_t)(a_div2 ? (z >> 1) : z) * strideA;
    const bf16* B = Bb + (long long)g_expert[z] * ((long long)K * N);
    int m0 = blockIdx.y * 128;
    int n0 = blockIdx.x * 128;
    int tid = threadIdx.x, lane = tid & 31, wid = tid >> 5;
    int wm0 = (wid & 1) * 64;
    int wn0 = (wid >> 1) * 32;
    int g = lane >> 2, t = lane & 3;

    auto load_tile = [&](int k0, int buf) {
        uint32_t base = sb + (uint32_t)(buf * STGB);
        #pragma unroll
        for (int p = 0; p < 4; p++) {
            int i = tid + p * 256;
            int row = i >> 3, ch = i & 7;
            cp16(base + (uint32_t)(row * ASTG + ch * 16),
                 A + (size_t)(m0 + row) * lda + k0 + ch * 8);
        }
        #pragma unroll
        for (int p = 0; p < 4; p++) {
            int i = tid + p * 256;
            int row = i >> 4, ch = i & 15;
            cp16(base + (uint32_t)(ABYTES + row * BSTG + ch * 16),
                 B + (size_t)(k0 + row) * N + n0 + ch * 8);
        }
    };

    int NT = K / 64;
    load_tile(0, 0);
    cp_commit();
    load_tile(64, 1);
    cp_commit();

    float acc[4][4][4];
    #pragma unroll
    for (int i = 0; i < 4; i++)
        #pragma unroll
        for (int j = 0; j < 4; j++)
            #pragma unroll
            for (int q = 0; q < 4; q++) acc[i][j][q] = 0.f;

    uint32_t af[2][4][4];
    uint32_t bfr[2][4][2];

    int buf = 0;
    for (int tI = 0; tI < NT; ++tI) {
        if (tI + 1 < NT) cp_wait1(); else cp_wait0();
        __syncthreads();
        if (tI + 2 < NT) {
            int nb = buf + 2; if (nb >= 3) nb -= 3;
            load_tile((tI + 2) * 64, nb);
            cp_commit();
        }
        uint32_t stage = sb + (uint32_t)(buf * STGB);
        uint32_t aB = stage + (uint32_t)((wm0 + (lane & 15)) * ASTG + (lane >> 4) * 16);
        uint32_t bB = stage + (uint32_t)(ABYTES + (lane & 15) * BSTG + wn0 * 2);

        #pragma unroll
        for (int i = 0; i < 4; i++) ldsm_x4(af[0][i], aB + (uint32_t)(i * 16 * ASTG));
        #pragma unroll
        for (int j = 0; j < 4; j++) ldsm_x2t(bfr[0][j], bB + (uint32_t)(j * 16));

        #pragma unroll
        for (int ks = 0; ks < 4; ks++) {
            int cb = ks & 1, nb2 = cb ^ 1;
            if (ks < 3) {
                #pragma unroll
                for (int i = 0; i < 4; i++)
                    ldsm_x4(af[nb2][i], aB + (uint32_t)(i * 16 * ASTG + (ks + 1) * 32));
                #pragma unroll
                for (int j = 0; j < 4; j++)
                    ldsm_x2t(bfr[nb2][j], bB + (uint32_t)((ks + 1) * 16 * BSTG + j * 16));
            }
            #pragma unroll
            for (int i = 0; i < 4; i++)
                #pragma unroll
                for (int j = 0; j < 4; j++)
                    mma_bf16(acc[i][j], af[cb][i], bfr[cb][j]);
        }
        buf++; if (buf == 3) buf = 0;
    }

    #pragma unroll
    for (int i = 0; i < 4; i++) {
        #pragma unroll
        for (int j = 0; j < 4; j++) {
            int r = m0 + wm0 + i * 16 + g;
            int c = n0 + wn0 + j * 8 + 2 * t;
            if (MODE == 1) {
                bf16* C = (bf16*)Cb + (size_t)z * strideC;
                *(uint32_t*)(C + (size_t)r * N + c) = packbf(acc[i][j][1], acc[i][j][0]);
                *(uint32_t*)(C + (size_t)(r + 8) * N + c) = packbf(acc[i][j][3], acc[i][j][2]);
            } else if (MODE == 2) {
                bf16* C = (bf16*)Cb + (size_t)z * strideC;
                int oc = c >> 1;
                float g0 = acc[i][j][0], u0 = acc[i][j][1];
                float g1 = acc[i][j][2], u1 = acc[i][j][3];
                float s0 = g0 / (1.0f + __expf(-g0)) * u0;
                float s1 = g1 / (1.0f + __expf(-g1)) * u1;
                C[(size_t)r * (N / 2) + oc]       = __float2bfloat16(s0);
                C[(size_t)(r + 8) * (N / 2) + oc] = __float2bfloat16(s1);
            } else {  // MODE 3: fp32 + residual
                float* C = (float*)Cb + (size_t)z * strideC;
                const float* R = Res + (size_t)(r_div2 ? (z >> 1) : z) * strideC;
                float2 r0 = *(const float2*)(R + (size_t)r * N + c);
                float2 r1 = *(const float2*)(R + (size_t)(r + 8) * N + c);
                *(float2*)(C + (size_t)r * N + c) =
                    make_float2(acc[i][j][0] + r0.x, acc[i][j][1] + r0.y);
                *(float2*)(C + (size_t)(r + 8) * N + c) =
                    make_float2(acc[i][j][2] + r1.x, acc[i][j][3] + r1.y);
            }
        }
    }
}

// ---------------- RoPE (in-place on bf16 q,k) ---------------------------------
__global__ void rope_kernel(const float* __restrict__ cosb, const float* __restrict__ sinb) {
    int s = blockIdx.x, n = blockIdx.y;
    int tid = threadIdx.x;            // 512
    int h = tid >> 5, j = tid & 31;
    float c0 = cosb[s * HDIM + j],      s0 = sinb[s * HDIM + j];
    float c1 = cosb[s * HDIM + j + 32], s1 = sinb[s * HDIM + j + 32];
    bf16* row = g_qkvb + ((size_t)n * SEQ + s) * (3 * DM);
    bf16* q = row + h * HDIM;
    float qa = __bfloat162float(q[j]), qb = __bfloat162float(q[j + 32]);
    q[j]      = __float2bfloat16(qa * c0 - qb * s0);
    q[j + 32] = __float2bfloat16(qb * c1 + qa * s1);
    bf16* k = row + DM + h * HDIM;
    float ka = __bfloat162float(k[j]), kb = __bfloat162float(k[j + 32]);
    k[j]      = __float2bfloat16(ka * c0 - kb * s0);
    k[j + 32] = __float2bfloat16(kb * c1 + ka * s1);
}

// ---------------- flash attention (bf16 mma, Q tile 64, 128 thr) ----------------
#define FQ 0
#define FK 9216
#define FV (9216 * 3)
#define FLASH_SMEM (9216 * 5)

__global__ __launch_bounds__(128) void flash_kernel() {
    extern __shared__ char smraw[];
    uint32_t sb = (uint32_t)__cvta_generic_to_shared(smraw);

    int nh = blockIdx.y;
    int n = nh >> 4, h = nh & 15;
    int q0 = blockIdx.x * 64;
    const bf16* qbase = g_qkvb + (size_t)n * SEQ * (3 * DM) + h * HDIM;
    const bf16* kbase = qbase + DM;
    const bf16* vbase = qbase + 2 * DM;

    int tid = threadIdx.x, lane = tid & 31, wid = tid >> 5;
    int g = lane >> 2, t = lane & 3;
    int wm0 = wid * 16;

    #pragma unroll
    for (int p = 0; p < 4; p++) {
        int i = tid + p * 128;
        int row = i >> 3, ch = i & 7;
        cp16(sb + (uint32_t)(FQ + row * 144 + ch * 16),
             qbase + (size_t)(q0 + row) * (3 * DM) + ch * 8);
        cp16(sb + (uint32_t)(FK + row * 144 + ch * 16),
             kbase + (size_t)row * (3 * DM) + ch * 8);
        cp16(sb + (uint32_t)(FV + row * 144 + ch * 16),
             vbase + (size_t)row * (3 * DM) + ch * 8);
    }
    cp_commit();
    cp_wait0();
    __syncthreads();

    uint32_t qf[4][4];
    uint32_t qA = sb + (uint32_t)(FQ + (wm0 + (lane & 15)) * 144 + (lane >> 4) * 16);
    #pragma unroll
    for (int kc = 0; kc < 4; kc++) ldsm_x4(qf[kc], qA + (uint32_t)(kc * 32));

    float m0 = -INFINITY, m1 = -INFINITY, l0 = 0.f, l1 = 0.f;
    float oa[8][4];
    #pragma unroll
    for (int j = 0; j < 8; j++)
        #pragma unroll
        for (int q = 0; q < 4; q++) oa[j][q] = 0.f;

    const int NT = SEQ / 64;
    for (int it = 0; it < NT; it++) {
        int buf = it & 1;
        if (it + 1 < NT) {
            int kv = (it + 1) * 64;
            int ob = buf ^ 1;
            #pragma unroll
            for (int p = 0; p < 4; p++) {
                int i = tid + p * 128;
                int row = i >> 3, ch = i & 7;
                cp16(sb + (uint32_t)(FK + ob * 9216 + row * 144 + ch * 16),
                     kbase + (size_t)(kv + row) * (3 * DM) + ch * 8);
                cp16(sb + (uint32_t)(FV + ob * 9216 + row * 144 + ch * 16),
                     vbase + (size_t)(kv + row) * (3 * DM) + ch * 8);
            }
            cp_commit();
        }
        uint32_t kB = sb + (uint32_t)(FK + buf * 9216);
        uint32_t vB = sb + (uint32_t)(FV + buf * 9216);

        float sacc[8][4];
        #pragma unroll
        for (int j = 0; j < 8; j++)
            #pragma unroll
            for (int q = 0; q < 4; q++) sacc[j][q] = 0.f;

        #pragma unroll
        for (int kc = 0; kc < 4; kc++) {
            #pragma unroll
            for (int nt = 0; nt < 8; nt++) {
                uint32_t ba = kB + (uint32_t)((nt * 8 + g) * 144 + kc * 32 + t * 4);
                uint32_t bb[2];
                bb[0] = lds32(ba);
                bb[1] = lds32(ba + 16);
                mma_bf16(sacc[nt], qf[kc], bb);
            }
        }

        float rm0 = -INFINITY, rm1 = -INFINITY;
        #pragma unroll
        for (int nt = 0; nt < 8; nt++) {
            #pragma unroll
            for (int q = 0; q < 4; q++) sacc[nt][q] *= 0.125f;
            rm0 = fmaxf(rm0, fmaxf(sacc[nt][0], sacc[nt][1]));
            rm1 = fmaxf(rm1, fmaxf(sacc[nt][2], sacc[nt][3]));
        }
        rm0 = fmaxf(rm0, __shfl_xor_sync(0xFFFFFFFFu, rm0, 1));
        rm0 = fmaxf(rm0, __shfl_xor_sync(0xFFFFFFFFu, rm0, 2));
        rm1 = fmaxf(rm1, __shfl_xor_sync(0xFFFFFFFFu, rm1, 1));
        rm1 = fmaxf(rm1, __shfl_xor_sync(0xFFFFFFFFu, rm1, 2));
        float mn0 = fmaxf(m0, rm0), mn1 = fmaxf(m1, rm1);
        float c0 = __expf(m0 - mn0), c1 = __expf(m1 - mn1);
        float ls0 = 0.f, ls1 = 0.f;
        #pragma unroll
        for (int nt = 0; nt < 8; nt++) {
            sacc[nt][0] = __expf(sacc[nt][0] - mn0);
            sacc[nt][1] = __expf(sacc[nt][1] - mn0);
            sacc[nt][2] = __expf(sacc[nt][2] - mn1);
            sacc[nt][3] = __expf(sacc[nt][3] - mn1);
            ls0 += sacc[nt][0] + sacc[nt][1];
            ls1 += sacc[nt][2] + sacc[nt][3];
        }
        ls0 += __shfl_xor_sync(0xFFFFFFFFu, ls0, 1);
        ls0 += __shfl_xor_sync(0xFFFFFFFFu, ls0, 2);
        ls1 += __shfl_xor_sync(0xFFFFFFFFu, ls1, 1);
        ls1 += __shfl_xor_sync(0xFFFFFFFFu, ls1, 2);
        l0 = l0 * c0 + ls0;
        l1 = l1 * c1 + ls1;
        m0 = mn0; m1 = mn1;
        #pragma unroll
        for (int j = 0; j < 8; j++) {
            oa[j][0] *= c0; oa[j][1] *= c0;
            oa[j][2] *= c1; oa[j][3] *= c1;
        }

        #pragma unroll
        for (int mC = 0; mC < 4; mC++) {
            uint32_t pa[4];
            pa[0] = packbf(sacc[2 * mC][1],     sacc[2 * mC][0]);
            pa[1] = packbf(sacc[2 * mC][3],     sacc[2 * mC][2]);
            pa[2] = packbf(sacc[2 * mC + 1][1], sacc[2 * mC + 1][0]);
            pa[3] = packbf(sacc[2 * mC + 1][3], sacc[2 * mC + 1][2]);
            #pragma unroll
            for (int jn = 0; jn < 8; jn++) {
                uint32_t vb[2];
                ldsm_x2t(vb, vB + (uint32_t)((mC * 16 + (lane & 15)) * 144 + jn * 16));
                mma_bf16(oa[jn], pa, vb);
            }
        }

        cp_wait0();
        __syncthreads();
    }

    float inv0 = 1.0f / l0, inv1 = 1.0f / l1;
    int grow0 = q0 + wm0 + g;
    bf16* cbase = g_ctxb + (size_t)n * SEQ * DM + h * HDIM;
    #pragma unroll
    for (int jn = 0; jn < 8; jn++) {
        int col = jn * 8 + 2 * t;
        *(uint32_t*)(cbase + (size_t)grow0 * DM + col) =
            packbf(oa[jn][1] * inv0, oa[jn][0] * inv0);
        *(uint32_t*)(cbase + (size_t)(grow0 + 8) * DM + col) =
            packbf(oa[jn][3] * inv1, oa[jn][2] * inv1);
    }
}

// ---------------- rmsnorm of (x+ao) (already summed in Wo epilogue) ------------
__global__ void resid_rms_kernel() {
    __shared__ float sh[32];
    int ns = blockIdx.x;
    int n = ns >> 10, s = ns & 1023;
    int tid = threadIdx.x;           // 256
    int d0 = tid * 4;
    size_t base = ((size_t)n * SEQ + s) * DM;
    float4 y = *(const float4*)(g_ao + base + d0);
    float ss = y.x * y.x + y.y * y.y + y.z * y.z + y.w * y.w;
    ss = block_reduce_sum(ss, sh);
    float scale = rsqrtf(ss * (1.0f / (float)DM) + EPS);
    y.x *= scale; y.y *= scale; y.z *= scale; y.w *= scale;
    *(float4*)(g_x1 + base + d0) = y;
    uint2 o;
    o.x = packbf(y.y, y.x);
    o.y = packbf(y.w, y.z);
    *(uint2*)(g_x1b + base + d0) = o;
}

// ---------------- final: rmsnorm(x1+mlp) (sum done in Wd epilogue) --------------
__global__ void final_kernel(float* __restrict__ out) {
    __shared__ float sh[32];
    int bs = blockIdx.x;
    int b = bs >> 10, s = bs & 1023;
    int tid = threadIdx.x;
    int n0 = 2 * b, n1 = 2 * b + 1;
    size_t base0 = ((size_t)n0 * SEQ + s) * DM;
    size_t base1 = ((size_t)n1 * SEQ + s) * DM;
    float y0[4], y1[4];
    float ss0 = 0.f, ss1 = 0.f;
    #pragma unroll
    for (int i = 0; i < 4; i++) {
        int d = tid + i * 256;
        y0[i] = g_mlp[base0 + d];
        y1[i] = g_mlp[base1 + d];
        ss0 = fmaf(y0[i], y0[i], ss0);
        ss1 = fmaf(y1[i], y1[i], ss1);
    }
    ss0 = block_reduce_sum(ss0, sh);
    ss1 = block_reduce_sum(ss1, sh);
    float r0 = rsqrtf(ss0 * (1.0f / (float)DM) + EPS) * g_w[n0];
    float r1 = rsqrtf(ss1 * (1.0f / (float)DM) + EPS) * g_w[n1];
    float* orow = out + ((size_t)b * SEQ + s) * DM;
    #pragma unroll
    for (int i = 0; i < 4; i++) {
        int d = tid + i * 256;
        orow[d] = y0[i] * r0 + y1[i] * r1;
    }
}

// ---------------- host launcher --------------------------------------------------
extern "C" void kernel_launch(void* const* d_in, const int* in_sizes, int n_in,
                              void* d_out, int out_size) {
    const float* hidden = (const float*)d_in[0];
    const float* cosb   = (const float*)d_in[1];
    const float* sinb   = (const float*)d_in[2];
    const float* Wr     = (const float*)d_in[3];
    const float* temp   = (const float*)d_in[4];
    const float* Wqkv   = (const float*)d_in[5];
    const float* Wo     = (const float*)d_in[6];
    const float* Wgu    = (const float*)d_in[7];
    const float* Wd     = (const float*)d_in[8];
    float* out = (float*)d_out;

    bf16 *p_hb, *p_qkvb, *p_ctxb, *p_x1b, *p_actb, *p_wb;
    float *p_ao, *p_x1, *p_mlp;
    cudaGetSymbolAddress((void**)&p_hb,   g_hb);
    cudaGetSymbolAddress((void**)&p_qkvb, g_qkvb);
    cudaGetSymbolAddress((void**)&p_ctxb, g_ctxb);
    cudaGetSymbolAddress((void**)&p_x1b,  g_x1b);
    cudaGetSymbolAddress((void**)&p_actb, g_actb);
    cudaGetSymbolAddress((void**)&p_wb,   g_wb);
    cudaGetSymbolAddress((void**)&p_ao,   g_ao);
    cudaGetSymbolAddress((void**)&p_x1,   g_x1);
    cudaGetSymbolAddress((void**)&p_mlp,  g_mlp);

    cudaFuncSetAttribute(flash_kernel,
                         cudaFuncAttributeMaxDynamicSharedMemorySize, FLASH_SMEM);
    cudaFuncSetAttribute((const void*)gemm_bf<1>,
                         cudaFuncAttributeMaxDynamicSharedMemorySize, GEMM_SMEM);
    cudaFuncSetAttribute((const void*)gemm_bf<2>,
                         cudaFuncAttributeMaxDynamicSharedMemorySize, GEMM_SMEM);
    cudaFuncSetAttribute((const void*)gemm_bf<3>,
                         cudaFuncAttributeMaxDynamicSharedMemorySize, GEMM_SMEM);

    // routing first (sets g_need for routed-only weight conversion)
    mean1_kernel<<<dim3(BATCH, 16), 256>>>(hidden);
    mean2_kernel<<<BATCH, 256>>>();
    routing_kernel<<<1, 1024>>>(Wr, temp, out + (size_t)BATCH * SEQ * DM);

    // bf16 conversions
    {
        int n4 = BATCH * SEQ * DM / 4;
        cvt_bf16<<<(n4 + 255) / 256, 256>>>((const float4*)hidden, (uint2*)p_hb, n4);
        n4 = 8 * DM * 3 * DM / 4;
        cvt_w<<<(n4 + 255) / 256, 256>>>((const float4*)Wqkv, (uint2*)(p_wb + WB_QKV),
                                         n4, DM * 3 * DM / 4);
        n4 = 8 * DM * DM / 4;
        cvt_w<<<(n4 + 255) / 256, 256>>>((const float4*)Wo, (uint2*)(p_wb + WB_WO),
                                         n4, DM * DM / 4);
        int tg = 8 * DM * (INTER / 4);
        cvt_wgu<<<(tg + 255) / 256, 256>>>(Wgu, p_wb + WB_GU, tg);
        n4 = 8 * INTER * DM / 4;
        cvt_w<<<(n4 + 255) / 256, 256>>>((const float4*)Wd, (uint2*)(p_wb + WB_WD),
                                         n4, INTER * DM / 4);
    }

    // qkv = x @ Wqkv[e]   (bf16 out)
    gemm_bf<1><<<dim3(3072 / 128, SEQ / 128, NSAMP), 256, GEMM_SMEM>>>(
        p_hb, p_wb + WB_QKV, p_qkvb, 3 * DM, DM, DM,
        (long long)SEQ * DM, 1, (long long)SEQ * 3 * DM, nullptr, 0);

    // rope in-place (bf16)
    rope_kernel<<<dim3(SEQ, NSAMP), 512>>>(cosb, sinb);

    // fused attention -> g_ctxb (bf16), Q tile 64
    flash_kernel<<<dim3(SEQ / 64, NSAMP * HN), 128, FLASH_SMEM>>>();

    // g_ao = hidden + ctx @ Wo[e]   (fp32 out + residual)
    gemm_bf<3><<<dim3(DM / 128, SEQ / 128, NSAMP), 256, GEMM_SMEM>>>(
        p_ctxb, p_wb + WB_WO, p_ao, DM, DM, DM,
        (long long)SEQ * DM, 0, (long long)SEQ * DM, hidden, 1);

    // x1 = rmsnorm(g_ao)
    resid_rms_kernel<<<NSAMP * SEQ, 256>>>();

    // act = silu(gate)*up fused into Wgu GEMM (interleaved weights)
    gemm_bf<2><<<dim3(2 * INTER / 128, SEQ / 128, NSAMP), 256, GEMM_SMEM>>>(
        p_x1b, p_wb + WB_GU, p_actb, 2 * INTER, DM, DM,
        (long long)SEQ * DM, 0, (long long)SEQ * INTER, nullptr, 0);

    // g_mlp = x1 + act @ Wd[e]   (fp32 out + residual)
    gemm_bf<3><<<dim3(DM / 128, SEQ / 128, NSAMP), 256, GEMM_SMEM>>>(
        p_actb, p_wb + WB_WD, p_mlp, DM, INTER, INTER,
        (long long)SEQ * INTER, 0, (long long)SEQ * DM, p_x1, 0);

    // out = sum of weighted rmsnorm(g_mlp)
    final_kernel<<<BATCH * SEQ, 256>>>(out);
}

// round 12
// speedup vs baseline: 1.0140x; 1.0011x over previous
#include <cuda_runtime.h>
#include <cuda_bf16.h>
#include <math.h>
#include <stdint.h>

#define SEQ   1024
#define DM    1024
#define HN    16
#define HDIM  64
#define NSAMP 8
#define INTER 768
#define BATCH 4
#define EPS   1e-5f

typedef __nv_bfloat16 bf16;

// ---------------- scratch (device globals; no allocations allowed) ----------
__device__ float g_hsmean[BATCH * DM];
__device__ float g_partial[BATCH * 16 * DM];
__device__ int   g_expert[NSAMP];
__device__ int   g_need[8];
__device__ float g_w[NSAMP];
__device__ float g_scale[NSAMP * SEQ];
__device__ bf16  g_hb[(size_t)BATCH * SEQ * DM];
__device__ bf16  g_qkvb[(size_t)NSAMP * SEQ * 3 * DM];       // 48 MB (rope fused)
__device__ bf16  g_ctxb[(size_t)NSAMP * SEQ * DM];           // 16 MB
__device__ float g_ao[(size_t)NSAMP * SEQ * DM];             // 32 MB (holds x+ao)
__device__ bf16  g_x1b[(size_t)NSAMP * SEQ * DM];            // 16 MB
__device__ bf16  g_actb[(size_t)NSAMP * SEQ * INTER];        // 12 MB
__device__ float g_mlp[(size_t)NSAMP * SEQ * DM];            // 32 MB (holds x1+mlp)
// all-expert bf16 weights (gu stored column-interleaved: 2i=gate_i, 2i+1=up_i)
#define WB_QKV 0LL
#define WB_WO  25165824LL
#define WB_GU  33554432LL
#define WB_WD  46137344LL
#define WB_TOTAL 52428800LL
__device__ bf16 g_wb[WB_TOTAL];                              // 105 MB

// ---------------- small helpers ----------------------------------------------
__device__ __forceinline__ float block_reduce_sum(float v, float* sh) {
    int tid = threadIdx.x;
    #pragma unroll
    for (int o = 16; o; o >>= 1) v += __shfl_down_sync(0xFFFFFFFFu, v, o);
    if ((tid & 31) == 0) sh[tid >> 5] = v;
    __syncthreads();
    float r = 0.f;
    if (tid < 32) {
        float x = (tid < (int)(blockDim.x >> 5)) ? sh[tid] : 0.f;
        #pragma unroll
        for (int o = 16; o; o >>= 1) x += __shfl_down_sync(0xFFFFFFFFu, x, o);
        if (tid == 0) sh[0] = x;
    }
    __syncthreads();
    r = sh[0];
    __syncthreads();
    return r;
}

__device__ __forceinline__ void mma_bf16(float* d, const uint32_t* a, const uint32_t* b) {
    asm volatile(
        "mma.sync.aligned.m16n8k16.row.col.f32.bf16.bf16.f32 "
        "{%0,%1,%2,%3},{%4,%5,%6,%7},{%8,%9},{%0,%1,%2,%3};"
        : "+f"(d[0]), "+f"(d[1]), "+f"(d[2]), "+f"(d[3])
        : "r"(a[0]), "r"(a[1]), "r"(a[2]), "r"(a[3]), "r"(b[0]), "r"(b[1]));
}

__device__ __forceinline__ void ldsm_x4(uint32_t* r, uint32_t addr) {
    asm volatile(
        "ldmatrix.sync.aligned.m8n8.x4.shared.b16 {%0,%1,%2,%3}, [%4];"
        : "=r"(r[0]), "=r"(r[1]), "=r"(r[2]), "=r"(r[3]) : "r"(addr));
}
__device__ __forceinline__ void ldsm_x2t(uint32_t* r, uint32_t addr) {
    asm volatile(
        "ldmatrix.sync.aligned.m8n8.x2.trans.shared.b16 {%0,%1}, [%2];"
        : "=r"(r[0]), "=r"(r[1]) : "r"(addr));
}
__device__ __forceinline__ uint32_t lds32(uint32_t a) {
    uint32_t v;
    asm volatile("ld.shared.b32 %0, [%1];" : "=r"(v) : "r"(a));
    return v;
}
__device__ __forceinline__ uint32_t packbf(float hi, float lo) {
    uint32_t r;
    asm("cvt.rn.bf16x2.f32 %0, %1, %2;" : "=r"(r) : "f"(hi), "f"(lo));
    return r;
}

__device__ __forceinline__ void cp16(uint32_t s, const void* g) {
    asm volatile("cp.async.cg.shared.global [%0], [%1], 16;" :: "r"(s), "l"(g));
}
__device__ __forceinline__ void cp_commit() {
    asm volatile("cp.async.commit_group;" ::: "memory");
}
__device__ __forceinline__ void cp_wait0() {
    asm volatile("cp.async.wait_group 0;" ::: "memory");
}
__device__ __forceinline__ void cp_wait1() {
    asm volatile("cp.async.wait_group 1;" ::: "memory");
}

// ---------------- fp32 -> bf16 conversion ------------------------------------
__global__ void cvt_bf16(const float4* __restrict__ s, uint2* __restrict__ d, int n4) {
    int i = blockIdx.x * blockDim.x + threadIdx.x;
    if (i < n4) {
        float4 v = s[i];
        uint2 o;
        o.x = packbf(v.y, v.x);
        o.y = packbf(v.w, v.z);
        d[i] = o;
    }
}

// convert expert weights only if routed (g_need flag)
__global__ void cvt_w(const float4* __restrict__ s, uint2* __restrict__ d,
                      int n4, int perExp4) {
    int i = blockIdx.x * blockDim.x + threadIdx.x;
    if (i >= n4) return;
    if (!g_need[i / perExp4]) return;
    float4 v = s[i];
    uint2 o;
    o.x = packbf(v.y, v.x);
    o.y = packbf(v.w, v.z);
    d[i] = o;
}

// Wgu: convert + interleave columns (dst col 2i = gate_i, 2i+1 = up_i)
__global__ void cvt_wgu(const float* __restrict__ W, bf16* __restrict__ dst, int total) {
    int i = blockIdx.x * blockDim.x + threadIdx.x;
    if (i >= total) return;
    const int perE = DM * (INTER / 4);
    int e = i / perE;
    if (!g_need[e]) return;
    int rem = i % perE;
    int k = rem / (INTER / 4);
    int nq = rem % (INTER / 4);
    const float* row = W + ((size_t)e * DM + k) * (2 * INTER);
    float4 gv = *(const float4*)(row + nq * 4);
    float4 uv = *(const float4*)(row + INTER + nq * 4);
    uint4 o;
    o.x = packbf(uv.x, gv.x);
    o.y = packbf(uv.y, gv.y);
    o.z = packbf(uv.z, gv.z);
    o.w = packbf(uv.w, gv.w);
    *(uint4*)(dst + ((size_t)e * DM + k) * (2 * INTER) + nq * 8) = o;
}

// ---------------- routing ----------------------------------------------------
__global__ void mean1_kernel(const float* __restrict__ hidden) {
    int b = blockIdx.x, c = blockIdx.y;
    int tid = threadIdx.x;
    float acc[4] = {0.f, 0.f, 0.f, 0.f};
    for (int s = c * 64; s < c * 64 + 64; s++) {
        const float* row = hidden + ((size_t)b * SEQ + s) * DM;
        #pragma unroll
        for (int i = 0; i < 4; i++) acc[i] += row[tid + i * 256];
    }
    #pragma unroll
    for (int i = 0; i < 4; i++)
        g_partial[((size_t)b * 16 + c) * DM + tid + i * 256] = acc[i];
}

__global__ void mean2_kernel() {
    int b = blockIdx.x;
    int tid = threadIdx.x;
    #pragma unroll
    for (int i = 0; i < 4; i++) {
        int d = tid + i * 256;
        float s = 0.f;
        for (int c = 0; c < 16; c++) s += g_partial[((size_t)b * 16 + c) * DM + d];
        g_hsmean[b * DM + d] = s * (1.0f / (float)SEQ);
    }
}

__global__ void routing_kernel(const float* __restrict__ Wr,
                               const float* __restrict__ temperature,
                               float* __restrict__ out_logits) {
    int tid = threadIdx.x;          // 1024
    int w = tid >> 5, lane = tid & 31;
    int b = w >> 3, c = w & 7;
    float s = 0.f;
    for (int d = lane; d < DM; d += 32)
        s += g_hsmean[b * DM + d] * Wr[c * DM + d];
    #pragma unroll
    for (int o = 16; o; o >>= 1) s += __shfl_down_sync(0xFFFFFFFFu, s, o);
    __shared__ float logits[32];
    if (lane == 0) logits[w] = s;
    if (tid < 8) g_need[tid] = 0;
    __syncthreads();
    if (tid < BATCH) {
        float t = fminf(fmaxf(temperature[0], 0.1f), 10.0f);
        float lv[8];
        #pragma unroll
        for (int cc = 0; cc < 8; cc++) {
            lv[cc] = logits[tid * 8 + cc] / t;
            out_logits[tid * 8 + cc] = lv[cc];
        }
        int i0 = 0;
        #pragma unroll
        for (int cc = 1; cc < 8; cc++) if (lv[cc] > lv[i0]) i0 = cc;
        int i1 = -1;
        #pragma unroll
        for (int cc = 0; cc < 8; cc++) {
            if (cc == i0) continue;
            if (i1 < 0 || lv[cc] > lv[i1]) i1 = cc;
        }
        float e = expf(lv[i1] - lv[i0]);
        g_expert[2 * tid]     = i0;
        g_expert[2 * tid + 1] = i1;
        g_w[2 * tid]     = 1.0f / (1.0f + e);
        g_w[2 * tid + 1] = e / (1.0f + e);
        g_need[i0] = 1;
        g_need[i1] = 1;
    }
}

// ---------------- bf16 tensor-core GEMM ----------------------------------------
// BM=BN=128, BK=64, 3-stage cp.async, 2 CTA/SM.
// MODE 1: bf16 out + fused RoPE (QKV; warp tile 32x64 so rope pairs are in-thread)
// MODE 2: fused silu(gate)*up, interleaved cols -> bf16 act.
// MODE 3: fp32 out + residual (Res fp32; optionally scaled by g_scale per row).
#define ASTG 144
#define BSTG 272
#define ABYTES (128 * ASTG)
#define BBYTES (64 * BSTG)
#define STGB (ABYTES + BBYTES)
#define GEMM_SMEM (3 * STGB)

template<int MODE>
__global__ __launch_bounds__(256, 2) void gemm_bf(
    const bf16* __restrict__ Ab, const bf16* __restrict__ Bb, void* __restrict__ Cb,
    int N, int K, int lda, long long strideA, int a_div2, long long strideC,
    const float* __restrict__ Res, int r_div2, int useScale,
    const float* __restrict__ cosp, const float* __restrict__ sinp)
{
    constexpr int MI = (MODE == 1) ? 2 : 4;
    constexpr int NJ = (MODE == 1) ? 8 : 4;

    extern __shared__ char smraw[];
    uint32_t sb = (uint32_t)__cvta_generic_to_shared(smraw);
    int z = blockIdx.z;
    const bf16* A = Ab + (size_t)(a_div2 ? (z >> 1) : z) * strideA;
    const bf16* B = Bb + (long long)g_expert[z] * ((long long)K * N);
    int m0 = blockIdx.y * 128;
    int n0 = blockIdx.x * 128;
    int tid = threadIdx.x, lane = tid & 31, wid = tid >> 5;
    int wm0, wn0;
    if (MODE == 1) { wm0 = (wid & 3) * 32; wn0 = (wid >> 2) * 64; }
    else           { wm0 = (wid & 1) * 64; wn0 = (wid >> 1) * 32; }
    int g = lane >> 2, t = lane & 3;

    auto load_tile = [&](int k0, int buf) {
        uint32_t base = sb + (uint32_t)(buf * STGB);
        #pragma unroll
        for (int p = 0; p < 4; p++) {
            int i = tid + p * 256;
            int row = i >> 3, ch = i & 7;
            cp16(base + (uint32_t)(row * ASTG + ch * 16),
                 A + (size_t)(m0 + row) * lda + k0 + ch * 8);
        }
        #pragma unroll
        for (int p = 0; p < 4; p++) {
            int i = tid + p * 256;
            int row = i >> 4, ch = i & 15;
            cp16(base + (uint32_t)(ABYTES + row * BSTG + ch * 16),
                 B + (size_t)(k0 + row) * N + n0 + ch * 8);
        }
    };

    int NT = K / 64;
    load_tile(0, 0);
    cp_commit();
    load_tile(64, 1);
    cp_commit();

    float acc[MI][NJ][4];
    #pragma unroll
    for (int i = 0; i < MI; i++)
        #pragma unroll
        for (int j = 0; j < NJ; j++)
            #pragma unroll
            for (int q = 0; q < 4; q++) acc[i][j][q] = 0.f;

    uint32_t af[2][MI][4];
    uint32_t bfr[2][NJ][2];

    int buf = 0;
    for (int tI = 0; tI < NT; ++tI) {
        if (tI + 1 < NT) cp_wait1(); else cp_wait0();
        __syncthreads();
        if (tI + 2 < NT) {
            int nb = buf + 2; if (nb >= 3) nb -= 3;
            load_tile((tI + 2) * 64, nb);
            cp_commit();
        }
        uint32_t stage = sb + (uint32_t)(buf * STGB);
        uint32_t aB = stage + (uint32_t)((wm0 + (lane & 15)) * ASTG + (lane >> 4) * 16);
        uint32_t bB = stage + (uint32_t)(ABYTES + (lane & 15) * BSTG + wn0 * 2);

        #pragma unroll
        for (int i = 0; i < MI; i++) ldsm_x4(af[0][i], aB + (uint32_t)(i * 16 * ASTG));
        #pragma unroll
        for (int j = 0; j < NJ; j++) ldsm_x2t(bfr[0][j], bB + (uint32_t)(j * 16));

        #pragma unroll
        for (int ks = 0; ks < 4; ks++) {
            int cb = ks & 1, nb2 = cb ^ 1;
            if (ks < 3) {
                #pragma unroll
                for (int i = 0; i < MI; i++)
                    ldsm_x4(af[nb2][i], aB + (uint32_t)(i * 16 * ASTG + (ks + 1) * 32));
                #pragma unroll
                for (int j = 0; j < NJ; j++)
                    ldsm_x2t(bfr[nb2][j], bB + (uint32_t)((ks + 1) * 16 * BSTG + j * 16));
            }
            #pragma unroll
            for (int i = 0; i < MI; i++)
                #pragma unroll
                for (int j = 0; j < NJ; j++)
                    mma_bf16(acc[i][j], af[cb][i], bfr[cb][j]);
        }
        buf++; if (buf == 3) buf = 0;
    }

    if (MODE == 1) {
        bf16* C = (bf16*)Cb + (size_t)z * strideC;
        bool isv = (n0 + wn0) >= 2 * DM;   // v columns: no rope
        #pragma unroll
        for (int i = 0; i < MI; i++) {
            int r = m0 + wm0 + i * 16 + g;
            if (isv) {
                #pragma unroll
                for (int j = 0; j < NJ; j++) {
                    int c = n0 + wn0 + j * 8 + 2 * t;
                    *(uint32_t*)(C + (size_t)r * N + c) = packbf(acc[i][j][1], acc[i][j][0]);
                    *(uint32_t*)(C + (size_t)(r + 8) * N + c) = packbf(acc[i][j][3], acc[i][j][2]);
                }
            } else {
                #pragma unroll
                for (int j = 0; j < 4; j++) {
                    int hc = j * 8 + 2 * t;            // [0,32)
                    int c = n0 + wn0 + hc;
                    // rows r and r+8; cos/sin per (row, hc) and (row, hc+32)
                    float2 cl0 = *(const float2*)(cosp + r * HDIM + hc);
                    float2 sl0 = *(const float2*)(sinp + r * HDIM + hc);
                    float2 ch0 = *(const float2*)(cosp + r * HDIM + hc + 32);
                    float2 sh0 = *(const float2*)(sinp + r * HDIM + hc + 32);
                    float2 cl1 = *(const float2*)(cosp + (r + 8) * HDIM + hc);
                    float2 sl1 = *(const float2*)(sinp + (r + 8) * HDIM + hc);
                    float2 ch1 = *(const float2*)(cosp + (r + 8) * HDIM + hc + 32);
                    float2 sh1 = *(const float2*)(sinp + (r + 8) * HDIM + hc + 32);
                    float alo0 = acc[i][j][0], alo1 = acc[i][j][1];
                    float ahi0 = acc[i][j + 4][0], ahi1 = acc[i][j + 4][1];
                    float blo0 = acc[i][j][2], blo1 = acc[i][j][3];
                    float bhi0 = acc[i][j + 4][2], bhi1 = acc[i][j + 4][3];
                    *(uint32_t*)(C + (size_t)r * N + c) =
                        packbf(alo1 * cl0.y - ahi1 * sl0.y, alo0 * cl0.x - ahi0 * sl0.x);
                    *(uint32_t*)(C + (size_t)r * N + c + 32) =
                        packbf(ahi1 * ch0.y + alo1 * sh0.y, ahi0 * ch0.x + alo0 * sh0.x);
                    *(uint32_t*)(C + (size_t)(r + 8) * N + c) =
                        packbf(blo1 * cl1.y - bhi1 * sl1.y, blo0 * cl1.x - bhi0 * sl1.x);
                    *(uint32_t*)(C + (size_t)(r + 8) * N + c + 32) =
                        packbf(bhi1 * ch1.y + blo1 * sh1.y, bhi0 * ch1.x + blo0 * sh1.x);
                }
            }
        }
    } else {
        #pragma unroll
        for (int i = 0; i < MI; i++) {
            int r = m0 + wm0 + i * 16 + g;
            float sc0 = 1.0f, sc1 = 1.0f;
            if (MODE == 3 && useScale) {
                sc0 = g_scale[z * SEQ + r];
                sc1 = g_scale[z * SEQ + r + 8];
            }
            #pragma unroll
            for (int j = 0; j < NJ; j++) {
                int c = n0 + wn0 + j * 8 + 2 * t;
                if (MODE == 2) {
                    bf16* C = (bf16*)Cb + (size_t)z * strideC;
                    int oc = c >> 1;
                    float g0 = acc[i][j][0], u0 = acc[i][j][1];
                    float g1 = acc[i][j][2], u1 = acc[i][j][3];
                    float s0 = g0 / (1.0f + __expf(-g0)) * u0;
                    float s1 = g1 / (1.0f + __expf(-g1)) * u1;
                    C[(size_t)r * (N / 2) + oc]       = __float2bfloat16(s0);
                    C[(size_t)(r + 8) * (N / 2) + oc] = __float2bfloat16(s1);
                } else {  // MODE 3
                    float* C = (float*)Cb + (size_t)z * strideC;
                    const float* R = Res + (size_t)(r_div2 ? (z >> 1) : z) * strideC;
                    float2 r0 = *(const float2*)(R + (size_t)r * N + c);
                    float2 r1 = *(const float2*)(R + (size_t)(r + 8) * N + c);
                    *(float2*)(C + (size_t)r * N + c) =
                        make_float2(acc[i][j][0] + r0.x * sc0, acc[i][j][1] + r0.y * sc0);
                    *(float2*)(C + (size_t)(r + 8) * N + c) =
                        make_float2(acc[i][j][2] + r1.x * sc1, acc[i][j][3] + r1.y * sc1);
                }
            }
        }
    }
}

// ---------------- flash attention (bf16 mma, Q tile 64, 128 thr) ----------------
#define FQ 0
#define FK 9216
#define FV (9216 * 3)
#define FLASH_SMEM (9216 * 5)

__global__ __launch_bounds__(128) void flash_kernel() {
    extern __shared__ char smraw[];
    uint32_t sb = (uint32_t)__cvta_generic_to_shared(smraw);

    int nh = blockIdx.y;
    int n = nh >> 4, h = nh & 15;
    int q0 = blockIdx.x * 64;
    const bf16* qbase = g_qkvb + (size_t)n * SEQ * (3 * DM) + h * HDIM;
    const bf16* kbase = qbase + DM;
    const bf16* vbase = qbase + 2 * DM;

    int tid = threadIdx.x, lane = tid & 31, wid = tid >> 5;
    int g = lane >> 2, t = lane & 3;
    int wm0 = wid * 16;

    #pragma unroll
    for (int p = 0; p < 4; p++) {
        int i = tid + p * 128;
        int row = i >> 3, ch = i & 7;
        cp16(sb + (uint32_t)(FQ + row * 144 + ch * 16),
             qbase + (size_t)(q0 + row) * (3 * DM) + ch * 8);
        cp16(sb + (uint32_t)(FK + row * 144 + ch * 16),
             kbase + (size_t)row * (3 * DM) + ch * 8);
        cp16(sb + (uint32_t)(FV + row * 144 + ch * 16),
             vbase + (size_t)row * (3 * DM) + ch * 8);
    }
    cp_commit();
    cp_wait0();
    __syncthreads();

    uint32_t qf[4][4];
    uint32_t qA = sb + (uint32_t)(FQ + (wm0 + (lane & 15)) * 144 + (lane >> 4) * 16);
    #pragma unroll
    for (int kc = 0; kc < 4; kc++) ldsm_x4(qf[kc], qA + (uint32_t)(kc * 32));

    float m0 = -INFINITY, m1 = -INFINITY, l0 = 0.f, l1 = 0.f;
    float oa[8][4];
    #pragma unroll
    for (int j = 0; j < 8; j++)
        #pragma unroll
        for (int q = 0; q < 4; q++) oa[j][q] = 0.f;

    const int NT = SEQ / 64;
    for (int it = 0; it < NT; it++) {
        int buf = it & 1;
        if (it + 1 < NT) {
            int kv = (it + 1) * 64;
            int ob = buf ^ 1;
            #pragma unroll
            for (int p = 0; p < 4; p++) {
                int i = tid + p * 128;
                int row = i >> 3, ch = i & 7;
                cp16(sb + (uint32_t)(FK + ob * 9216 + row * 144 + ch * 16),
                     kbase + (size_t)(kv + row) * (3 * DM) + ch * 8);
                cp16(sb + (uint32_t)(FV + ob * 9216 + row * 144 + ch * 16),
                     vbase + (size_t)(kv + row) * (3 * DM) + ch * 8);
            }
            cp_commit();
        }
        uint32_t kB = sb + (uint32_t)(FK + buf * 9216);
        uint32_t vB = sb + (uint32_t)(FV + buf * 9216);

        float sacc[8][4];
        #pragma unroll
        for (int j = 0; j < 8; j++)
            #pragma unroll
            for (int q = 0; q < 4; q++) sacc[j][q] = 0.f;

        #pragma unroll
        for (int kc = 0; kc < 4; kc++) {
            #pragma unroll
            for (int nt = 0; nt < 8; nt++) {
                uint32_t ba = kB + (uint32_t)((nt * 8 + g) * 144 + kc * 32 + t * 4);
                uint32_t bb[2];
                bb[0] = lds32(ba);
                bb[1] = lds32(ba + 16);
                mma_bf16(sacc[nt], qf[kc], bb);
            }
        }

        float rm0 = -INFINITY, rm1 = -INFINITY;
        #pragma unroll
        for (int nt = 0; nt < 8; nt++) {
            #pragma unroll
            for (int q = 0; q < 4; q++) sacc[nt][q] *= 0.125f;
            rm0 = fmaxf(rm0, fmaxf(sacc[nt][0], sacc[nt][1]));
            rm1 = fmaxf(rm1, fmaxf(sacc[nt][2], sacc[nt][3]));
        }
        rm0 = fmaxf(rm0, __shfl_xor_sync(0xFFFFFFFFu, rm0, 1));
        rm0 = fmaxf(rm0, __shfl_xor_sync(0xFFFFFFFFu, rm0, 2));
        rm1 = fmaxf(rm1, __shfl_xor_sync(0xFFFFFFFFu, rm1, 1));
        rm1 = fmaxf(rm1, __shfl_xor_sync(0xFFFFFFFFu, rm1, 2));
        float mn0 = fmaxf(m0, rm0), mn1 = fmaxf(m1, rm1);
        float c0 = __expf(m0 - mn0), c1 = __expf(m1 - mn1);
        float ls0 = 0.f, ls1 = 0.f;
        #pragma unroll
        for (int nt = 0; nt < 8; nt++) {
            sacc[nt][0] = __expf(sacc[nt][0] - mn0);
            sacc[nt][1] = __expf(sacc[nt][1] - mn0);
            sacc[nt][2] = __expf(sacc[nt][2] - mn1);
            sacc[nt][3] = __expf(sacc[nt][3] - mn1);
            ls0 += sacc[nt][0] + sacc[nt][1];
            ls1 += sacc[nt][2] + sacc[nt][3];
        }
        ls0 += __shfl_xor_sync(0xFFFFFFFFu, ls0, 1);
        ls0 += __shfl_xor_sync(0xFFFFFFFFu, ls0, 2);
        ls1 += __shfl_xor_sync(0xFFFFFFFFu, ls1, 1);
        ls1 += __shfl_xor_sync(0xFFFFFFFFu, ls1, 2);
        l0 = l0 * c0 + ls0;
        l1 = l1 * c1 + ls1;
        m0 = mn0; m1 = mn1;
        #pragma unroll
        for (int j = 0; j < 8; j++) {
            oa[j][0] *= c0; oa[j][1] *= c0;
            oa[j][2] *= c1; oa[j][3] *= c1;
        }

        #pragma unroll
        for (int mC = 0; mC < 4; mC++) {
            uint32_t pa[4];
            pa[0] = packbf(sacc[2 * mC][1],     sacc[2 * mC][0]);
            pa[1] = packbf(sacc[2 * mC][3],     sacc[2 * mC][2]);
            pa[2] = packbf(sacc[2 * mC + 1][1], sacc[2 * mC + 1][0]);
            pa[3] = packbf(sacc[2 * mC + 1][3], sacc[2 * mC + 1][2]);
            #pragma unroll
            for (int jn = 0; jn < 8; jn++) {
                uint32_t vb[2];
                ldsm_x2t(vb, vB + (uint32_t)((mC * 16 + (lane & 15)) * 144 + jn * 16));
                mma_bf16(oa[jn], pa, vb);
            }
        }

        cp_wait0();
        __syncthreads();
    }

    float inv0 = 1.0f / l0, inv1 = 1.0f / l1;
    int grow0 = q0 + wm0 + g;
    bf16* cbase = g_ctxb + (size_t)n * SEQ * DM + h * HDIM;
    #pragma unroll
    for (int jn = 0; jn < 8; jn++) {
        int col = jn * 8 + 2 * t;
        *(uint32_t*)(cbase + (size_t)grow0 * DM + col) =
            packbf(oa[jn][1] * inv0, oa[jn][0] * inv0);
        *(uint32_t*)(cbase + (size_t)(grow0 + 8) * DM + col) =
            packbf(oa[jn][3] * inv1, oa[jn][2] * inv1);
    }
}

// ---------------- rmsnorm of (x+ao): writes x1b (bf16) + per-row scale ----------
__global__ void resid_rms_kernel() {
    __shared__ float sh[32];
    int ns = blockIdx.x;
    int tid = threadIdx.x;           // 256
    int d0 = tid * 4;
    size_t base = (size_t)ns * DM;
    float4 y = *(const float4*)(g_ao + base + d0);
    float ss = y.x * y.x + y.y * y.y + y.z * y.z + y.w * y.w;
    ss = block_reduce_sum(ss, sh);
    float scale = rsqrtf(ss * (1.0f / (float)DM) + EPS);
    if (tid == 0) g_scale[ns] = scale;
    y.x *= scale; y.y *= scale; y.z *= scale; y.w *= scale;
    uint2 o;
    o.x = packbf(y.y, y.x);
    o.y = packbf(y.w, y.z);
    *(uint2*)(g_x1b + base + d0) = o;
}

// ---------------- final: rmsnorm(x1+mlp) (sum done in Wd epilogue) --------------
__global__ void final_kernel(float* __restrict__ out) {
    __shared__ float sh[32];
    int bs = blockIdx.x;
    int b = bs >> 10, s = bs & 1023;
    int tid = threadIdx.x;
    int n0 = 2 * b, n1 = 2 * b + 1;
    size_t base0 = ((size_t)n0 * SEQ + s) * DM;
    size_t base1 = ((size_t)n1 * SEQ + s) * DM;
    float y0[4], y1[4];
    float ss0 = 0.f, ss1 = 0.f;
    #pragma unroll
    for (int i = 0; i < 4; i++) {
        int d = tid + i * 256;
        y0[i] = g_mlp[base0 + d];
        y1[i] = g_mlp[base1 + d];
        ss0 = fmaf(y0[i], y0[i], ss0);
        ss1 = fmaf(y1[i], y1[i], ss1);
    }
    ss0 = block_reduce_sum(ss0, sh);
    ss1 = block_reduce_sum(ss1, sh);
    float r0 = rsqrtf(ss0 * (1.0f / (float)DM) + EPS) * g_w[n0];
    float r1 = rsqrtf(ss1 * (1.0f / (float)DM) + EPS) * g_w[n1];
    float* orow = out + ((size_t)b * SEQ + s) * DM;
    #pragma unroll
    for (int i = 0; i < 4; i++) {
        int d = tid + i * 256;
        orow[d] = y0[i] * r0 + y1[i] * r1;
    }
}

// ---------------- host launcher --------------------------------------------------
extern "C" void kernel_launch(void* const* d_in, const int* in_sizes, int n_in,
                              void* d_out, int out_size) {
    const float* hidden = (const float*)d_in[0];
    const float* cosb   = (const float*)d_in[1];
    const float* sinb   = (const float*)d_in[2];
    const float* Wr     = (const float*)d_in[3];
    const float* temp   = (const float*)d_in[4];
    const float* Wqkv   = (const float*)d_in[5];
    const float* Wo     = (const float*)d_in[6];
    const float* Wgu    = (const float*)d_in[7];
    const float* Wd     = (const float*)d_in[8];
    float* out = (float*)d_out;

    bf16 *p_hb, *p_qkvb, *p_ctxb, *p_x1b, *p_actb, *p_wb;
    float *p_ao, *p_mlp;
    cudaGetSymbolAddress((void**)&p_hb,   g_hb);
    cudaGetSymbolAddress((void**)&p_qkvb, g_qkvb);
    cudaGetSymbolAddress((void**)&p_ctxb, g_ctxb);
    cudaGetSymbolAddress((void**)&p_x1b,  g_x1b);
    cudaGetSymbolAddress((void**)&p_actb, g_actb);
    cudaGetSymbolAddress((void**)&p_wb,   g_wb);
    cudaGetSymbolAddress((void**)&p_ao,   g_ao);
    cudaGetSymbolAddress((void**)&p_mlp,  g_mlp);

    cudaFuncSetAttribute(flash_kernel,
                         cudaFuncAttributeMaxDynamicSharedMemorySize, FLASH_SMEM);
    cudaFuncSetAttribute((const void*)gemm_bf<1>,
                         cudaFuncAttributeMaxDynamicSharedMemorySize, GEMM_SMEM);
    cudaFuncSetAttribute((const void*)gemm_bf<2>,
                         cudaFuncAttributeMaxDynamicSharedMemorySize, GEMM_SMEM);
    cudaFuncSetAttribute((const void*)gemm_bf<3>,
                         cudaFuncAttributeMaxDynamicSharedMemorySize, GEMM_SMEM);

    // routing first (sets g_need for routed-only weight conversion)
    mean1_kernel<<<dim3(BATCH, 16), 256>>>(hidden);
    mean2_kernel<<<BATCH, 256>>>();
    routing_kernel<<<1, 1024>>>(Wr, temp, out + (size_t)BATCH * SEQ * DM);

    // bf16 conversions
    {
        int n4 = BATCH * SEQ * DM / 4;
        cvt_bf16<<<(n4 + 255) / 256, 256>>>((const float4*)hidden, (uint2*)p_hb, n4);
        n4 = 8 * DM * 3 * DM / 4;
        cvt_w<<<(n4 + 255) / 256, 256>>>((const float4*)Wqkv, (uint2*)(p_wb + WB_QKV),
                                         n4, DM * 3 * DM / 4);
        n4 = 8 * DM * DM / 4;
        cvt_w<<<(n4 + 255) / 256, 256>>>((const float4*)Wo, (uint2*)(p_wb + WB_WO),
                                         n4, DM * DM / 4);
        int tg = 8 * DM * (INTER / 4);
        cvt_wgu<<<(tg + 255) / 256, 256>>>(Wgu, p_wb + WB_GU, tg);
        n4 = 8 * INTER * DM / 4;
        cvt_w<<<(n4 + 255) / 256, 256>>>((const float4*)Wd, (uint2*)(p_wb + WB_WD),
                                         n4, INTER * DM / 4);
    }

    // qkv = x @ Wqkv[e]   (bf16 out, RoPE fused on q,k)
    gemm_bf<1><<<dim3(3072 / 128, SEQ / 128, NSAMP), 256, GEMM_SMEM>>>(
        p_hb, p_wb + WB_QKV, p_qkvb, 3 * DM, DM, DM,
        (long long)SEQ * DM, 1, (long long)SEQ * 3 * DM, nullptr, 0, 0, cosb, sinb);

    // fused attention -> g_ctxb (bf16), Q tile 64
    flash_kernel<<<dim3(SEQ / 64, NSAMP * HN), 128, FLASH_SMEM>>>();

    // g_ao = hidden + ctx @ Wo[e]   (fp32 out + residual)
    gemm_bf<3><<<dim3(DM / 128, SEQ / 128, NSAMP), 256, GEMM_SMEM>>>(
        p_ctxb, p_wb + WB_WO, p_ao, DM, DM, DM,
        (long long)SEQ * DM, 0, (long long)SEQ * DM, hidden, 1, 0, nullptr, nullptr);

    // x1b + g_scale = rmsnorm(g_ao)
    resid_rms_kernel<<<NSAMP * SEQ, 256>>>();

    // act = silu(gate)*up fused into Wgu GEMM (interleaved weights)
    gemm_bf<2><<<dim3(2 * INTER / 128, SEQ / 128, NSAMP), 256, GEMM_SMEM>>>(
        p_x1b, p_wb + WB_GU, p_actb, 2 * INTER, DM, DM,
        (long long)SEQ * DM, 0, (long long)SEQ * INTER, nullptr, 0, 0, nullptr, nullptr);

    // g_mlp = x1 + act @ Wd[e]   (fp32 out + residual = g_ao * g_scale)
    gemm_bf<3><<<dim3(DM / 128, SEQ / 128, NSAMP), 256, GEMM_SMEM>>>(
        p_actb, p_wb + WB_WD, p_mlp, DM, INTER, INTER,
        (long long)SEQ * INTER, 0, (long long)SEQ * DM, p_ao, 0, 1, nullptr, nullptr);

    // out = sum of weighted rmsnorm(g_mlp)
    final_kernel<<<BATCH * SEQ, 256>>>(out);
}

// round 13
// speedup vs baseline: 1.0232x; 1.0090x over previous
#include <cuda_runtime.h>
#include <cuda_bf16.h>
#include <math.h>
#include <stdint.h>

#define SEQ   1024
#define DM    1024
#define HN    16
#define HDIM  64
#define NSAMP 8
#define INTER 768
#define BATCH 4
#define EPS   1e-5f

typedef __nv_bfloat16 bf16;

// ---------------- scratch (device globals; no allocations allowed) ----------
__device__ float g_hsmean[BATCH * DM];
__device__ float g_partial[BATCH * 16 * DM];
__device__ int   g_expert[NSAMP];
__device__ int   g_need[8];
__device__ float g_w[NSAMP];
__device__ float g_scale[NSAMP * SEQ];
__device__ bf16  g_hb[(size_t)BATCH * SEQ * DM];
__device__ bf16  g_qkvb[(size_t)NSAMP * SEQ * 3 * DM];       // 48 MB (rope fused)
__device__ bf16  g_ctxb[(size_t)NSAMP * SEQ * DM];           // 16 MB
__device__ float g_ao[(size_t)NSAMP * SEQ * DM];             // 32 MB (holds x+ao)
__device__ bf16  g_x1b[(size_t)NSAMP * SEQ * DM];            // 16 MB
__device__ bf16  g_actb[(size_t)NSAMP * SEQ * INTER];        // 12 MB
__device__ float g_mlp[(size_t)NSAMP * SEQ * DM];            // 32 MB (holds x1+mlp)
// all-expert bf16 weights (gu stored column-interleaved: 2i=gate_i, 2i+1=up_i)
#define WB_QKV 0LL
#define WB_WO  25165824LL
#define WB_GU  33554432LL
#define WB_WD  46137344LL
#define WB_TOTAL 52428800LL
__device__ bf16 g_wb[WB_TOTAL];                              // 105 MB

// ---------------- small helpers ----------------------------------------------
__device__ __forceinline__ float block_reduce_sum(float v, float* sh) {
    int tid = threadIdx.x;
    #pragma unroll
    for (int o = 16; o; o >>= 1) v += __shfl_down_sync(0xFFFFFFFFu, v, o);
    if ((tid & 31) == 0) sh[tid >> 5] = v;
    __syncthreads();
    float r = 0.f;
    if (tid < 32) {
        float x = (tid < (int)(blockDim.x >> 5)) ? sh[tid] : 0.f;
        #pragma unroll
        for (int o = 16; o; o >>= 1) x += __shfl_down_sync(0xFFFFFFFFu, x, o);
        if (tid == 0) sh[0] = x;
    }
    __syncthreads();
    r = sh[0];
    __syncthreads();
    return r;
}

__device__ __forceinline__ void mma_bf16(float* d, const uint32_t* a, const uint32_t* b) {
    asm volatile(
        "mma.sync.aligned.m16n8k16.row.col.f32.bf16.bf16.f32 "
        "{%0,%1,%2,%3},{%4,%5,%6,%7},{%8,%9},{%0,%1,%2,%3};"
        : "+f"(d[0]), "+f"(d[1]), "+f"(d[2]), "+f"(d[3])
        : "r"(a[0]), "r"(a[1]), "r"(a[2]), "r"(a[3]), "r"(b[0]), "r"(b[1]));
}

__device__ __forceinline__ void ldsm_x4(uint32_t* r, uint32_t addr) {
    asm volatile(
        "ldmatrix.sync.aligned.m8n8.x4.shared.b16 {%0,%1,%2,%3}, [%4];"
        : "=r"(r[0]), "=r"(r[1]), "=r"(r[2]), "=r"(r[3]) : "r"(addr));
}
__device__ __forceinline__ void ldsm_x2t(uint32_t* r, uint32_t addr) {
    asm volatile(
        "ldmatrix.sync.aligned.m8n8.x2.trans.shared.b16 {%0,%1}, [%2];"
        : "=r"(r[0]), "=r"(r[1]) : "r"(addr));
}
__device__ __forceinline__ uint32_t lds32(uint32_t a) {
    uint32_t v;
    asm volatile("ld.shared.b32 %0, [%1];" : "=r"(v) : "r"(a));
    return v;
}
__device__ __forceinline__ uint32_t packbf(float hi, float lo) {
    uint32_t r;
    asm("cvt.rn.bf16x2.f32 %0, %1, %2;" : "=r"(r) : "f"(hi), "f"(lo));
    return r;
}

__device__ __forceinline__ void cp16(uint32_t s, const void* g) {
    asm volatile("cp.async.cg.shared.global [%0], [%1], 16;" :: "r"(s), "l"(g));
}
__device__ __forceinline__ void cp_commit() {
    asm volatile("cp.async.commit_group;" ::: "memory");
}
__device__ __forceinline__ void cp_wait0() {
    asm volatile("cp.async.wait_group 0;" ::: "memory");
}
__device__ __forceinline__ void cp_wait1() {
    asm volatile("cp.async.wait_group 1;" ::: "memory");
}

// ---------------- fp32 -> bf16 conversion (ILP-4) ------------------------------
__global__ void cvt_bf16(const float4* __restrict__ s, uint2* __restrict__ d, int n4) {
    int base = blockIdx.x * (blockDim.x * 4) + threadIdx.x;
    float4 v[4];
    bool ok[4];
    #pragma unroll
    for (int u = 0; u < 4; u++) {
        int i = base + u * 256;
        ok[u] = (i < n4);
        if (ok[u]) v[u] = s[i];
    }
    #pragma unroll
    for (int u = 0; u < 4; u++) {
        if (ok[u]) {
            uint2 o;
            o.x = packbf(v[u].y, v[u].x);
            o.y = packbf(v[u].w, v[u].z);
            d[base + u * 256] = o;
        }
    }
}

// convert expert weights only if routed (g_need flag), ILP-4
__global__ void cvt_w(const float4* __restrict__ s, uint2* __restrict__ d,
                      int n4, int perExp4) {
    int base = blockIdx.x * (blockDim.x * 4) + threadIdx.x;
    float4 v[4];
    bool ok[4];
    #pragma unroll
    for (int u = 0; u < 4; u++) {
        int i = base + u * 256;
        ok[u] = (i < n4) && g_need[i / perExp4];
        if (ok[u]) v[u] = s[i];
    }
    #pragma unroll
    for (int u = 0; u < 4; u++) {
        if (ok[u]) {
            uint2 o;
            o.x = packbf(v[u].y, v[u].x);
            o.y = packbf(v[u].w, v[u].z);
            d[base + u * 256] = o;
        }
    }
}

// Wgu: convert + interleave columns (dst col 2i = gate_i, 2i+1 = up_i), ILP-2
__global__ void cvt_wgu(const float* __restrict__ W, bf16* __restrict__ dst, int total) {
    const int perE = DM * (INTER / 4);
    int base = blockIdx.x * (blockDim.x * 2) + threadIdx.x;
    float4 gv[2], uv[2];
    bool ok[2];
    int kk[2], nqq[2], ee[2];
    #pragma unroll
    for (int u = 0; u < 2; u++) {
        int i = base + u * 256;
        ok[u] = false;
        if (i < total) {
            int e = i / perE;
            if (g_need[e]) {
                int rem = i % perE;
                kk[u] = rem / (INTER / 4);
                nqq[u] = rem % (INTER / 4);
                ee[u] = e;
                const float* row = W + ((size_t)e * DM + kk[u]) * (2 * INTER);
                gv[u] = *(const float4*)(row + nqq[u] * 4);
                uv[u] = *(const float4*)(row + INTER + nqq[u] * 4);
                ok[u] = true;
            }
        }
    }
    #pragma unroll
    for (int u = 0; u < 2; u++) {
        if (ok[u]) {
            uint4 o;
            o.x = packbf(uv[u].x, gv[u].x);
            o.y = packbf(uv[u].y, gv[u].y);
            o.z = packbf(uv[u].z, gv[u].z);
            o.w = packbf(uv[u].w, gv[u].w);
            *(uint4*)(dst + ((size_t)ee[u] * DM + kk[u]) * (2 * INTER) + nqq[u] * 8) = o;
        }
    }
}

// ---------------- routing ----------------------------------------------------
__global__ void mean1_kernel(const float* __restrict__ hidden) {
    int b = blockIdx.x, c = blockIdx.y;
    int tid = threadIdx.x;
    float acc[4] = {0.f, 0.f, 0.f, 0.f};
    for (int s = c * 64; s < c * 64 + 64; s++) {
        const float* row = hidden + ((size_t)b * SEQ + s) * DM;
        #pragma unroll
        for (int i = 0; i < 4; i++) acc[i] += row[tid + i * 256];
    }
    #pragma unroll
    for (int i = 0; i < 4; i++)
        g_partial[((size_t)b * 16 + c) * DM + tid + i * 256] = acc[i];
}

__global__ void mean2_kernel() {
    int b = blockIdx.x;
    int tid = threadIdx.x;
    #pragma unroll
    for (int i = 0; i < 4; i++) {
        int d = tid + i * 256;
        float s = 0.f;
        for (int c = 0; c < 16; c++) s += g_partial[((size_t)b * 16 + c) * DM + d];
        g_hsmean[b * DM + d] = s * (1.0f / (float)SEQ);
    }
}

__global__ void routing_kernel(const float* __restrict__ Wr,
                               const float* __restrict__ temperature,
                               float* __restrict__ out_logits) {
    int tid = threadIdx.x;          // 1024
    int w = tid >> 5, lane = tid & 31;
    int b = w >> 3, c = w & 7;
    float s = 0.f;
    for (int d = lane; d < DM; d += 32)
        s += g_hsmean[b * DM + d] * Wr[c * DM + d];
    #pragma unroll
    for (int o = 16; o; o >>= 1) s += __shfl_down_sync(0xFFFFFFFFu, s, o);
    __shared__ float logits[32];
    if (lane == 0) logits[w] = s;
    if (tid < 8) g_need[tid] = 0;
    __syncthreads();
    if (tid < BATCH) {
        float t = fminf(fmaxf(temperature[0], 0.1f), 10.0f);
        float lv[8];
        #pragma unroll
        for (int cc = 0; cc < 8; cc++) {
            lv[cc] = logits[tid * 8 + cc] / t;
            out_logits[tid * 8 + cc] = lv[cc];
        }
        int i0 = 0;
        #pragma unroll
        for (int cc = 1; cc < 8; cc++) if (lv[cc] > lv[i0]) i0 = cc;
        int i1 = -1;
        #pragma unroll
        for (int cc = 0; cc < 8; cc++) {
            if (cc == i0) continue;
            if (i1 < 0 || lv[cc] > lv[i1]) i1 = cc;
        }
        float e = expf(lv[i1] - lv[i0]);
        g_expert[2 * tid]     = i0;
        g_expert[2 * tid + 1] = i1;
        g_w[2 * tid]     = 1.0f / (1.0f + e);
        g_w[2 * tid + 1] = e / (1.0f + e);
        g_need[i0] = 1;
        g_need[i1] = 1;
    }
}

// ---------------- bf16 tensor-core GEMM ----------------------------------------
// BM=BN=128, BK=64, 3-stage cp.async, 2 CTA/SM.
// MODE 1: bf16 out + fused RoPE (QKV; warp tile 32x64 so rope pairs are in-thread)
// MODE 2: fused silu(gate)*up, interleaved cols -> bf16 act.
// MODE 3: fp32 out + residual (Res fp32; optionally scaled by g_scale per row).
#define ASTG 144
#define BSTG 272
#define ABYTES (128 * ASTG)
#define BBYTES (64 * BSTG)
#define STGB (ABYTES + BBYTES)
#define GEMM_SMEM (3 * STGB)

template<int MODE>
__global__ __launch_bounds__(256, 2) void gemm_bf(
    const bf16* __restrict__ Ab, const bf16* __restrict__ Bb, void* __restrict__ Cb,
    int N, int K, int lda, long long strideA, int a_div2, long long strideC,
    const float* __restrict__ Res, int r_div2, int useScale,
    const float* __restrict__ cosp, const float* __restrict__ sinp)
{
    constexpr int MI = (MODE == 1) ? 2 : 4;
    constexpr int NJ = (MODE == 1) ? 8 : 4;

    extern __shared__ char smraw[];
    uint32_t sb = (uint32_t)__cvta_generic_to_shared(smraw);
    int z = blockIdx.z;
    const bf16* A = Ab + (size_t)(a_div2 ? (z >> 1) : z) * strideA;
    const bf16* B = Bb + (long long)g_expert[z] * ((long long)K * N);
    int m0 = blockIdx.y * 128;
    int n0 = blockIdx.x * 128;
    int tid = threadIdx.x, lane = tid & 31, wid = tid >> 5;
    int wm0, wn0;
    if (MODE == 1) { wm0 = (wid & 3) * 32; wn0 = (wid >> 2) * 64; }
    else           { wm0 = (wid & 1) * 64; wn0 = (wid >> 1) * 32; }
    int g = lane >> 2, t = lane & 3;

    auto load_tile = [&](int k0, int buf) {
        uint32_t base = sb + (uint32_t)(buf * STGB);
        #pragma unroll
        for (int p = 0; p < 4; p++) {
            int i = tid + p * 256;
            int row = i >> 3, ch = i & 7;
            cp16(base + (uint32_t)(row * ASTG + ch * 16),
                 A + (size_t)(m0 + row) * lda + k0 + ch * 8);
        }
        #pragma unroll
        for (int p = 0; p < 4; p++) {
            int i = tid + p * 256;
            int row = i >> 4, ch = i & 15;
            cp16(base + (uint32_t)(ABYTES + row * BSTG + ch * 16),
                 B + (size_t)(k0 + row) * N + n0 + ch * 8);
        }
    };

    int NT = K / 64;
    load_tile(0, 0);
    cp_commit();
    load_tile(64, 1);
    cp_commit();

    float acc[MI][NJ][4];
    #pragma unroll
    for (int i = 0; i < MI; i++)
        #pragma unroll
        for (int j = 0; j < NJ; j++)
            #pragma unroll
            for (int q = 0; q < 4; q++) acc[i][j][q] = 0.f;

    uint32_t af[2][MI][4];
    uint32_t bfr[2][NJ][2];

    int buf = 0;
    for (int tI = 0; tI < NT; ++tI) {
        if (tI + 1 < NT) cp_wait1(); else cp_wait0();
        __syncthreads();
        if (tI + 2 < NT) {
            int nb = buf + 2; if (nb >= 3) nb -= 3;
            load_tile((tI + 2) * 64, nb);
            cp_commit();
        }
        uint32_t stage = sb + (uint32_t)(buf * STGB);
        uint32_t aB = stage + (uint32_t)((wm0 + (lane & 15)) * ASTG + (lane >> 4) * 16);
        uint32_t bB = stage + (uint32_t)(ABYTES + (lane & 15) * BSTG + wn0 * 2);

        #pragma unroll
        for (int i = 0; i < MI; i++) ldsm_x4(af[0][i], aB + (uint32_t)(i * 16 * ASTG));
        #pragma unroll
        for (int j = 0; j < NJ; j++) ldsm_x2t(bfr[0][j], bB + (uint32_t)(j * 16));

        #pragma unroll
        for (int ks = 0; ks < 4; ks++) {
            int cb = ks & 1, nb2 = cb ^ 1;
            if (ks < 3) {
                #pragma unroll
                for (int i = 0; i < MI; i++)
                    ldsm_x4(af[nb2][i], aB + (uint32_t)(i * 16 * ASTG + (ks + 1) * 32));
                #pragma unroll
                for (int j = 0; j < NJ; j++)
                    ldsm_x2t(bfr[nb2][j], bB + (uint32_t)((ks + 1) * 16 * BSTG + j * 16));
            }
            #pragma unroll
            for (int i = 0; i < MI; i++)
                #pragma unroll
                for (int j = 0; j < NJ; j++)
                    mma_bf16(acc[i][j], af[cb][i], bfr[cb][j]);
        }
        buf++; if (buf == 3) buf = 0;
    }

    if (MODE == 1) {
        bf16* C = (bf16*)Cb + (size_t)z * strideC;
        bool isv = (n0 + wn0) >= 2 * DM;   // v columns: no rope
        #pragma unroll
        for (int i = 0; i < MI; i++) {
            int r = m0 + wm0 + i * 16 + g;
            if (isv) {
                #pragma unroll
                for (int j = 0; j < NJ; j++) {
                    int c = n0 + wn0 + j * 8 + 2 * t;
                    *(uint32_t*)(C + (size_t)r * N + c) = packbf(acc[i][j][1], acc[i][j][0]);
                    *(uint32_t*)(C + (size_t)(r + 8) * N + c) = packbf(acc[i][j][3], acc[i][j][2]);
                }
            } else {
                #pragma unroll
                for (int j = 0; j < 4; j++) {
                    int hc = j * 8 + 2 * t;            // [0,32)
                    int c = n0 + wn0 + hc;
                    float2 cl0 = *(const float2*)(cosp + r * HDIM + hc);
                    float2 sl0 = *(const float2*)(sinp + r * HDIM + hc);
                    float2 ch0 = *(const float2*)(cosp + r * HDIM + hc + 32);
                    float2 sh0 = *(const float2*)(sinp + r * HDIM + hc + 32);
                    float2 cl1 = *(const float2*)(cosp + (r + 8) * HDIM + hc);
                    float2 sl1 = *(const float2*)(sinp + (r + 8) * HDIM + hc);
                    float2 ch1 = *(const float2*)(cosp + (r + 8) * HDIM + hc + 32);
                    float2 sh1 = *(const float2*)(sinp + (r + 8) * HDIM + hc + 32);
                    float alo0 = acc[i][j][0], alo1 = acc[i][j][1];
                    float ahi0 = acc[i][j + 4][0], ahi1 = acc[i][j + 4][1];
                    float blo0 = acc[i][j][2], blo1 = acc[i][j][3];
                    float bhi0 = acc[i][j + 4][2], bhi1 = acc[i][j + 4][3];
                    *(uint32_t*)(C + (size_t)r * N + c) =
                        packbf(alo1 * cl0.y - ahi1 * sl0.y, alo0 * cl0.x - ahi0 * sl0.x);
                    *(uint32_t*)(C + (size_t)r * N + c + 32) =
                        packbf(ahi1 * ch0.y + alo1 * sh0.y, ahi0 * ch0.x + alo0 * sh0.x);
                    *(uint32_t*)(C + (size_t)(r + 8) * N + c) =
                        packbf(blo1 * cl1.y - bhi1 * sl1.y, blo0 * cl1.x - bhi0 * sl1.x);
                    *(uint32_t*)(C + (size_t)(r + 8) * N + c + 32) =
                        packbf(bhi1 * ch1.y + blo1 * sh1.y, bhi0 * ch1.x + blo0 * sh1.x);
                }
            }
        }
    } else {
        #pragma unroll
        for (int i = 0; i < MI; i++) {
            int r = m0 + wm0 + i * 16 + g;
            float sc0 = 1.0f, sc1 = 1.0f;
            if (MODE == 3 && useScale) {
                sc0 = g_scale[z * SEQ + r];
                sc1 = g_scale[z * SEQ + r + 8];
            }
            #pragma unroll
            for (int j = 0; j < NJ; j++) {
                int c = n0 + wn0 + j * 8 + 2 * t;
                if (MODE == 2) {
                    bf16* C = (bf16*)Cb + (size_t)z * strideC;
                    int oc = c >> 1;
                    float g0 = acc[i][j][0], u0 = acc[i][j][1];
                    float g1 = acc[i][j][2], u1 = acc[i][j][3];
                    float s0 = g0 / (1.0f + __expf(-g0)) * u0;
                    float s1 = g1 / (1.0f + __expf(-g1)) * u1;
                    C[(size_t)r * (N / 2) + oc]       = __float2bfloat16(s0);
                    C[(size_t)(r + 8) * (N / 2) + oc] = __float2bfloat16(s1);
                } else {  // MODE 3
                    float* C = (float*)Cb + (size_t)z * strideC;
                    const float* R = Res + (size_t)(r_div2 ? (z >> 1) : z) * strideC;
                    float2 r0 = *(const float2*)(R + (size_t)r * N + c);
                    float2 r1 = *(const float2*)(R + (size_t)(r + 8) * N + c);
                    *(float2*)(C + (size_t)r * N + c) =
                        make_float2(acc[i][j][0] + r0.x * sc0, acc[i][j][1] + r0.y * sc0);
                    *(float2*)(C + (size_t)(r + 8) * N + c) =
                        make_float2(acc[i][j][2] + r1.x * sc1, acc[i][j][3] + r1.y * sc1);
                }
            }
        }
    }
}

// ---------------- flash attention (bf16 mma, Q tile 64, 128 thr) ----------------
#define FQ 0
#define FK 9216
#define FV (9216 * 3)
#define FLASH_SMEM (9216 * 5)

__global__ __launch_bounds__(128) void flash_kernel() {
    extern __shared__ char smraw[];
    uint32_t sb = (uint32_t)__cvta_generic_to_shared(smraw);

    int nh = blockIdx.y;
    int n = nh >> 4, h = nh & 15;
    int q0 = blockIdx.x * 64;
    const bf16* qbase = g_qkvb + (size_t)n * SEQ * (3 * DM) + h * HDIM;
    const bf16* kbase = qbase + DM;
    const bf16* vbase = qbase + 2 * DM;

    int tid = threadIdx.x, lane = tid & 31, wid = tid >> 5;
    int g = lane >> 2, t = lane & 3;
    int wm0 = wid * 16;

    #pragma unroll
    for (int p = 0; p < 4; p++) {
        int i = tid + p * 128;
        int row = i >> 3, ch = i & 7;
        cp16(sb + (uint32_t)(FQ + row * 144 + ch * 16),
             qbase + (size_t)(q0 + row) * (3 * DM) + ch * 8);
        cp16(sb + (uint32_t)(FK + row * 144 + ch * 16),
             kbase + (size_t)row * (3 * DM) + ch * 8);
        cp16(sb + (uint32_t)(FV + row * 144 + ch * 16),
             vbase + (size_t)row * (3 * DM) + ch * 8);
    }
    cp_commit();
    cp_wait0();
    __syncthreads();

    uint32_t qf[4][4];
    uint32_t qA = sb + (uint32_t)(FQ + (wm0 + (lane & 15)) * 144 + (lane >> 4) * 16);
    #pragma unroll
    for (int kc = 0; kc < 4; kc++) ldsm_x4(qf[kc], qA + (uint32_t)(kc * 32));

    float m0 = -INFINITY, m1 = -INFINITY, l0 = 0.f, l1 = 0.f;
    float oa[8][4];
    #pragma unroll
    for (int j = 0; j < 8; j++)
        #pragma unroll
        for (int q = 0; q < 4; q++) oa[j][q] = 0.f;

    const int NT = SEQ / 64;
    for (int it = 0; it < NT; it++) {
        int buf = it & 1;
        if (it + 1 < NT) {
            int kv = (it + 1) * 64;
            int ob = buf ^ 1;
            #pragma unroll
            for (int p = 0; p < 4; p++) {
                int i = tid + p * 128;
                int row = i >> 3, ch = i & 7;
                cp16(sb + (uint32_t)(FK + ob * 9216 + row * 144 + ch * 16),
                     kbase + (size_t)(kv + row) * (3 * DM) + ch * 8);
                cp16(sb + (uint32_t)(FV + ob * 9216 + row * 144 + ch * 16),
                     vbase + (size_t)(kv + row) * (3 * DM) + ch * 8);
            }
            cp_commit();
        }
        uint32_t kB = sb + (uint32_t)(FK + buf * 9216);
        uint32_t vB = sb + (uint32_t)(FV + buf * 9216);

        float sacc[8][4];
        #pragma unroll
        for (int j = 0; j < 8; j++)
            #pragma unroll
            for (int q = 0; q < 4; q++) sacc[j][q] = 0.f;

        #pragma unroll
        for (int kc = 0; kc < 4; kc++) {
            #pragma unroll
            for (int nt = 0; nt < 8; nt++) {
                uint32_t ba = kB + (uint32_t)((nt * 8 + g) * 144 + kc * 32 + t * 4);
                uint32_t bb[2];
                bb[0] = lds32(ba);
                bb[1] = lds32(ba + 16);
                mma_bf16(sacc[nt], qf[kc], bb);
            }
        }

        float rm0 = -INFINITY, rm1 = -INFINITY;
        #pragma unroll
        for (int nt = 0; nt < 8; nt++) {
            #pragma unroll
            for (int q = 0; q < 4; q++) sacc[nt][q] *= 0.125f;
            rm0 = fmaxf(rm0, fmaxf(sacc[nt][0], sacc[nt][1]));
            rm1 = fmaxf(rm1, fmaxf(sacc[nt][2], sacc[nt][3]));
        }
        rm0 = fmaxf(rm0, __shfl_xor_sync(0xFFFFFFFFu, rm0, 1));
        rm0 = fmaxf(rm0, __shfl_xor_sync(0xFFFFFFFFu, rm0, 2));
        rm1 = fmaxf(rm1, __shfl_xor_sync(0xFFFFFFFFu, rm1, 1));
        rm1 = fmaxf(rm1, __shfl_xor_sync(0xFFFFFFFFu, rm1, 2));
        float mn0 = fmaxf(m0, rm0), mn1 = fmaxf(m1, rm1);
        float c0 = __expf(m0 - mn0), c1 = __expf(m1 - mn1);
        float ls0 = 0.f, ls1 = 0.f;
        #pragma unroll
        for (int nt = 0; nt < 8; nt++) {
            sacc[nt][0] = __expf(sacc[nt][0] - mn0);
            sacc[nt][1] = __expf(sacc[nt][1] - mn0);
            sacc[nt][2] = __expf(sacc[nt][2] - mn1);
            sacc[nt][3] = __expf(sacc[nt][3] - mn1);
            ls0 += sacc[nt][0] + sacc[nt][1];
            ls1 += sacc[nt][2] + sacc[nt][3];
        }
        ls0 += __shfl_xor_sync(0xFFFFFFFFu, ls0, 1);
        ls0 += __shfl_xor_sync(0xFFFFFFFFu, ls0, 2);
        ls1 += __shfl_xor_sync(0xFFFFFFFFu, ls1, 1);
        ls1 += __shfl_xor_sync(0xFFFFFFFFu, ls1, 2);
        l0 = l0 * c0 + ls0;
        l1 = l1 * c1 + ls1;
        m0 = mn0; m1 = mn1;
        #pragma unroll
        for (int j = 0; j < 8; j++) {
            oa[j][0] *= c0; oa[j][1] *= c0;
            oa[j][2] *= c1; oa[j][3] *= c1;
        }

        #pragma unroll
        for (int mC = 0; mC < 4; mC++) {
            uint32_t pa[4];
            pa[0] = packbf(sacc[2 * mC][1],     sacc[2 * mC][0]);
            pa[1] = packbf(sacc[2 * mC][3],     sacc[2 * mC][2]);
            pa[2] = packbf(sacc[2 * mC + 1][1], sacc[2 * mC + 1][0]);
            pa[3] = packbf(sacc[2 * mC + 1][3], sacc[2 * mC + 1][2]);
            #pragma unroll
            for (int jn = 0; jn < 8; jn++) {
                uint32_t vb[2];
                ldsm_x2t(vb, vB + (uint32_t)((mC * 16 + (lane & 15)) * 144 + jn * 16));
                mma_bf16(oa[jn], pa, vb);
            }
        }

        cp_wait0();
        __syncthreads();
    }

    float inv0 = 1.0f / l0, inv1 = 1.0f / l1;
    int grow0 = q0 + wm0 + g;
    bf16* cbase = g_ctxb + (size_t)n * SEQ * DM + h * HDIM;
    #pragma unroll
    for (int jn = 0; jn < 8; jn++) {
        int col = jn * 8 + 2 * t;
        *(uint32_t*)(cbase + (size_t)grow0 * DM + col) =
            packbf(oa[jn][1] * inv0, oa[jn][0] * inv0);
        *(uint32_t*)(cbase + (size_t)(grow0 + 8) * DM + col) =
            packbf(oa[jn][3] * inv1, oa[jn][2] * inv1);
    }
}

// ---------------- rmsnorm of (x+ao): writes x1b (bf16) + per-row scale ----------
__global__ void resid_rms_kernel() {
    __shared__ float sh[32];
    int ns = blockIdx.x;
    int tid = threadIdx.x;           // 256
    int d0 = tid * 4;
    size_t base = (size_t)ns * DM;
    float4 y = *(const float4*)(g_ao + base + d0);
    float ss = y.x * y.x + y.y * y.y + y.z * y.z + y.w * y.w;
    ss = block_reduce_sum(ss, sh);
    float scale = rsqrtf(ss * (1.0f / (float)DM) + EPS);
    if (tid == 0) g_scale[ns] = scale;
    y.x *= scale; y.y *= scale; y.z *= scale; y.w *= scale;
    uint2 o;
    o.x = packbf(y.y, y.x);
    o.y = packbf(y.w, y.z);
    *(uint2*)(g_x1b + base + d0) = o;
}

// ---------------- final: rmsnorm(x1+mlp) (sum done in Wd epilogue) --------------
__global__ void final_kernel(float* __restrict__ out) {
    __shared__ float sh[32];
    int bs = blockIdx.x;
    int b = bs >> 10, s = bs & 1023;
    int tid = threadIdx.x;
    int n0 = 2 * b, n1 = 2 * b + 1;
    size_t base0 = ((size_t)n0 * SEQ + s) * DM;
    size_t base1 = ((size_t)n1 * SEQ + s) * DM;
    float y0[4], y1[4];
    float ss0 = 0.f, ss1 = 0.f;
    #pragma unroll
    for (int i = 0; i < 4; i++) {
        int d = tid + i * 256;
        y0[i] = g_mlp[base0 + d];
        y1[i] = g_mlp[base1 + d];
        ss0 = fmaf(y0[i], y0[i], ss0);
        ss1 = fmaf(y1[i], y1[i], ss1);
    }
    ss0 = block_reduce_sum(ss0, sh);
    ss1 = block_reduce_sum(ss1, sh);
    float r0 = rsqrtf(ss0 * (1.0f / (float)DM) + EPS) * g_w[n0];
    float r1 = rsqrtf(ss1 * (1.0f / (float)DM) + EPS) * g_w[n1];
    float* orow = out + ((size_t)b * SEQ + s) * DM;
    #pragma unroll
    for (int i = 0; i < 4; i++) {
        int d = tid + i * 256;
        orow[d] = y0[i] * r0 + y1[i] * r1;
    }
}

// ---------------- host launcher --------------------------------------------------
extern "C" void kernel_launch(void* const* d_in, const int* in_sizes, int n_in,
                              void* d_out, int out_size) {
    const float* hidden = (const float*)d_in[0];
    const float* cosb   = (const float*)d_in[1];
    const float* sinb   = (const float*)d_in[2];
    const float* Wr     = (const float*)d_in[3];
    const float* temp   = (const float*)d_in[4];
    const float* Wqkv   = (const float*)d_in[5];
    const float* Wo     = (const float*)d_in[6];
    const float* Wgu    = (const float*)d_in[7];
    const float* Wd     = (const float*)d_in[8];
    float* out = (float*)d_out;

    bf16 *p_hb, *p_qkvb, *p_ctxb, *p_x1b, *p_actb, *p_wb;
    float *p_ao, *p_mlp;
    cudaGetSymbolAddress((void**)&p_hb,   g_hb);
    cudaGetSymbolAddress((void**)&p_qkvb, g_qkvb);
    cudaGetSymbolAddress((void**)&p_ctxb, g_ctxb);
    cudaGetSymbolAddress((void**)&p_x1b,  g_x1b);
    cudaGetSymbolAddress((void**)&p_actb, g_actb);
    cudaGetSymbolAddress((void**)&p_wb,   g_wb);
    cudaGetSymbolAddress((void**)&p_ao,   g_ao);
    cudaGetSymbolAddress((void**)&p_mlp,  g_mlp);

    cudaFuncSetAttribute(flash_kernel,
                         cudaFuncAttributeMaxDynamicSharedMemorySize, FLASH_SMEM);
    cudaFuncSetAttribute((const void*)gemm_bf<1>,
                         cudaFuncAttributeMaxDynamicSharedMemorySize, GEMM_SMEM);
    cudaFuncSetAttribute((const void*)gemm_bf<2>,
                         cudaFuncAttributeMaxDynamicSharedMemorySize, GEMM_SMEM);
    cudaFuncSetAttribute((const void*)gemm_bf<3>,
                         cudaFuncAttributeMaxDynamicSharedMemorySize, GEMM_SMEM);

    // routing first (sets g_need for routed-only weight conversion)
    mean1_kernel<<<dim3(BATCH, 16), 256>>>(hidden);
    mean2_kernel<<<BATCH, 256>>>();
    routing_kernel<<<1, 1024>>>(Wr, temp, out + (size_t)BATCH * SEQ * DM);

    // bf16 conversions (ILP-4)
    {
        int n4 = BATCH * SEQ * DM / 4;
        cvt_bf16<<<(n4 + 1023) / 1024, 256>>>((const float4*)hidden, (uint2*)p_hb, n4);
        n4 = 8 * DM * 3 * DM / 4;
        cvt_w<<<(n4 + 1023) / 1024, 256>>>((const float4*)Wqkv, (uint2*)(p_wb + WB_QKV),
                                           n4, DM * 3 * DM / 4);
        n4 = 8 * DM * DM / 4;
        cvt_w<<<(n4 + 1023) / 1024, 256>>>((const float4*)Wo, (uint2*)(p_wb + WB_WO),
                                           n4, DM * DM / 4);
        int tg = 8 * DM * (INTER / 4);
        cvt_wgu<<<(tg + 511) / 512, 256>>>(Wgu, p_wb + WB_GU, tg);
        n4 = 8 * INTER * DM / 4;
        cvt_w<<<(n4 + 1023) / 1024, 256>>>((const float4*)Wd, (uint2*)(p_wb + WB_WD),
                                           n4, INTER * DM / 4);
    }

    // qkv = x @ Wqkv[e]   (bf16 out, RoPE fused on q,k)
    gemm_bf<1><<<dim3(3072 / 128, SEQ / 128, NSAMP), 256, GEMM_SMEM>>>(
        p_hb, p_wb + WB_QKV, p_qkvb, 3 * DM, DM, DM,
        (long long)SEQ * DM, 1, (long long)SEQ * 3 * DM, nullptr, 0, 0, cosb, sinb);

    // fused attention -> g_ctxb (bf16), Q tile 64
    flash_kernel<<<dim3(SEQ / 64, NSAMP * HN), 128, FLASH_SMEM>>>();

    // g_ao = hidden + ctx @ Wo[e]   (fp32 out + residual)
    gemm_bf<3><<<dim3(DM / 128, SEQ / 128, NSAMP), 256, GEMM_SMEM>>>(
        p_ctxb, p_wb + WB_WO, p_ao, DM, DM, DM,
        (long long)SEQ * DM, 0, (long long)SEQ * DM, hidden, 1, 0, nullptr, nullptr);

    // x1b + g_scale = rmsnorm(g_ao)
    resid_rms_kernel<<<NSAMP * SEQ, 256>>>();

    // act = silu(gate)*up fused into Wgu GEMM (interleaved weights)
    gemm_bf<2><<<dim3(2 * INTER / 128, SEQ / 128, NSAMP), 256, GEMM_SMEM>>>(
        p_x1b, p_wb + WB_GU, p_actb, 2 * INTER, DM, DM,
        (long long)SEQ * DM, 0, (long long)SEQ * INTER, nullptr, 0, 0, nullptr, nullptr);

    // g_mlp = x1 + act @ Wd[e]   (fp32 out + residual = g_ao * g_scale)
    gemm_bf<3><<<dim3(DM / 128, SEQ / 128, NSAMP), 256, GEMM_SMEM>>>(
        p_actb, p_wb + WB_WD, p_mlp, DM, INTER, INTER,
        (long long)SEQ * INTER, 0, (long long)SEQ * DM, p_ao, 0, 1, nullptr, nullptr);

    // out = sum of weighted rmsnorm(g_mlp)
    final_kernel<<<BATCH * SEQ, 256>>>(out);
}

// round 14
// speedup vs baseline: 1.0384x; 1.0148x over previous
#include <cuda_runtime.h>
#include <cuda_bf16.h>
#include <math.h>
#include <stdint.h>

#define SEQ   1024
#define DM    1024
#define HN    16
#define HDIM  64
#define NSAMP 8
#define INTER 768
#define BATCH 4
#define EPS   1e-5f

typedef __nv_bfloat16 bf16;

// ---------------- scratch (device globals; no allocations allowed) ----------
__device__ float g_hsmean[BATCH * DM];
__device__ float g_partial[BATCH * 16 * DM];
__device__ int   g_expert[NSAMP];
__device__ int   g_need[8];
__device__ float g_w[NSAMP];
__device__ float g_scale[NSAMP * SEQ];
__device__ bf16  g_hb[(size_t)BATCH * SEQ * DM];
__device__ bf16  g_qkvb[(size_t)NSAMP * SEQ * 3 * DM];       // 48 MB (rope fused)
__device__ bf16  g_ctxb[(size_t)NSAMP * SEQ * DM];           // 16 MB
__device__ float g_ao[(size_t)NSAMP * SEQ * DM];             // 32 MB (holds x+ao)
__device__ bf16  g_x1b[(size_t)NSAMP * SEQ * DM];            // 16 MB
__device__ bf16  g_actb[(size_t)NSAMP * SEQ * INTER];        // 12 MB
__device__ float g_mlp[(size_t)NSAMP * SEQ * DM];            // 32 MB (holds x1+mlp)
// all-expert bf16 weights (gu stored column-interleaved: 2i=gate_i, 2i+1=up_i)
#define WB_QKV 0LL
#define WB_WO  25165824LL
#define WB_GU  33554432LL
#define WB_WD  46137344LL
#define WB_TOTAL 52428800LL
__device__ bf16 g_wb[WB_TOTAL];                              // 105 MB

// ---------------- small helpers ----------------------------------------------
__device__ __forceinline__ float block_reduce_sum(float v, float* sh) {
    int tid = threadIdx.x;
    #pragma unroll
    for (int o = 16; o; o >>= 1) v += __shfl_down_sync(0xFFFFFFFFu, v, o);
    if ((tid & 31) == 0) sh[tid >> 5] = v;
    __syncthreads();
    float r = 0.f;
    if (tid < 32) {
        float x = (tid < (int)(blockDim.x >> 5)) ? sh[tid] : 0.f;
        #pragma unroll
        for (int o = 16; o; o >>= 1) x += __shfl_down_sync(0xFFFFFFFFu, x, o);
        if (tid == 0) sh[0] = x;
    }
    __syncthreads();
    r = sh[0];
    __syncthreads();
    return r;
}

__device__ __forceinline__ void mma_bf16(float* d, const uint32_t* a, const uint32_t* b) {
    asm volatile(
        "mma.sync.aligned.m16n8k16.row.col.f32.bf16.bf16.f32 "
        "{%0,%1,%2,%3},{%4,%5,%6,%7},{%8,%9},{%0,%1,%2,%3};"
        : "+f"(d[0]), "+f"(d[1]), "+f"(d[2]), "+f"(d[3])
        : "r"(a[0]), "r"(a[1]), "r"(a[2]), "r"(a[3]), "r"(b[0]), "r"(b[1]));
}

__device__ __forceinline__ void ldsm_x4(uint32_t* r, uint32_t addr) {
    asm volatile(
        "ldmatrix.sync.aligned.m8n8.x4.shared.b16 {%0,%1,%2,%3}, [%4];"
        : "=r"(r[0]), "=r"(r[1]), "=r"(r[2]), "=r"(r[3]) : "r"(addr));
}
__device__ __forceinline__ void ldsm_x2t(uint32_t* r, uint32_t addr) {
    asm volatile(
        "ldmatrix.sync.aligned.m8n8.x2.trans.shared.b16 {%0,%1}, [%2];"
        : "=r"(r[0]), "=r"(r[1]) : "r"(addr));
}
__device__ __forceinline__ uint32_t packbf(float hi, float lo) {
    uint32_t r;
    asm("cvt.rn.bf16x2.f32 %0, %1, %2;" : "=r"(r) : "f"(hi), "f"(lo));
    return r;
}

__device__ __forceinline__ void cp16(uint32_t s, const void* g) {
    asm volatile("cp.async.cg.shared.global [%0], [%1], 16;" :: "r"(s), "l"(g));
}
__device__ __forceinline__ void cp_commit() {
    asm volatile("cp.async.commit_group;" ::: "memory");
}
__device__ __forceinline__ void cp_wait0() {
    asm volatile("cp.async.wait_group 0;" ::: "memory");
}
__device__ __forceinline__ void cp_wait1() {
    asm volatile("cp.async.wait_group 1;" ::: "memory");
}

// ---------------- fp32 -> bf16 conversion (ILP-4) ------------------------------
__global__ void cvt_bf16(const float4* __restrict__ s, uint2* __restrict__ d, int n4) {
    int base = blockIdx.x * (blockDim.x * 4) + threadIdx.x;
    float4 v[4];
    bool ok[4];
    #pragma unroll
    for (int u = 0; u < 4; u++) {
        int i = base + u * 256;
        ok[u] = (i < n4);
        if (ok[u]) v[u] = s[i];
    }
    #pragma unroll
    for (int u = 0; u < 4; u++) {
        if (ok[u]) {
            uint2 o;
            o.x = packbf(v[u].y, v[u].x);
            o.y = packbf(v[u].w, v[u].z);
            d[base + u * 256] = o;
        }
    }
}

// convert expert weights only if routed (g_need flag), ILP-4
__global__ void cvt_w(const float4* __restrict__ s, uint2* __restrict__ d,
                      int n4, int perExp4) {
    int base = blockIdx.x * (blockDim.x * 4) + threadIdx.x;
    float4 v[4];
    bool ok[4];
    #pragma unroll
    for (int u = 0; u < 4; u++) {
        int i = base + u * 256;
        ok[u] = (i < n4) && g_need[i / perExp4];
        if (ok[u]) v[u] = s[i];
    }
    #pragma unroll
    for (int u = 0; u < 4; u++) {
        if (ok[u]) {
            uint2 o;
            o.x = packbf(v[u].y, v[u].x);
            o.y = packbf(v[u].w, v[u].z);
            d[base + u * 256] = o;
        }
    }
}

// Wgu: convert + interleave columns (dst col 2i = gate_i, 2i+1 = up_i), ILP-2
__global__ void cvt_wgu(const float* __restrict__ W, bf16* __restrict__ dst, int total) {
    const int perE = DM * (INTER / 4);
    int base = blockIdx.x * (blockDim.x * 2) + threadIdx.x;
    float4 gv[2], uv[2];
    bool ok[2];
    int kk[2], nqq[2], ee[2];
    #pragma unroll
    for (int u = 0; u < 2; u++) {
        int i = base + u * 256;
        ok[u] = false;
        if (i < total) {
            int e = i / perE;
            if (g_need[e]) {
                int rem = i % perE;
                kk[u] = rem / (INTER / 4);
                nqq[u] = rem % (INTER / 4);
                ee[u] = e;
                const float* row = W + ((size_t)e * DM + kk[u]) * (2 * INTER);
                gv[u] = *(const float4*)(row + nqq[u] * 4);
                uv[u] = *(const float4*)(row + INTER + nqq[u] * 4);
                ok[u] = true;
            }
        }
    }
    #pragma unroll
    for (int u = 0; u < 2; u++) {
        if (ok[u]) {
            uint4 o;
            o.x = packbf(uv[u].x, gv[u].x);
            o.y = packbf(uv[u].y, gv[u].y);
            o.z = packbf(uv[u].z, gv[u].z);
            o.w = packbf(uv[u].w, gv[u].w);
            *(uint4*)(dst + ((size_t)ee[u] * DM + kk[u]) * (2 * INTER) + nqq[u] * 8) = o;
        }
    }
}

// ---------------- routing ----------------------------------------------------
__global__ void mean1_kernel(const float* __restrict__ hidden) {
    int b = blockIdx.x, c = blockIdx.y;
    int tid = threadIdx.x;
    float acc[4] = {0.f, 0.f, 0.f, 0.f};
    for (int s = c * 64; s < c * 64 + 64; s++) {
        const float* row = hidden + ((size_t)b * SEQ + s) * DM;
        #pragma unroll
        for (int i = 0; i < 4; i++) acc[i] += row[tid + i * 256];
    }
    #pragma unroll
    for (int i = 0; i < 4; i++)
        g_partial[((size_t)b * 16 + c) * DM + tid + i * 256] = acc[i];
}

__global__ void mean2_kernel() {
    int b = blockIdx.x;
    int tid = threadIdx.x;
    #pragma unroll
    for (int i = 0; i < 4; i++) {
        int d = tid + i * 256;
        float s = 0.f;
        for (int c = 0; c < 16; c++) s += g_partial[((size_t)b * 16 + c) * DM + d];
        g_hsmean[b * DM + d] = s * (1.0f / (float)SEQ);
    }
}

__global__ void routing_kernel(const float* __restrict__ Wr,
                               const float* __restrict__ temperature,
                               float* __restrict__ out_logits) {
    int tid = threadIdx.x;          // 1024
    int w = tid >> 5, lane = tid & 31;
    int b = w >> 3, c = w & 7;
    float s = 0.f;
    for (int d = lane; d < DM; d += 32)
        s += g_hsmean[b * DM + d] * Wr[c * DM + d];
    #pragma unroll
    for (int o = 16; o; o >>= 1) s += __shfl_down_sync(0xFFFFFFFFu, s, o);
    __shared__ float logits[32];
    if (lane == 0) logits[w] = s;
    if (tid < 8) g_need[tid] = 0;
    __syncthreads();
    if (tid < BATCH) {
        float t = fminf(fmaxf(temperature[0], 0.1f), 10.0f);
        float lv[8];
        #pragma unroll
        for (int cc = 0; cc < 8; cc++) {
            lv[cc] = logits[tid * 8 + cc] / t;
            out_logits[tid * 8 + cc] = lv[cc];
        }
        int i0 = 0;
        #pragma unroll
        for (int cc = 1; cc < 8; cc++) if (lv[cc] > lv[i0]) i0 = cc;
        int i1 = -1;
        #pragma unroll
        for (int cc = 0; cc < 8; cc++) {
            if (cc == i0) continue;
            if (i1 < 0 || lv[cc] > lv[i1]) i1 = cc;
        }
        float e = expf(lv[i1] - lv[i0]);
        g_expert[2 * tid]     = i0;
        g_expert[2 * tid + 1] = i1;
        g_w[2 * tid]     = 1.0f / (1.0f + e);
        g_w[2 * tid + 1] = e / (1.0f + e);
        g_need[i0] = 1;
        g_need[i1] = 1;
    }
}

// ---------------- bf16 tensor-core GEMM ----------------------------------------
// BM=BN=128, BK=64, 3-stage cp.async, 2 CTA/SM.
// MODE 1: bf16 out + fused RoPE (QKV; warp tile 32x64 so rope pairs are in-thread)
// MODE 2: fused silu(gate)*up, interleaved cols -> bf16 act.
// MODE 3: fp32 out + residual (Res fp32; optionally scaled by g_scale per row).
#define ASTG 144
#define BSTG 272
#define ABYTES (128 * ASTG)
#define BBYTES (64 * BSTG)
#define STGB (ABYTES + BBYTES)
#define GEMM_SMEM (3 * STGB)

template<int MODE>
__global__ __launch_bounds__(256, 2) void gemm_bf(
    const bf16* __restrict__ Ab, const bf16* __restrict__ Bb, void* __restrict__ Cb,
    int N, int K, int lda, long long strideA, int a_div2, long long strideC,
    const float* __restrict__ Res, int r_div2, int useScale,
    const float* __restrict__ cosp, const float* __restrict__ sinp)
{
    constexpr int MI = (MODE == 1) ? 2 : 4;
    constexpr int NJ = (MODE == 1) ? 8 : 4;

    extern __shared__ char smraw[];
    uint32_t sb = (uint32_t)__cvta_generic_to_shared(smraw);
    int z = blockIdx.z;
    const bf16* A = Ab + (size_t)(a_div2 ? (z >> 1) : z) * strideA;
    const bf16* B = Bb + (long long)g_expert[z] * ((long long)K * N);
    int m0 = blockIdx.y * 128;
    int n0 = blockIdx.x * 128;
    int tid = threadIdx.x, lane = tid & 31, wid = tid >> 5;
    int wm0, wn0;
    if (MODE == 1) { wm0 = (wid & 3) * 32; wn0 = (wid >> 2) * 64; }
    else           { wm0 = (wid & 1) * 64; wn0 = (wid >> 1) * 32; }
    int g = lane >> 2, t = lane & 3;

    auto load_tile = [&](int k0, int buf) {
        uint32_t base = sb + (uint32_t)(buf * STGB);
        #pragma unroll
        for (int p = 0; p < 4; p++) {
            int i = tid + p * 256;
            int row = i >> 3, ch = i & 7;
            cp16(base + (uint32_t)(row * ASTG + ch * 16),
                 A + (size_t)(m0 + row) * lda + k0 + ch * 8);
        }
        #pragma unroll
        for (int p = 0; p < 4; p++) {
            int i = tid + p * 256;
            int row = i >> 4, ch = i & 15;
            cp16(base + (uint32_t)(ABYTES + row * BSTG + ch * 16),
                 B + (size_t)(k0 + row) * N + n0 + ch * 8);
        }
    };

    int NT = K / 64;
    load_tile(0, 0);
    cp_commit();
    load_tile(64, 1);
    cp_commit();

    float acc[MI][NJ][4];
    #pragma unroll
    for (int i = 0; i < MI; i++)
        #pragma unroll
        for (int j = 0; j < NJ; j++)
            #pragma unroll
            for (int q = 0; q < 4; q++) acc[i][j][q] = 0.f;

    uint32_t af[2][MI][4];
    uint32_t bfr[2][NJ][2];

    int buf = 0;
    for (int tI = 0; tI < NT; ++tI) {
        if (tI + 1 < NT) cp_wait1(); else cp_wait0();
        __syncthreads();
        if (tI + 2 < NT) {
            int nb = buf + 2; if (nb >= 3) nb -= 3;
            load_tile((tI + 2) * 64, nb);
            cp_commit();
        }
        uint32_t stage = sb + (uint32_t)(buf * STGB);
        uint32_t aB = stage + (uint32_t)((wm0 + (lane & 15)) * ASTG + (lane >> 4) * 16);
        uint32_t bB = stage + (uint32_t)(ABYTES + (lane & 15) * BSTG + wn0 * 2);

        #pragma unroll
        for (int i = 0; i < MI; i++) ldsm_x4(af[0][i], aB + (uint32_t)(i * 16 * ASTG));
        #pragma unroll
        for (int j = 0; j < NJ; j++) ldsm_x2t(bfr[0][j], bB + (uint32_t)(j * 16));

        #pragma unroll
        for (int ks = 0; ks < 4; ks++) {
            int cb = ks & 1, nb2 = cb ^ 1;
            if (ks < 3) {
                #pragma unroll
                for (int i = 0; i < MI; i++)
                    ldsm_x4(af[nb2][i], aB + (uint32_t)(i * 16 * ASTG + (ks + 1) * 32));
                #pragma unroll
                for (int j = 0; j < NJ; j++)
                    ldsm_x2t(bfr[nb2][j], bB + (uint32_t)((ks + 1) * 16 * BSTG + j * 16));
            }
            #pragma unroll
            for (int i = 0; i < MI; i++)
                #pragma unroll
                for (int j = 0; j < NJ; j++)
                    mma_bf16(acc[i][j], af[cb][i], bfr[cb][j]);
        }
        buf++; if (buf == 3) buf = 0;
    }

    if (MODE == 1) {
        bf16* C = (bf16*)Cb + (size_t)z * strideC;
        bool isv = (n0 + wn0) >= 2 * DM;   // v columns: no rope
        #pragma unroll
        for (int i = 0; i < MI; i++) {
            int r = m0 + wm0 + i * 16 + g;
            if (isv) {
                #pragma unroll
                for (int j = 0; j < NJ; j++) {
                    int c = n0 + wn0 + j * 8 + 2 * t;
                    *(uint32_t*)(C + (size_t)r * N + c) = packbf(acc[i][j][1], acc[i][j][0]);
                    *(uint32_t*)(C + (size_t)(r + 8) * N + c) = packbf(acc[i][j][3], acc[i][j][2]);
                }
            } else {
                #pragma unroll
                for (int j = 0; j < 4; j++) {
                    int hc = j * 8 + 2 * t;            // [0,32)
                    int c = n0 + wn0 + hc;
                    float2 cl0 = *(const float2*)(cosp + r * HDIM + hc);
                    float2 sl0 = *(const float2*)(sinp + r * HDIM + hc);
                    float2 ch0 = *(const float2*)(cosp + r * HDIM + hc + 32);
                    float2 sh0 = *(const float2*)(sinp + r * HDIM + hc + 32);
                    float2 cl1 = *(const float2*)(cosp + (r + 8) * HDIM + hc);
                    float2 sl1 = *(const float2*)(sinp + (r + 8) * HDIM + hc);
                    float2 ch1 = *(const float2*)(cosp + (r + 8) * HDIM + hc + 32);
                    float2 sh1 = *(const float2*)(sinp + (r + 8) * HDIM + hc + 32);
                    float alo0 = acc[i][j][0], alo1 = acc[i][j][1];
                    float ahi0 = acc[i][j + 4][0], ahi1 = acc[i][j + 4][1];
                    float blo0 = acc[i][j][2], blo1 = acc[i][j][3];
                    float bhi0 = acc[i][j + 4][2], bhi1 = acc[i][j + 4][3];
                    *(uint32_t*)(C + (size_t)r * N + c) =
                        packbf(alo1 * cl0.y - ahi1 * sl0.y, alo0 * cl0.x - ahi0 * sl0.x);
                    *(uint32_t*)(C + (size_t)r * N + c + 32) =
                        packbf(ahi1 * ch0.y + alo1 * sh0.y, ahi0 * ch0.x + alo0 * sh0.x);
                    *(uint32_t*)(C + (size_t)(r + 8) * N + c) =
                        packbf(blo1 * cl1.y - bhi1 * sl1.y, blo0 * cl1.x - bhi0 * sl1.x);
                    *(uint32_t*)(C + (size_t)(r + 8) * N + c + 32) =
                        packbf(bhi1 * ch1.y + blo1 * sh1.y, bhi0 * ch1.x + blo0 * sh1.x);
                }
            }
        }
    } else {
        #pragma unroll
        for (int i = 0; i < MI; i++) {
            int r = m0 + wm0 + i * 16 + g;
            float sc0 = 1.0f, sc1 = 1.0f;
            if (MODE == 3 && useScale) {
                sc0 = g_scale[z * SEQ + r];
                sc1 = g_scale[z * SEQ + r + 8];
            }
            #pragma unroll
            for (int j = 0; j < NJ; j++) {
                int c = n0 + wn0 + j * 8 + 2 * t;
                if (MODE == 2) {
                    bf16* C = (bf16*)Cb + (size_t)z * strideC;
                    int oc = c >> 1;
                    float g0 = acc[i][j][0], u0 = acc[i][j][1];
                    float g1 = acc[i][j][2], u1 = acc[i][j][3];
                    float s0 = g0 / (1.0f + __expf(-g0)) * u0;
                    float s1 = g1 / (1.0f + __expf(-g1)) * u1;
                    C[(size_t)r * (N / 2) + oc]       = __float2bfloat16(s0);
                    C[(size_t)(r + 8) * (N / 2) + oc] = __float2bfloat16(s1);
                } else {  // MODE 3
                    float* C = (float*)Cb + (size_t)z * strideC;
                    const float* R = Res + (size_t)(r_div2 ? (z >> 1) : z) * strideC;
                    float2 r0 = *(const float2*)(R + (size_t)r * N + c);
                    float2 r1 = *(const float2*)(R + (size_t)(r + 8) * N + c);
                    *(float2*)(C + (size_t)r * N + c) =
                        make_float2(acc[i][j][0] + r0.x * sc0, acc[i][j][1] + r0.y * sc0);
                    *(float2*)(C + (size_t)(r + 8) * N + c) =
                        make_float2(acc[i][j][2] + r1.x * sc1, acc[i][j][3] + r1.y * sc1);
                }
            }
        }
    }
}

// ---------------- flash attention (bf16 mma, Q tile 64, 128 thr) ----------------
// QK^T B-fragments via ldmatrix.x4 (non-trans): lanes 0-7 -> rows nt*8+l (k lo 16B),
// 8-15 -> same rows k hi, 16-23/24-31 -> rows (nt+1)*8+l. Fragments land as
// {b0,b1} of nt and {b0,b1} of nt+1 (identical values to the previous scalar loads).
#define FQ 0
#define FK 9216
#define FV (9216 * 3)
#define FLASH_SMEM (9216 * 5)

__global__ __launch_bounds__(128) void flash_kernel() {
    extern __shared__ char smraw[];
    uint32_t sb = (uint32_t)__cvta_generic_to_shared(smraw);

    int nh = blockIdx.y;
    int n = nh >> 4, h = nh & 15;
    int q0 = blockIdx.x * 64;
    const bf16* qbase = g_qkvb + (size_t)n * SEQ * (3 * DM) + h * HDIM;
    const bf16* kbase = qbase + DM;
    const bf16* vbase = qbase + 2 * DM;

    int tid = threadIdx.x, lane = tid & 31, wid = tid >> 5;
    int g = lane >> 2, t = lane & 3;
    int wm0 = wid * 16;

    // per-lane ldsm address component for QK^T B tiles
    int rowL = (lane & 7) + ((lane >> 4) << 3);   // 0-7 (m0/m1), 8-15 (m2/m3)
    int colL = ((lane >> 3) & 1) * 16;            // k-lo / k-hi 16B chunk
    uint32_t kLane = (uint32_t)(rowL * 144 + colL);

    #pragma unroll
    for (int p = 0; p < 4; p++) {
        int i = tid + p * 128;
        int row = i >> 3, ch = i & 7;
        cp16(sb + (uint32_t)(FQ + row * 144 + ch * 16),
             qbase + (size_t)(q0 + row) * (3 * DM) + ch * 8);
        cp16(sb + (uint32_t)(FK + row * 144 + ch * 16),
             kbase + (size_t)row * (3 * DM) + ch * 8);
        cp16(sb + (uint32_t)(FV + row * 144 + ch * 16),
             vbase + (size_t)row * (3 * DM) + ch * 8);
    }
    cp_commit();
    cp_wait0();
    __syncthreads();

    uint32_t qf[4][4];
    uint32_t qA = sb + (uint32_t)(FQ + (wm0 + (lane & 15)) * 144 + (lane >> 4) * 16);
    #pragma unroll
    for (int kc = 0; kc < 4; kc++) ldsm_x4(qf[kc], qA + (uint32_t)(kc * 32));

    float m0 = -INFINITY, m1 = -INFINITY, l0 = 0.f, l1 = 0.f;
    float oa[8][4];
    #pragma unroll
    for (int j = 0; j < 8; j++)
        #pragma unroll
        for (int q = 0; q < 4; q++) oa[j][q] = 0.f;

    const int NT = SEQ / 64;
    for (int it = 0; it < NT; it++) {
        int buf = it & 1;
        if (it + 1 < NT) {
            int kv = (it + 1) * 64;
            int ob = buf ^ 1;
            #pragma unroll
            for (int p = 0; p < 4; p++) {
                int i = tid + p * 128;
                int row = i >> 3, ch = i & 7;
                cp16(sb + (uint32_t)(FK + ob * 9216 + row * 144 + ch * 16),
                     kbase + (size_t)(kv + row) * (3 * DM) + ch * 8);
                cp16(sb + (uint32_t)(FV + ob * 9216 + row * 144 + ch * 16),
                     vbase + (size_t)(kv + row) * (3 * DM) + ch * 8);
            }
            cp_commit();
        }
        uint32_t kB = sb + (uint32_t)(FK + buf * 9216) + kLane;
        uint32_t vB = sb + (uint32_t)(FV + buf * 9216);

        float sacc[8][4];
        #pragma unroll
        for (int j = 0; j < 8; j++)
            #pragma unroll
            for (int q = 0; q < 4; q++) sacc[j][q] = 0.f;

        #pragma unroll
        for (int kc = 0; kc < 4; kc++) {
            #pragma unroll
            for (int ntp = 0; ntp < 4; ntp++) {
                uint32_t bb[4];
                ldsm_x4(bb, kB + (uint32_t)(ntp * 16 * 144 + kc * 32));
                mma_bf16(sacc[2 * ntp],     qf[kc], bb);
                mma_bf16(sacc[2 * ntp + 1], qf[kc], bb + 2);
            }
        }

        float rm0 = -INFINITY, rm1 = -INFINITY;
        #pragma unroll
        for (int nt = 0; nt < 8; nt++) {
            #pragma unroll
            for (int q = 0; q < 4; q++) sacc[nt][q] *= 0.125f;
            rm0 = fmaxf(rm0, fmaxf(sacc[nt][0], sacc[nt][1]));
            rm1 = fmaxf(rm1, fmaxf(sacc[nt][2], sacc[nt][3]));
        }
        rm0 = fmaxf(rm0, __shfl_xor_sync(0xFFFFFFFFu, rm0, 1));
        rm0 = fmaxf(rm0, __shfl_xor_sync(0xFFFFFFFFu, rm0, 2));
        rm1 = fmaxf(rm1, __shfl_xor_sync(0xFFFFFFFFu, rm1, 1));
        rm1 = fmaxf(rm1, __shfl_xor_sync(0xFFFFFFFFu, rm1, 2));
        float mn0 = fmaxf(m0, rm0), mn1 = fmaxf(m1, rm1);
        float c0 = __expf(m0 - mn0), c1 = __expf(m1 - mn1);
        float ls0 = 0.f, ls1 = 0.f;
        #pragma unroll
        for (int nt = 0; nt < 8; nt++) {
            sacc[nt][0] = __expf(sacc[nt][0] - mn0);
            sacc[nt][1] = __expf(sacc[nt][1] - mn0);
            sacc[nt][2] = __expf(sacc[nt][2] - mn1);
            sacc[nt][3] = __expf(sacc[nt][3] - mn1);
            ls0 += sacc[nt][0] + sacc[nt][1];
            ls1 += sacc[nt][2] + sacc[nt][3];
        }
        ls0 += __shfl_xor_sync(0xFFFFFFFFu, ls0, 1);
        ls0 += __shfl_xor_sync(0xFFFFFFFFu, ls0, 2);
        ls1 += __shfl_xor_sync(0xFFFFFFFFu, ls1, 1);
        ls1 += __shfl_xor_sync(0xFFFFFFFFu, ls1, 2);
        l0 = l0 * c0 + ls0;
        l1 = l1 * c1 + ls1;
        m0 = mn0; m1 = mn1;
        #pragma unroll
        for (int j = 0; j < 8; j++) {
            oa[j][0] *= c0; oa[j][1] *= c0;
            oa[j][2] *= c1; oa[j][3] *= c1;
        }

        #pragma unroll
        for (int mC = 0; mC < 4; mC++) {
            uint32_t pa[4];
            pa[0] = packbf(sacc[2 * mC][1],     sacc[2 * mC][0]);
            pa[1] = packbf(sacc[2 * mC][3],     sacc[2 * mC][2]);
            pa[2] = packbf(sacc[2 * mC + 1][1], sacc[2 * mC + 1][0]);
            pa[3] = packbf(sacc[2 * mC + 1][3], sacc[2 * mC + 1][2]);
            #pragma unroll
            for (int jn = 0; jn < 8; jn++) {
                uint32_t vb[2];
                ldsm_x2t(vb, vB + (uint32_t)((mC * 16 + (lane & 15)) * 144 + jn * 16));
                mma_bf16(oa[jn], pa, vb);
            }
        }

        cp_wait0();
        __syncthreads();
    }

    float inv0 = 1.0f / l0, inv1 = 1.0f / l1;
    int grow0 = q0 + wm0 + g;
    bf16* cbase = g_ctxb + (size_t)n * SEQ * DM + h * HDIM;
    #pragma unroll
    for (int jn = 0; jn < 8; jn++) {
        int col = jn * 8 + 2 * t;
        *(uint32_t*)(cbase + (size_t)grow0 * DM + col) =
            packbf(oa[jn][1] * inv0, oa[jn][0] * inv0);
        *(uint32_t*)(cbase + (size_t)(grow0 + 8) * DM + col) =
            packbf(oa[jn][3] * inv1, oa[jn][2] * inv1);
    }
}

// ---------------- rmsnorm of (x+ao): writes x1b (bf16) + per-row scale ----------
__global__ void resid_rms_kernel() {
    __shared__ float sh[32];
    int ns = blockIdx.x;
    int tid = threadIdx.x;           // 256
    int d0 = tid * 4;
    size_t base = (size_t)ns * DM;
    float4 y = *(const float4*)(g_ao + base + d0);
    float ss = y.x * y.x + y.y * y.y + y.z * y.z + y.w * y.w;
    ss = block_reduce_sum(ss, sh);
    float scale = rsqrtf(ss * (1.0f / (float)DM) + EPS);
    if (tid == 0) g_scale[ns] = scale;
    y.x *= scale; y.y *= scale; y.z *= scale; y.w *= scale;
    uint2 o;
    o.x = packbf(y.y, y.x);
    o.y = packbf(y.w, y.z);
    *(uint2*)(g_x1b + base + d0) = o;
}

// ---------------- final: rmsnorm(x1+mlp) (sum done in Wd epilogue) --------------
__global__ void final_kernel(float* __restrict__ out) {
    __shared__ float sh[32];
    int bs = blockIdx.x;
    int b = bs >> 10, s = bs & 1023;
    int tid = threadIdx.x;
    int n0 = 2 * b, n1 = 2 * b + 1;
    size_t base0 = ((size_t)n0 * SEQ + s) * DM;
    size_t base1 = ((size_t)n1 * SEQ + s) * DM;
    float y0[4], y1[4];
    float ss0 = 0.f, ss1 = 0.f;
    #pragma unroll
    for (int i = 0; i < 4; i++) {
        int d = tid + i * 256;
        y0[i] = g_mlp[base0 + d];
        y1[i] = g_mlp[base1 + d];
        ss0 = fmaf(y0[i], y0[i], ss0);
        ss1 = fmaf(y1[i], y1[i], ss1);
    }
    ss0 = block_reduce_sum(ss0, sh);
    ss1 = block_reduce_sum(ss1, sh);
    float r0 = rsqrtf(ss0 * (1.0f / (float)DM) + EPS) * g_w[n0];
    float r1 = rsqrtf(ss1 * (1.0f / (float)DM) + EPS) * g_w[n1];
    float* orow = out + ((size_t)b * SEQ + s) * DM;
    #pragma unroll
    for (int i = 0; i < 4; i++) {
        int d = tid + i * 256;
        orow[d] = y0[i] * r0 + y1[i] * r1;
    }
}

// ---------------- host launcher --------------------------------------------------
extern "C" void kernel_launch(void* const* d_in, const int* in_sizes, int n_in,
                              void* d_out, int out_size) {
    const float* hidden = (const float*)d_in[0];
    const float* cosb   = (const float*)d_in[1];
    const float* sinb   = (const float*)d_in[2];
    const float* Wr     = (const float*)d_in[3];
    const float* temp   = (const float*)d_in[4];
    const float* Wqkv   = (const float*)d_in[5];
    const float* Wo     = (const float*)d_in[6];
    const float* Wgu    = (const float*)d_in[7];
    const float* Wd     = (const float*)d_in[8];
    float* out = (float*)d_out;

    bf16 *p_hb, *p_qkvb, *p_ctxb, *p_x1b, *p_actb, *p_wb;
    float *p_ao, *p_mlp;
    cudaGetSymbolAddress((void**)&p_hb,   g_hb);
    cudaGetSymbolAddress((void**)&p_qkvb, g_qkvb);
    cudaGetSymbolAddress((void**)&p_ctxb, g_ctxb);
    cudaGetSymbolAddress((void**)&p_x1b,  g_x1b);
    cudaGetSymbolAddress((void**)&p_actb, g_actb);
    cudaGetSymbolAddress((void**)&p_wb,   g_wb);
    cudaGetSymbolAddress((void**)&p_ao,   g_ao);
    cudaGetSymbolAddress((void**)&p_mlp,  g_mlp);

    cudaFuncSetAttribute(flash_kernel,
                         cudaFuncAttributeMaxDynamicSharedMemorySize, FLASH_SMEM);
    cudaFuncSetAttribute((const void*)gemm_bf<1>,
                         cudaFuncAttributeMaxDynamicSharedMemorySize, GEMM_SMEM);
    cudaFuncSetAttribute((const void*)gemm_bf<2>,
                         cudaFuncAttributeMaxDynamicSharedMemorySize, GEMM_SMEM);
    cudaFuncSetAttribute((const void*)gemm_bf<3>,
                         cudaFuncAttributeMaxDynamicSharedMemorySize, GEMM_SMEM);

    // routing first (sets g_need for routed-only weight conversion)
    mean1_kernel<<<dim3(BATCH, 16), 256>>>(hidden);
    mean2_kernel<<<BATCH, 256>>>();
    routing_kernel<<<1, 1024>>>(Wr, temp, out + (size_t)BATCH * SEQ * DM);

    // bf16 conversions (ILP-4)
    {
        int n4 = BATCH * SEQ * DM / 4;
        cvt_bf16<<<(n4 + 1023) / 1024, 256>>>((const float4*)hidden, (uint2*)p_hb, n4);
        n4 = 8 * DM * 3 * DM / 4;
        cvt_w<<<(n4 + 1023) / 1024, 256>>>((const float4*)Wqkv, (uint2*)(p_wb + WB_QKV),
                                           n4, DM * 3 * DM / 4);
        n4 = 8 * DM * DM / 4;
        cvt_w<<<(n4 + 1023) / 1024, 256>>>((const float4*)Wo, (uint2*)(p_wb + WB_WO),
                                           n4, DM * DM / 4);
        int tg = 8 * DM * (INTER / 4);
        cvt_wgu<<<(tg + 511) / 512, 256>>>(Wgu, p_wb + WB_GU, tg);
        n4 = 8 * INTER * DM / 4;
        cvt_w<<<(n4 + 1023) / 1024, 256>>>((const float4*)Wd, (uint2*)(p_wb + WB_WD),
                                           n4, INTER * DM / 4);
    }

    // qkv = x @ Wqkv[e]   (bf16 out, RoPE fused on q,k)
    gemm_bf<1><<<dim3(3072 / 128, SEQ / 128, NSAMP), 256, GEMM_SMEM>>>(
        p_hb, p_wb + WB_QKV, p_qkvb, 3 * DM, DM, DM,
        (long long)SEQ * DM, 1, (long long)SEQ * 3 * DM, nullptr, 0, 0, cosb, sinb);

    // fused attention -> g_ctxb (bf16), Q tile 64
    flash_kernel<<<dim3(SEQ / 64, NSAMP * HN), 128, FLASH_SMEM>>>();

    // g_ao = hidden + ctx @ Wo[e]   (fp32 out + residual)
    gemm_bf<3><<<dim3(DM / 128, SEQ / 128, NSAMP), 256, GEMM_SMEM>>>(
        p_ctxb, p_wb + WB_WO, p_ao, DM, DM, DM,
        (long long)SEQ * DM, 0, (long long)SEQ * DM, hidden, 1, 0, nullptr, nullptr);

    // x1b + g_scale = rmsnorm(g_ao)
    resid_rms_kernel<<<NSAMP * SEQ, 256>>>();

    // act = silu(gate)*up fused into Wgu GEMM (interleaved weights)
    gemm_bf<2><<<dim3(2 * INTER / 128, SEQ / 128, NSAMP), 256, GEMM_SMEM>>>(
        p_x1b, p_wb + WB_GU, p_actb, 2 * INTER, DM, DM,
        (long long)SEQ * DM, 0, (long long)SEQ * INTER, nullptr, 0, 0, nullptr, nullptr);

    // g_mlp = x1 + act @ Wd[e]   (fp32 out + residual = g_ao * g_scale)
    gemm_bf<3><<<dim3(DM / 128, SEQ / 128, NSAMP), 256, GEMM_SMEM>>>(
        p_actb, p_wb + WB_WD, p_mlp, DM, INTER, INTER,
        (long long)SEQ * INTER, 0, (long long)SEQ * DM, p_ao, 0, 1, nullptr, nullptr);

    // out = sum of weighted rmsnorm(g_mlp)
    final_kernel<<<BATCH * SEQ, 256>>>(out);
}

// round 15
// speedup vs baseline: 1.0440x; 1.0054x over previous
#include <cuda_runtime.h>
#include <cuda_bf16.h>
#include <math.h>
#include <stdint.h>

#define SEQ   1024
#define DM    1024
#define HN    16
#define HDIM  64
#define NSAMP 8
#define INTER 768
#define BATCH 4
#define EPS   1e-5f

typedef __nv_bfloat16 bf16;

// ---------------- scratch (device globals; no allocations allowed) ----------
__device__ float g_hsmean[BATCH * DM];
__device__ float g_partial[BATCH * 16 * DM];
__device__ int   g_expert[NSAMP];
__device__ int   g_need[8];
__device__ float g_w[NSAMP];
__device__ float g_scale[NSAMP * SEQ];
__device__ bf16  g_hb[(size_t)BATCH * SEQ * DM];
__device__ bf16  g_qkvb[(size_t)NSAMP * SEQ * 3 * DM];       // 48 MB (rope fused)
__device__ bf16  g_ctxb[(size_t)NSAMP * SEQ * DM];           // 16 MB
__device__ float g_ao[(size_t)NSAMP * SEQ * DM];             // 32 MB (holds x+ao)
__device__ bf16  g_x1b[(size_t)NSAMP * SEQ * DM];            // 16 MB
__device__ bf16  g_actb[(size_t)NSAMP * SEQ * INTER];        // 12 MB
__device__ float g_mlp[(size_t)NSAMP * SEQ * DM];            // 32 MB (holds x1+mlp)
// all-expert bf16 weights (gu stored column-interleaved: 2i=gate_i, 2i+1=up_i)
#define WB_QKV 0LL
#define WB_WO  25165824LL
#define WB_GU  33554432LL
#define WB_WD  46137344LL
#define WB_TOTAL 52428800LL
__device__ bf16 g_wb[WB_TOTAL];                              // 105 MB

// ---------------- small helpers ----------------------------------------------
__device__ __forceinline__ float block_reduce_sum(float v, float* sh) {
    int tid = threadIdx.x;
    #pragma unroll
    for (int o = 16; o; o >>= 1) v += __shfl_down_sync(0xFFFFFFFFu, v, o);
    if ((tid & 31) == 0) sh[tid >> 5] = v;
    __syncthreads();
    float r = 0.f;
    if (tid < 32) {
        float x = (tid < (int)(blockDim.x >> 5)) ? sh[tid] : 0.f;
        #pragma unroll
        for (int o = 16; o; o >>= 1) x += __shfl_down_sync(0xFFFFFFFFu, x, o);
        if (tid == 0) sh[0] = x;
    }
    __syncthreads();
    r = sh[0];
    __syncthreads();
    return r;
}

__device__ __forceinline__ void mma_bf16(float* d, const uint32_t* a, const uint32_t* b) {
    asm volatile(
        "mma.sync.aligned.m16n8k16.row.col.f32.bf16.bf16.f32 "
        "{%0,%1,%2,%3},{%4,%5,%6,%7},{%8,%9},{%0,%1,%2,%3};"
        : "+f"(d[0]), "+f"(d[1]), "+f"(d[2]), "+f"(d[3])
        : "r"(a[0]), "r"(a[1]), "r"(a[2]), "r"(a[3]), "r"(b[0]), "r"(b[1]));
}

__device__ __forceinline__ void ldsm_x4(uint32_t* r, uint32_t addr) {
    asm volatile(
        "ldmatrix.sync.aligned.m8n8.x4.shared.b16 {%0,%1,%2,%3}, [%4];"
        : "=r"(r[0]), "=r"(r[1]), "=r"(r[2]), "=r"(r[3]) : "r"(addr));
}
__device__ __forceinline__ void ldsm_x4t(uint32_t* r, uint32_t addr) {
    asm volatile(
        "ldmatrix.sync.aligned.m8n8.x4.trans.shared.b16 {%0,%1,%2,%3}, [%4];"
        : "=r"(r[0]), "=r"(r[1]), "=r"(r[2]), "=r"(r[3]) : "r"(addr));
}
__device__ __forceinline__ uint32_t packbf(float hi, float lo) {
    uint32_t r;
    asm("cvt.rn.bf16x2.f32 %0, %1, %2;" : "=r"(r) : "f"(hi), "f"(lo));
    return r;
}

__device__ __forceinline__ void cp16(uint32_t s, const void* g) {
    asm volatile("cp.async.cg.shared.global [%0], [%1], 16;" :: "r"(s), "l"(g));
}
__device__ __forceinline__ void cp_commit() {
    asm volatile("cp.async.commit_group;" ::: "memory");
}
__device__ __forceinline__ void cp_wait0() {
    asm volatile("cp.async.wait_group 0;" ::: "memory");
}
__device__ __forceinline__ void cp_wait1() {
    asm volatile("cp.async.wait_group 1;" ::: "memory");
}

// ---------------- fp32 -> bf16 conversion (ILP-4) ------------------------------
__global__ void cvt_bf16(const float4* __restrict__ s, uint2* __restrict__ d, int n4) {
    int base = blockIdx.x * (blockDim.x * 4) + threadIdx.x;
    float4 v[4];
    bool ok[4];
    #pragma unroll
    for (int u = 0; u < 4; u++) {
        int i = base + u * 256;
        ok[u] = (i < n4);
        if (ok[u]) v[u] = s[i];
    }
    #pragma unroll
    for (int u = 0; u < 4; u++) {
        if (ok[u]) {
            uint2 o;
            o.x = packbf(v[u].y, v[u].x);
            o.y = packbf(v[u].w, v[u].z);
            d[base + u * 256] = o;
        }
    }
}

// convert expert weights only if routed (g_need flag), ILP-4
__global__ void cvt_w(const float4* __restrict__ s, uint2* __restrict__ d,
                      int n4, int perExp4) {
    int base = blockIdx.x * (blockDim.x * 4) + threadIdx.x;
    float4 v[4];
    bool ok[4];
    #pragma unroll
    for (int u = 0; u < 4; u++) {
        int i = base + u * 256;
        ok[u] = (i < n4) && g_need[i / perExp4];
        if (ok[u]) v[u] = s[i];
    }
    #pragma unroll
    for (int u = 0; u < 4; u++) {
        if (ok[u]) {
            uint2 o;
            o.x = packbf(v[u].y, v[u].x);
            o.y = packbf(v[u].w, v[u].z);
            d[base + u * 256] = o;
        }
    }
}

// Wgu: convert + interleave columns (dst col 2i = gate_i, 2i+1 = up_i), ILP-2
__global__ void cvt_wgu(const float* __restrict__ W, bf16* __restrict__ dst, int total) {
    const int perE = DM * (INTER / 4);
    int base = blockIdx.x * (blockDim.x * 2) + threadIdx.x;
    float4 gv[2], uv[2];
    bool ok[2];
    int kk[2], nqq[2], ee[2];
    #pragma unroll
    for (int u = 0; u < 2; u++) {
        int i = base + u * 256;
        ok[u] = false;
        if (i < total) {
            int e = i / perE;
            if (g_need[e]) {
                int rem = i % perE;
                kk[u] = rem / (INTER / 4);
                nqq[u] = rem % (INTER / 4);
                ee[u] = e;
                const float* row = W + ((size_t)e * DM + kk[u]) * (2 * INTER);
                gv[u] = *(const float4*)(row + nqq[u] * 4);
                uv[u] = *(const float4*)(row + INTER + nqq[u] * 4);
                ok[u] = true;
            }
        }
    }
    #pragma unroll
    for (int u = 0; u < 2; u++) {
        if (ok[u]) {
            uint4 o;
            o.x = packbf(uv[u].x, gv[u].x);
            o.y = packbf(uv[u].y, gv[u].y);
            o.z = packbf(uv[u].z, gv[u].z);
            o.w = packbf(uv[u].w, gv[u].w);
            *(uint4*)(dst + ((size_t)ee[u] * DM + kk[u]) * (2 * INTER) + nqq[u] * 8) = o;
        }
    }
}

// ---------------- routing ----------------------------------------------------
__global__ void mean1_kernel(const float* __restrict__ hidden) {
    int b = blockIdx.x, c = blockIdx.y;
    int tid = threadIdx.x;
    float acc[4] = {0.f, 0.f, 0.f, 0.f};
    for (int s = c * 64; s < c * 64 + 64; s++) {
        const float* row = hidden + ((size_t)b * SEQ + s) * DM;
        #pragma unroll
        for (int i = 0; i < 4; i++) acc[i] += row[tid + i * 256];
    }
    #pragma unroll
    for (int i = 0; i < 4; i++)
        g_partial[((size_t)b * 16 + c) * DM + tid + i * 256] = acc[i];
}

__global__ void mean2_kernel() {
    int b = blockIdx.x;
    int tid = threadIdx.x;
    #pragma unroll
    for (int i = 0; i < 4; i++) {
        int d = tid + i * 256;
        float s = 0.f;
        for (int c = 0; c < 16; c++) s += g_partial[((size_t)b * 16 + c) * DM + d];
        g_hsmean[b * DM + d] = s * (1.0f / (float)SEQ);
    }
}

__global__ void routing_kernel(const float* __restrict__ Wr,
                               const float* __restrict__ temperature,
                               float* __restrict__ out_logits) {
    int tid = threadIdx.x;          // 1024
    int w = tid >> 5, lane = tid & 31;
    int b = w >> 3, c = w & 7;
    float s = 0.f;
    for (int d = lane; d < DM; d += 32)
        s += g_hsmean[b * DM + d] * Wr[c * DM + d];
    #pragma unroll
    for (int o = 16; o; o >>= 1) s += __shfl_down_sync(0xFFFFFFFFu, s, o);
    __shared__ float logits[32];
    if (lane == 0) logits[w] = s;
    if (tid < 8) g_need[tid] = 0;
    __syncthreads();
    if (tid < BATCH) {
        float t = fminf(fmaxf(temperature[0], 0.1f), 10.0f);
        float lv[8];
        #pragma unroll
        for (int cc = 0; cc < 8; cc++) {
            lv[cc] = logits[tid * 8 + cc] / t;
            out_logits[tid * 8 + cc] = lv[cc];
        }
        int i0 = 0;
        #pragma unroll
        for (int cc = 1; cc < 8; cc++) if (lv[cc] > lv[i0]) i0 = cc;
        int i1 = -1;
        #pragma unroll
        for (int cc = 0; cc < 8; cc++) {
            if (cc == i0) continue;
            if (i1 < 0 || lv[cc] > lv[i1]) i1 = cc;
        }
        float e = expf(lv[i1] - lv[i0]);
        g_expert[2 * tid]     = i0;
        g_expert[2 * tid + 1] = i1;
        g_w[2 * tid]     = 1.0f / (1.0f + e);
        g_w[2 * tid + 1] = e / (1.0f + e);
        g_need[i0] = 1;
        g_need[i1] = 1;
    }
}

// ---------------- bf16 tensor-core GEMM ----------------------------------------
// BM=BN=128, BK=64, 3-stage cp.async, 2 CTA/SM. B frags via ldsm.x4.trans pairs.
// MODE 1: bf16 out + fused RoPE. MODE 2: fused silu(gate)*up. MODE 3: fp32+residual.
#define ASTG 144
#define BSTG 272
#define ABYTES (128 * ASTG)
#define BBYTES (64 * BSTG)
#define STGB (ABYTES + BBYTES)
#define GEMM_SMEM (3 * STGB)

template<int MODE>
__global__ __launch_bounds__(256, 2) void gemm_bf(
    const bf16* __restrict__ Ab, const bf16* __restrict__ Bb, void* __restrict__ Cb,
    int N, int K, int lda, long long strideA, int a_div2, long long strideC,
    const float* __restrict__ Res, int r_div2, int useScale,
    const float* __restrict__ cosp, const float* __restrict__ sinp)
{
    constexpr int MI = (MODE == 1) ? 2 : 4;
    constexpr int NJ = (MODE == 1) ? 8 : 4;

    extern __shared__ char smraw[];
    uint32_t sb = (uint32_t)__cvta_generic_to_shared(smraw);
    int z = blockIdx.z;
    const bf16* A = Ab + (size_t)(a_div2 ? (z >> 1) : z) * strideA;
    const bf16* B = Bb + (long long)g_expert[z] * ((long long)K * N);
    int m0 = blockIdx.y * 128;
    int n0 = blockIdx.x * 128;
    int tid = threadIdx.x, lane = tid & 31, wid = tid >> 5;
    int wm0, wn0;
    if (MODE == 1) { wm0 = (wid & 3) * 32; wn0 = (wid >> 2) * 64; }
    else           { wm0 = (wid & 1) * 64; wn0 = (wid >> 1) * 32; }
    int g = lane >> 2, t = lane & 3;

    auto load_tile = [&](int k0, int buf) {
        uint32_t base = sb + (uint32_t)(buf * STGB);
        #pragma unroll
        for (int p = 0; p < 4; p++) {
            int i = tid + p * 256;
            int row = i >> 3, ch = i & 7;
            cp16(base + (uint32_t)(row * ASTG + ch * 16),
                 A + (size_t)(m0 + row) * lda + k0 + ch * 8);
        }
        #pragma unroll
        for (int p = 0; p < 4; p++) {
            int i = tid + p * 256;
            int row = i >> 4, ch = i & 15;
            cp16(base + (uint32_t)(ABYTES + row * BSTG + ch * 16),
                 B + (size_t)(k0 + row) * N + n0 + ch * 8);
        }
    };

    int NT = K / 64;
    load_tile(0, 0);
    cp_commit();
    load_tile(64, 1);
    cp_commit();

    float acc[MI][NJ][4];
    #pragma unroll
    for (int i = 0; i < MI; i++)
        #pragma unroll
        for (int j = 0; j < NJ; j++)
            #pragma unroll
            for (int q = 0; q < 4; q++) acc[i][j][q] = 0.f;

    uint32_t af[2][MI][4];
    uint32_t bfr[2][NJ][2];

    // B ldsm.x4.trans lane addressing: lanes 0-15 -> n-tile j, 16-31 -> n-tile j+1
    uint32_t bLane = (uint32_t)((lane & 15) * BSTG + (lane >> 4) * 16 + wn0 * 2);

    int buf = 0;
    for (int tI = 0; tI < NT; ++tI) {
        if (tI + 1 < NT) cp_wait1(); else cp_wait0();
        __syncthreads();
        if (tI + 2 < NT) {
            int nb = buf + 2; if (nb >= 3) nb -= 3;
            load_tile((tI + 2) * 64, nb);
            cp_commit();
        }
        uint32_t stage = sb + (uint32_t)(buf * STGB);
        uint32_t aB = stage + (uint32_t)((wm0 + (lane & 15)) * ASTG + (lane >> 4) * 16);
        uint32_t bB = stage + (uint32_t)ABYTES + bLane;

        #pragma unroll
        for (int i = 0; i < MI; i++) ldsm_x4(af[0][i], aB + (uint32_t)(i * 16 * ASTG));
        #pragma unroll
        for (int j = 0; j < NJ; j += 2)
            ldsm_x4t(&bfr[0][j][0], bB + (uint32_t)(j * 16));

        #pragma unroll
        for (int ks = 0; ks < 4; ks++) {
            int cb = ks & 1, nb2 = cb ^ 1;
            if (ks < 3) {
                #pragma unroll
                for (int i = 0; i < MI; i++)
                    ldsm_x4(af[nb2][i], aB + (uint32_t)(i * 16 * ASTG + (ks + 1) * 32));
                #pragma unroll
                for (int j = 0; j < NJ; j += 2)
                    ldsm_x4t(&bfr[nb2][j][0], bB + (uint32_t)((ks + 1) * 16 * BSTG + j * 16));
            }
            #pragma unroll
            for (int i = 0; i < MI; i++)
                #pragma unroll
                for (int j = 0; j < NJ; j++)
                    mma_bf16(acc[i][j], af[cb][i], bfr[cb][j]);
        }
        buf++; if (buf == 3) buf = 0;
    }

    if (MODE == 1) {
        bf16* C = (bf16*)Cb + (size_t)z * strideC;
        bool isv = (n0 + wn0) >= 2 * DM;   // v columns: no rope
        #pragma unroll
        for (int i = 0; i < MI; i++) {
            int r = m0 + wm0 + i * 16 + g;
            if (isv) {
                #pragma unroll
                for (int j = 0; j < NJ; j++) {
                    int c = n0 + wn0 + j * 8 + 2 * t;
                    *(uint32_t*)(C + (size_t)r * N + c) = packbf(acc[i][j][1], acc[i][j][0]);
                    *(uint32_t*)(C + (size_t)(r + 8) * N + c) = packbf(acc[i][j][3], acc[i][j][2]);
                }
            } else {
                #pragma unroll
                for (int j = 0; j < 4; j++) {
                    int hc = j * 8 + 2 * t;            // [0,32)
                    int c = n0 + wn0 + hc;
                    float2 cl0 = *(const float2*)(cosp + r * HDIM + hc);
                    float2 sl0 = *(const float2*)(sinp + r * HDIM + hc);
                    float2 ch0 = *(const float2*)(cosp + r * HDIM + hc + 32);
                    float2 sh0 = *(const float2*)(sinp + r * HDIM + hc + 32);
                    float2 cl1 = *(const float2*)(cosp + (r + 8) * HDIM + hc);
                    float2 sl1 = *(const float2*)(sinp + (r + 8) * HDIM + hc);
                    float2 ch1 = *(const float2*)(cosp + (r + 8) * HDIM + hc + 32);
                    float2 sh1 = *(const float2*)(sinp + (r + 8) * HDIM + hc + 32);
                    float alo0 = acc[i][j][0], alo1 = acc[i][j][1];
                    float ahi0 = acc[i][j + 4][0], ahi1 = acc[i][j + 4][1];
                    float blo0 = acc[i][j][2], blo1 = acc[i][j][3];
                    float bhi0 = acc[i][j + 4][2], bhi1 = acc[i][j + 4][3];
                    *(uint32_t*)(C + (size_t)r * N + c) =
                        packbf(alo1 * cl0.y - ahi1 * sl0.y, alo0 * cl0.x - ahi0 * sl0.x);
                    *(uint32_t*)(C + (size_t)r * N + c + 32) =
                        packbf(ahi1 * ch0.y + alo1 * sh0.y, ahi0 * ch0.x + alo0 * sh0.x);
                    *(uint32_t*)(C + (size_t)(r + 8) * N + c) =
                        packbf(blo1 * cl1.y - bhi1 * sl1.y, blo0 * cl1.x - bhi0 * sl1.x);
                    *(uint32_t*)(C + (size_t)(r + 8) * N + c + 32) =
                        packbf(bhi1 * ch1.y + blo1 * sh1.y, bhi0 * ch1.x + blo0 * sh1.x);
                }
            }
        }
    } else {
        #pragma unroll
        for (int i = 0; i < MI; i++) {
            int r = m0 + wm0 + i * 16 + g;
            float sc0 = 1.0f, sc1 = 1.0f;
            if (MODE == 3 && useScale) {
                sc0 = g_scale[z * SEQ + r];
                sc1 = g_scale[z * SEQ + r + 8];
            }
            #pragma unroll
            for (int j = 0; j < NJ; j++) {
                int c = n0 + wn0 + j * 8 + 2 * t;
                if (MODE == 2) {
                    bf16* C = (bf16*)Cb + (size_t)z * strideC;
                    int oc = c >> 1;
                    float g0 = acc[i][j][0], u0 = acc[i][j][1];
                    float g1 = acc[i][j][2], u1 = acc[i][j][3];
                    float s0 = g0 / (1.0f + __expf(-g0)) * u0;
                    float s1 = g1 / (1.0f + __expf(-g1)) * u1;
                    C[(size_t)r * (N / 2) + oc]       = __float2bfloat16(s0);
                    C[(size_t)(r + 8) * (N / 2) + oc] = __float2bfloat16(s1);
                } else {  // MODE 3
                    float* C = (float*)Cb + (size_t)z * strideC;
                    const float* R = Res + (size_t)(r_div2 ? (z >> 1) : z) * strideC;
                    float2 r0 = *(const float2*)(R + (size_t)r * N + c);
                    float2 r1 = *(const float2*)(R + (size_t)(r + 8) * N + c);
                    *(float2*)(C + (size_t)r * N + c) =
                        make_float2(acc[i][j][0] + r0.x * sc0, acc[i][j][1] + r0.y * sc0);
                    *(float2*)(C + (size_t)(r + 8) * N + c) =
                        make_float2(acc[i][j][2] + r1.x * sc1, acc[i][j][3] + r1.y * sc1);
                }
            }
        }
    }
}

// ---------------- flash attention (bf16 mma, Q tile 64, 128 thr) ----------------
// QK^T B-frags via ldsm.x4 (2 n-tiles each); P@V V-frags via ldsm.x4.trans
// (2 n-column groups each). All values bit-identical to scalar/x2 variants.
#define FQ 0
#define FK 9216
#define FV (9216 * 3)
#define FLASH_SMEM (9216 * 5)

__global__ __launch_bounds__(128) void flash_kernel() {
    extern __shared__ char smraw[];
    uint32_t sb = (uint32_t)__cvta_generic_to_shared(smraw);

    int nh = blockIdx.y;
    int n = nh >> 4, h = nh & 15;
    int q0 = blockIdx.x * 64;
    const bf16* qbase = g_qkvb + (size_t)n * SEQ * (3 * DM) + h * HDIM;
    const bf16* kbase = qbase + DM;
    const bf16* vbase = qbase + 2 * DM;

    int tid = threadIdx.x, lane = tid & 31, wid = tid >> 5;
    int g = lane >> 2, t = lane & 3;
    int wm0 = wid * 16;

    // per-lane ldsm address components
    int rowL = (lane & 7) + ((lane >> 4) << 3);
    int colL = ((lane >> 3) & 1) * 16;
    uint32_t kLane = (uint32_t)(rowL * 144 + colL);                  // QK^T (x4)
    uint32_t vLane = (uint32_t)((lane & 15) * 144 + (lane >> 4) * 16); // P@V (x4t)

    #pragma unroll
    for (int p = 0; p < 4; p++) {
        int i = tid + p * 128;
        int row = i >> 3, ch = i & 7;
        cp16(sb + (uint32_t)(FQ + row * 144 + ch * 16),
             qbase + (size_t)(q0 + row) * (3 * DM) + ch * 8);
        cp16(sb + (uint32_t)(FK + row * 144 + ch * 16),
             kbase + (size_t)row * (3 * DM) + ch * 8);
        cp16(sb + (uint32_t)(FV + row * 144 + ch * 16),
             vbase + (size_t)row * (3 * DM) + ch * 8);
    }
    cp_commit();
    cp_wait0();
    __syncthreads();

    uint32_t qf[4][4];
    uint32_t qA = sb + (uint32_t)(FQ + (wm0 + (lane & 15)) * 144 + (lane >> 4) * 16);
    #pragma unroll
    for (int kc = 0; kc < 4; kc++) ldsm_x4(qf[kc], qA + (uint32_t)(kc * 32));

    float m0 = -INFINITY, m1 = -INFINITY, l0 = 0.f, l1 = 0.f;
    float oa[8][4];
    #pragma unroll
    for (int j = 0; j < 8; j++)
        #pragma unroll
        for (int q = 0; q < 4; q++) oa[j][q] = 0.f;

    const int NT = SEQ / 64;
    for (int it = 0; it < NT; it++) {
        int buf = it & 1;
        if (it + 1 < NT) {
            int kv = (it + 1) * 64;
            int ob = buf ^ 1;
            #pragma unroll
            for (int p = 0; p < 4; p++) {
                int i = tid + p * 128;
                int row = i >> 3, ch = i & 7;
                cp16(sb + (uint32_t)(FK + ob * 9216 + row * 144 + ch * 16),
                     kbase + (size_t)(kv + row) * (3 * DM) + ch * 8);
                cp16(sb + (uint32_t)(FV + ob * 9216 + row * 144 + ch * 16),
                     vbase + (size_t)(kv + row) * (3 * DM) + ch * 8);
            }
            cp_commit();
        }
        uint32_t kB = sb + (uint32_t)(FK + buf * 9216) + kLane;
        uint32_t vB = sb + (uint32_t)(FV + buf * 9216) + vLane;

        float sacc[8][4];
        #pragma unroll
        for (int j = 0; j < 8; j++)
            #pragma unroll
            for (int q = 0; q < 4; q++) sacc[j][q] = 0.f;

        #pragma unroll
        for (int kc = 0; kc < 4; kc++) {
            #pragma unroll
            for (int ntp = 0; ntp < 4; ntp++) {
                uint32_t bb[4];
                ldsm_x4(bb, kB + (uint32_t)(ntp * 16 * 144 + kc * 32));
                mma_bf16(sacc[2 * ntp],     qf[kc], bb);
                mma_bf16(sacc[2 * ntp + 1], qf[kc], bb + 2);
            }
        }

        float rm0 = -INFINITY, rm1 = -INFINITY;
        #pragma unroll
        for (int nt = 0; nt < 8; nt++) {
            #pragma unroll
            for (int q = 0; q < 4; q++) sacc[nt][q] *= 0.125f;
            rm0 = fmaxf(rm0, fmaxf(sacc[nt][0], sacc[nt][1]));
            rm1 = fmaxf(rm1, fmaxf(sacc[nt][2], sacc[nt][3]));
        }
        rm0 = fmaxf(rm0, __shfl_xor_sync(0xFFFFFFFFu, rm0, 1));
        rm0 = fmaxf(rm0, __shfl_xor_sync(0xFFFFFFFFu, rm0, 2));
        rm1 = fmaxf(rm1, __shfl_xor_sync(0xFFFFFFFFu, rm1, 1));
        rm1 = fmaxf(rm1, __shfl_xor_sync(0xFFFFFFFFu, rm1, 2));
        float mn0 = fmaxf(m0, rm0), mn1 = fmaxf(m1, rm1);
        float c0 = __expf(m0 - mn0), c1 = __expf(m1 - mn1);
        float ls0 = 0.f, ls1 = 0.f;
        #pragma unroll
        for (int nt = 0; nt < 8; nt++) {
            sacc[nt][0] = __expf(sacc[nt][0] - mn0);
            sacc[nt][1] = __expf(sacc[nt][1] - mn0);
            sacc[nt][2] = __expf(sacc[nt][2] - mn1);
            sacc[nt][3] = __expf(sacc[nt][3] - mn1);
            ls0 += sacc[nt][0] + sacc[nt][1];
            ls1 += sacc[nt][2] + sacc[nt][3];
        }
        ls0 += __shfl_xor_sync(0xFFFFFFFFu, ls0, 1);
        ls0 += __shfl_xor_sync(0xFFFFFFFFu, ls0, 2);
        ls1 += __shfl_xor_sync(0xFFFFFFFFu, ls1, 1);
        ls1 += __shfl_xor_sync(0xFFFFFFFFu, ls1, 2);
        l0 = l0 * c0 + ls0;
        l1 = l1 * c1 + ls1;
        m0 = mn0; m1 = mn1;
        #pragma unroll
        for (int j = 0; j < 8; j++) {
            oa[j][0] *= c0; oa[j][1] *= c0;
            oa[j][2] *= c1; oa[j][3] *= c1;
        }

        #pragma unroll
        for (int mC = 0; mC < 4; mC++) {
            uint32_t pa[4];
            pa[0] = packbf(sacc[2 * mC][1],     sacc[2 * mC][0]);
            pa[1] = packbf(sacc[2 * mC][3],     sacc[2 * mC][2]);
            pa[2] = packbf(sacc[2 * mC + 1][1], sacc[2 * mC + 1][0]);
            pa[3] = packbf(sacc[2 * mC + 1][3], sacc[2 * mC + 1][2]);
            #pragma unroll
            for (int jn = 0; jn < 8; jn += 2) {
                uint32_t vb4[4];
                ldsm_x4t(vb4, vB + (uint32_t)(mC * 16 * 144 + jn * 16));
                mma_bf16(oa[jn],     pa, vb4);
                mma_bf16(oa[jn + 1], pa, vb4 + 2);
            }
        }

        cp_wait0();
        __syncthreads();
    }

    float inv0 = 1.0f / l0, inv1 = 1.0f / l1;
    int grow0 = q0 + wm0 + g;
    bf16* cbase = g_ctxb + (size_t)n * SEQ * DM + h * HDIM;
    #pragma unroll
    for (int jn = 0; jn < 8; jn++) {
        int col = jn * 8 + 2 * t;
        *(uint32_t*)(cbase + (size_t)grow0 * DM + col) =
            packbf(oa[jn][1] * inv0, oa[jn][0] * inv0);
        *(uint32_t*)(cbase + (size_t)(grow0 + 8) * DM + col) =
            packbf(oa[jn][3] * inv1, oa[jn][2] * inv1);
    }
}

// ---------------- rmsnorm of (x+ao): writes x1b (bf16) + per-row scale ----------
__global__ void resid_rms_kernel() {
    __shared__ float sh[32];
    int ns = blockIdx.x;
    int tid = threadIdx.x;           // 256
    int d0 = tid * 4;
    size_t base = (size_t)ns * DM;
    float4 y = *(const float4*)(g_ao + base + d0);
    float ss = y.x * y.x + y.y * y.y + y.z * y.z + y.w * y.w;
    ss = block_reduce_sum(ss, sh);
    float scale = rsqrtf(ss * (1.0f / (float)DM) + EPS);
    if (tid == 0) g_scale[ns] = scale;
    y.x *= scale; y.y *= scale; y.z *= scale; y.w *= scale;
    uint2 o;
    o.x = packbf(y.y, y.x);
    o.y = packbf(y.w, y.z);
    *(uint2*)(g_x1b + base + d0) = o;
}

// ---------------- final: rmsnorm(x1+mlp) (sum done in Wd epilogue) --------------
__global__ void final_kernel(float* __restrict__ out) {
    __shared__ float sh[32];
    int bs = blockIdx.x;
    int b = bs >> 10, s = bs & 1023;
    int tid = threadIdx.x;
    int n0 = 2 * b, n1 = 2 * b + 1;
    size_t base0 = ((size_t)n0 * SEQ + s) * DM;
    size_t base1 = ((size_t)n1 * SEQ + s) * DM;
    float y0[4], y1[4];
    float ss0 = 0.f, ss1 = 0.f;
    #pragma unroll
    for (int i = 0; i < 4; i++) {
        int d = tid + i * 256;
        y0[i] = g_mlp[base0 + d];
        y1[i] = g_mlp[base1 + d];
        ss0 = fmaf(y0[i], y0[i], ss0);
        ss1 = fmaf(y1[i], y1[i], ss1);
    }
    ss0 = block_reduce_sum(ss0, sh);
    ss1 = block_reduce_sum(ss1, sh);
    float r0 = rsqrtf(ss0 * (1.0f / (float)DM) + EPS) * g_w[n0];
    float r1 = rsqrtf(ss1 * (1.0f / (float)DM) + EPS) * g_w[n1];
    float* orow = out + ((size_t)b * SEQ + s) * DM;
    #pragma unroll
    for (int i = 0; i < 4; i++) {
        int d = tid + i * 256;
        orow[d] = y0[i] * r0 + y1[i] * r1;
    }
}

// ---------------- host launcher --------------------------------------------------
extern "C" void kernel_launch(void* const* d_in, const int* in_sizes, int n_in,
                              void* d_out, int out_size) {
    const float* hidden = (const float*)d_in[0];
    const float* cosb   = (const float*)d_in[1];
    const float* sinb   = (const float*)d_in[2];
    const float* Wr     = (const float*)d_in[3];
    const float* temp   = (const float*)d_in[4];
    const float* Wqkv   = (const float*)d_in[5];
    const float* Wo     = (const float*)d_in[6];
    const float* Wgu    = (const float*)d_in[7];
    const float* Wd     = (const float*)d_in[8];
    float* out = (float*)d_out;

    bf16 *p_hb, *p_qkvb, *p_ctxb, *p_x1b, *p_actb, *p_wb;
    float *p_ao, *p_mlp;
    cudaGetSymbolAddress((void**)&p_hb,   g_hb);
    cudaGetSymbolAddress((void**)&p_qkvb, g_qkvb);
    cudaGetSymbolAddress((void**)&p_ctxb, g_ctxb);
    cudaGetSymbolAddress((void**)&p_x1b,  g_x1b);
    cudaGetSymbolAddress((void**)&p_actb, g_actb);
    cudaGetSymbolAddress((void**)&p_wb,   g_wb);
    cudaGetSymbolAddress((void**)&p_ao,   g_ao);
    cudaGetSymbolAddress((void**)&p_mlp,  g_mlp);

    cudaFuncSetAttribute(flash_kernel,
                         cudaFuncAttributeMaxDynamicSharedMemorySize, FLASH_SMEM);
    cudaFuncSetAttribute((const void*)gemm_bf<1>,
                         cudaFuncAttributeMaxDynamicSharedMemorySize, GEMM_SMEM);
    cudaFuncSetAttribute((const void*)gemm_bf<2>,
                         cudaFuncAttributeMaxDynamicSharedMemorySize, GEMM_SMEM);
    cudaFuncSetAttribute((const void*)gemm_bf<3>,
                         cudaFuncAttributeMaxDynamicSharedMemorySize, GEMM_SMEM);

    // routing first (sets g_need for routed-only weight conversion)
    mean1_kernel<<<dim3(BATCH, 16), 256>>>(hidden);
    mean2_kernel<<<BATCH, 256>>>();
    routing_kernel<<<1, 1024>>>(Wr, temp, out + (size_t)BATCH * SEQ * DM);

    // bf16 conversions (ILP-4)
    {
        int n4 = BATCH * SEQ * DM / 4;
        cvt_bf16<<<(n4 + 1023) / 1024, 256>>>((const float4*)hidden, (uint2*)p_hb, n4);
        n4 = 8 * DM * 3 * DM / 4;
        cvt_w<<<(n4 + 1023) / 1024, 256>>>((const float4*)Wqkv, (uint2*)(p_wb + WB_QKV),
                                           n4, DM * 3 * DM / 4);
        n4 = 8 * DM * DM / 4;
        cvt_w<<<(n4 + 1023) / 1024, 256>>>((const float4*)Wo, (uint2*)(p_wb + WB_WO),
                                           n4, DM * DM / 4);
        int tg = 8 * DM * (INTER / 4);
        cvt_wgu<<<(tg + 511) / 512, 256>>>(Wgu, p_wb + WB_GU, tg);
        n4 = 8 * INTER * DM / 4;
        cvt_w<<<(n4 + 1023) / 1024, 256>>>((const float4*)Wd, (uint2*)(p_wb + WB_WD),
                                           n4, INTER * DM / 4);
    }

    // qkv = x @ Wqkv[e]   (bf16 out, RoPE fused on q,k)
    gemm_bf<1><<<dim3(3072 / 128, SEQ / 128, NSAMP), 256, GEMM_SMEM>>>(
        p_hb, p_wb + WB_QKV, p_qkvb, 3 * DM, DM, DM,
        (long long)SEQ * DM, 1, (long long)SEQ * 3 * DM, nullptr, 0, 0, cosb, sinb);

    // fused attention -> g_ctxb (bf16), Q tile 64
    flash_kernel<<<dim3(SEQ / 64, NSAMP * HN), 128, FLASH_SMEM>>>();

    // g_ao = hidden + ctx @ Wo[e]   (fp32 out + residual)
    gemm_bf<3><<<dim3(DM / 128, SEQ / 128, NSAMP), 256, GEMM_SMEM>>>(
        p_ctxb, p_wb + WB_WO, p_ao, DM, DM, DM,
        (long long)SEQ * DM, 0, (long long)SEQ * DM, hidden, 1, 0, nullptr, nullptr);

    // x1b + g_scale = rmsnorm(g_ao)
    resid_rms_kernel<<<NSAMP * SEQ, 256>>>();

    // act = silu(gate)*up fused into Wgu GEMM (interleaved weights)
    gemm_bf<2><<<dim3(2 * INTER / 128, SEQ / 128, NSAMP), 256, GEMM_SMEM>>>(
        p_x1b, p_wb + WB_GU, p_actb, 2 * INTER, DM, DM,
        (long long)SEQ * DM, 0, (long long)SEQ * INTER, nullptr, 0, 0, nullptr, nullptr);

    // g_mlp = x1 + act @ Wd[e]   (fp32 out + residual = g_ao * g_scale)
    gemm_bf<3><<<dim3(DM / 128, SEQ / 128, NSAMP), 256, GEMM_SMEM>>>(
        p_actb, p_wb + WB_WD, p_mlp, DM, INTER, INTER,
        (long long)SEQ * INTER, 0, (long long)SEQ * DM, p_ao, 0, 1, nullptr, nullptr);

    // out = sum of weighted rmsnorm(g_mlp)
    final_kernel<<<BATCH * SEQ, 256>>>(out);
}

// round 16
// speedup vs baseline: 1.0605x; 1.0158x over previous
#include <cuda_runtime.h>
#include <cuda_bf16.h>
#include <math.h>
#include <stdint.h>

#define SEQ   1024
#define DM    1024
#define HN    16
#define HDIM  64
#define NSAMP 8
#define INTER 768
#define BATCH 4
#define EPS   1e-5f

typedef __nv_bfloat16 bf16;

// ---------------- scratch (device globals; no allocations allowed) ----------
__device__ float g_hsmean[BATCH * DM];
__device__ float g_partial[BATCH * 16 * DM];
__device__ int   g_expert[NSAMP];
__device__ int   g_need[8];
__device__ float g_w[NSAMP];
__device__ float g_scale[NSAMP * SEQ];
__device__ bf16  g_hb[(size_t)BATCH * SEQ * DM];
__device__ bf16  g_qkvb[(size_t)NSAMP * SEQ * 3 * DM];       // 48 MB (rope+qscale fused)
__device__ bf16  g_ctxb[(size_t)NSAMP * SEQ * DM];           // 16 MB
__device__ float g_ao[(size_t)NSAMP * SEQ * DM];             // 32 MB (holds x+ao)
__device__ bf16  g_x1b[(size_t)NSAMP * SEQ * DM];            // 16 MB
__device__ bf16  g_actb[(size_t)NSAMP * SEQ * INTER];        // 12 MB
__device__ float g_mlp[(size_t)NSAMP * SEQ * DM];            // 32 MB (holds x1+mlp)
// all-expert bf16 weights (gu stored column-interleaved: 2i=gate_i, 2i+1=up_i)
#define WB_QKV 0LL
#define WB_WO  25165824LL
#define WB_GU  33554432LL
#define WB_WD  46137344LL
#define WB_TOTAL 52428800LL
__device__ bf16 g_wb[WB_TOTAL];                              // 105 MB

// ---------------- small helpers ----------------------------------------------
__device__ __forceinline__ float block_reduce_sum(float v, float* sh) {
    int tid = threadIdx.x;
    #pragma unroll
    for (int o = 16; o; o >>= 1) v += __shfl_down_sync(0xFFFFFFFFu, v, o);
    if ((tid & 31) == 0) sh[tid >> 5] = v;
    __syncthreads();
    float r = 0.f;
    if (tid < 32) {
        float x = (tid < (int)(blockDim.x >> 5)) ? sh[tid] : 0.f;
        #pragma unroll
        for (int o = 16; o; o >>= 1) x += __shfl_down_sync(0xFFFFFFFFu, x, o);
        if (tid == 0) sh[0] = x;
    }
    __syncthreads();
    r = sh[0];
    __syncthreads();
    return r;
}

__device__ __forceinline__ void mma_bf16(float* d, const uint32_t* a, const uint32_t* b) {
    asm volatile(
        "mma.sync.aligned.m16n8k16.row.col.f32.bf16.bf16.f32 "
        "{%0,%1,%2,%3},{%4,%5,%6,%7},{%8,%9},{%0,%1,%2,%3};"
        : "+f"(d[0]), "+f"(d[1]), "+f"(d[2]), "+f"(d[3])
        : "r"(a[0]), "r"(a[1]), "r"(a[2]), "r"(a[3]), "r"(b[0]), "r"(b[1]));
}

__device__ __forceinline__ void ldsm_x4(uint32_t* r, uint32_t addr) {
    asm volatile(
        "ldmatrix.sync.aligned.m8n8.x4.shared.b16 {%0,%1,%2,%3}, [%4];"
        : "=r"(r[0]), "=r"(r[1]), "=r"(r[2]), "=r"(r[3]) : "r"(addr));
}
__device__ __forceinline__ void ldsm_x4t(uint32_t* r, uint32_t addr) {
    asm volatile(
        "ldmatrix.sync.aligned.m8n8.x4.trans.shared.b16 {%0,%1,%2,%3}, [%4];"
        : "=r"(r[0]), "=r"(r[1]), "=r"(r[2]), "=r"(r[3]) : "r"(addr));
}
__device__ __forceinline__ uint32_t packbf(float hi, float lo) {
    uint32_t r;
    asm("cvt.rn.bf16x2.f32 %0, %1, %2;" : "=r"(r) : "f"(hi), "f"(lo));
    return r;
}

__device__ __forceinline__ void cp16(uint32_t s, const void* g) {
    asm volatile("cp.async.cg.shared.global [%0], [%1], 16;" :: "r"(s), "l"(g));
}
__device__ __forceinline__ void cp_commit() {
    asm volatile("cp.async.commit_group;" ::: "memory");
}
__device__ __forceinline__ void cp_wait0() {
    asm volatile("cp.async.wait_group 0;" ::: "memory");
}
__device__ __forceinline__ void cp_wait1() {
    asm volatile("cp.async.wait_group 1;" ::: "memory");
}

// ---------------- fp32 -> bf16 conversion (ILP-4) ------------------------------
__global__ void cvt_bf16(const float4* __restrict__ s, uint2* __restrict__ d, int n4) {
    int base = blockIdx.x * (blockDim.x * 4) + threadIdx.x;
    float4 v[4];
    bool ok[4];
    #pragma unroll
    for (int u = 0; u < 4; u++) {
        int i = base + u * 256;
        ok[u] = (i < n4);
        if (ok[u]) v[u] = s[i];
    }
    #pragma unroll
    for (int u = 0; u < 4; u++) {
        if (ok[u]) {
            uint2 o;
            o.x = packbf(v[u].y, v[u].x);
            o.y = packbf(v[u].w, v[u].z);
            d[base + u * 256] = o;
        }
    }
}

// convert expert weights only if routed (g_need flag), ILP-4
__global__ void cvt_w(const float4* __restrict__ s, uint2* __restrict__ d,
                      int n4, int perExp4) {
    int base = blockIdx.x * (blockDim.x * 4) + threadIdx.x;
    float4 v[4];
    bool ok[4];
    #pragma unroll
    for (int u = 0; u < 4; u++) {
        int i = base + u * 256;
        ok[u] = (i < n4) && g_need[i / perExp4];
        if (ok[u]) v[u] = s[i];
    }
    #pragma unroll
    for (int u = 0; u < 4; u++) {
        if (ok[u]) {
            uint2 o;
            o.x = packbf(v[u].y, v[u].x);
            o.y = packbf(v[u].w, v[u].z);
            d[base + u * 256] = o;
        }
    }
}

// Wgu: convert + interleave columns (dst col 2i = gate_i, 2i+1 = up_i), ILP-2
__global__ void cvt_wgu(const float* __restrict__ W, bf16* __restrict__ dst, int total) {
    const int perE = DM * (INTER / 4);
    int base = blockIdx.x * (blockDim.x * 2) + threadIdx.x;
    float4 gv[2], uv[2];
    bool ok[2];
    int kk[2], nqq[2], ee[2];
    #pragma unroll
    for (int u = 0; u < 2; u++) {
        int i = base + u * 256;
        ok[u] = false;
        if (i < total) {
            int e = i / perE;
            if (g_need[e]) {
                int rem = i % perE;
                kk[u] = rem / (INTER / 4);
                nqq[u] = rem % (INTER / 4);
                ee[u] = e;
                const float* row = W + ((size_t)e * DM + kk[u]) * (2 * INTER);
                gv[u] = *(const float4*)(row + nqq[u] * 4);
                uv[u] = *(const float4*)(row + INTER + nqq[u] * 4);
                ok[u] = true;
            }
        }
    }
    #pragma unroll
    for (int u = 0; u < 2; u++) {
        if (ok[u]) {
            uint4 o;
            o.x = packbf(uv[u].x, gv[u].x);
            o.y = packbf(uv[u].y, gv[u].y);
            o.z = packbf(uv[u].z, gv[u].z);
            o.w = packbf(uv[u].w, gv[u].w);
            *(uint4*)(dst + ((size_t)ee[u] * DM + kk[u]) * (2 * INTER) + nqq[u] * 8) = o;
        }
    }
}

// ---------------- routing ----------------------------------------------------
__global__ void mean1_kernel(const float* __restrict__ hidden) {
    int b = blockIdx.x, c = blockIdx.y;
    int tid = threadIdx.x;
    float acc[4] = {0.f, 0.f, 0.f, 0.f};
    for (int s = c * 64; s < c * 64 + 64; s++) {
        const float* row = hidden + ((size_t)b * SEQ + s) * DM;
        #pragma unroll
        for (int i = 0; i < 4; i++) acc[i] += row[tid + i * 256];
    }
    #pragma unroll
    for (int i = 0; i < 4; i++)
        g_partial[((size_t)b * 16 + c) * DM + tid + i * 256] = acc[i];
}

__global__ void mean2_kernel() {
    int b = blockIdx.x;
    int tid = threadIdx.x;
    #pragma unroll
    for (int i = 0; i < 4; i++) {
        int d = tid + i * 256;
        float s = 0.f;
        for (int c = 0; c < 16; c++) s += g_partial[((size_t)b * 16 + c) * DM + d];
        g_hsmean[b * DM + d] = s * (1.0f / (float)SEQ);
    }
}

__global__ void routing_kernel(const float* __restrict__ Wr,
                               const float* __restrict__ temperature,
                               float* __restrict__ out_logits) {
    int tid = threadIdx.x;          // 1024
    int w = tid >> 5, lane = tid & 31;
    int b = w >> 3, c = w & 7;
    float s = 0.f;
    for (int d = lane; d < DM; d += 32)
        s += g_hsmean[b * DM + d] * Wr[c * DM + d];
    #pragma unroll
    for (int o = 16; o; o >>= 1) s += __shfl_down_sync(0xFFFFFFFFu, s, o);
    __shared__ float logits[32];
    if (lane == 0) logits[w] = s;
    if (tid < 8) g_need[tid] = 0;
    __syncthreads();
    if (tid < BATCH) {
        float t = fminf(fmaxf(temperature[0], 0.1f), 10.0f);
        float lv[8];
        #pragma unroll
        for (int cc = 0; cc < 8; cc++) {
            lv[cc] = logits[tid * 8 + cc] / t;
            out_logits[tid * 8 + cc] = lv[cc];
        }
        int i0 = 0;
        #pragma unroll
        for (int cc = 1; cc < 8; cc++) if (lv[cc] > lv[i0]) i0 = cc;
        int i1 = -1;
        #pragma unroll
        for (int cc = 0; cc < 8; cc++) {
            if (cc == i0) continue;
            if (i1 < 0 || lv[cc] > lv[i1]) i1 = cc;
        }
        float e = expf(lv[i1] - lv[i0]);
        g_expert[2 * tid]     = i0;
        g_expert[2 * tid + 1] = i1;
        g_w[2 * tid]     = 1.0f / (1.0f + e);
        g_w[2 * tid + 1] = e / (1.0f + e);
        g_need[i0] = 1;
        g_need[i1] = 1;
    }
}

// ---------------- bf16 tensor-core GEMM ----------------------------------------
// BM=BN=128, BK=64, 3-stage cp.async, 2 CTA/SM. B frags via ldsm.x4.trans pairs.
// MODE 1: bf16 out + fused RoPE (q scaled by 1/8 — exact exponent shift).
// MODE 2: fused silu(gate)*up. MODE 3: fp32 out + residual.
#define ASTG 144
#define BSTG 272
#define ABYTES (128 * ASTG)
#define BBYTES (64 * BSTG)
#define STGB (ABYTES + BBYTES)
#define GEMM_SMEM (3 * STGB)

template<int MODE>
__global__ __launch_bounds__(256, 2) void gemm_bf(
    const bf16* __restrict__ Ab, const bf16* __restrict__ Bb, void* __restrict__ Cb,
    int N, int K, int lda, long long strideA, int a_div2, long long strideC,
    const float* __restrict__ Res, int r_div2, int useScale,
    const float* __restrict__ cosp, const float* __restrict__ sinp)
{
    constexpr int MI = (MODE == 1) ? 2 : 4;
    constexpr int NJ = (MODE == 1) ? 8 : 4;

    extern __shared__ char smraw[];
    uint32_t sb = (uint32_t)__cvta_generic_to_shared(smraw);
    int z = blockIdx.z;
    const bf16* A = Ab + (size_t)(a_div2 ? (z >> 1) : z) * strideA;
    const bf16* B = Bb + (long long)g_expert[z] * ((long long)K * N);
    int m0 = blockIdx.y * 128;
    int n0 = blockIdx.x * 128;
    int tid = threadIdx.x, lane = tid & 31, wid = tid >> 5;
    int wm0, wn0;
    if (MODE == 1) { wm0 = (wid & 3) * 32; wn0 = (wid >> 2) * 64; }
    else           { wm0 = (wid & 1) * 64; wn0 = (wid >> 1) * 32; }
    int g = lane >> 2, t = lane & 3;

    auto load_tile = [&](int k0, int buf) {
        uint32_t base = sb + (uint32_t)(buf * STGB);
        #pragma unroll
        for (int p = 0; p < 4; p++) {
            int i = tid + p * 256;
            int row = i >> 3, ch = i & 7;
            cp16(base + (uint32_t)(row * ASTG + ch * 16),
                 A + (size_t)(m0 + row) * lda + k0 + ch * 8);
        }
        #pragma unroll
        for (int p = 0; p < 4; p++) {
            int i = tid + p * 256;
            int row = i >> 4, ch = i & 15;
            cp16(base + (uint32_t)(ABYTES + row * BSTG + ch * 16),
                 B + (size_t)(k0 + row) * N + n0 + ch * 8);
        }
    };

    int NT = K / 64;
    load_tile(0, 0);
    cp_commit();
    load_tile(64, 1);
    cp_commit();

    float acc[MI][NJ][4];
    #pragma unroll
    for (int i = 0; i < MI; i++)
        #pragma unroll
        for (int j = 0; j < NJ; j++)
            #pragma unroll
            for (int q = 0; q < 4; q++) acc[i][j][q] = 0.f;

    uint32_t af[2][MI][4];
    uint32_t bfr[2][NJ][2];

    // B ldsm.x4.trans lane addressing: lanes 0-15 -> n-tile j, 16-31 -> n-tile j+1
    uint32_t bLane = (uint32_t)((lane & 15) * BSTG + (lane >> 4) * 16 + wn0 * 2);

    int buf = 0;
    for (int tI = 0; tI < NT; ++tI) {
        if (tI + 1 < NT) cp_wait1(); else cp_wait0();
        __syncthreads();
        if (tI + 2 < NT) {
            int nb = buf + 2; if (nb >= 3) nb -= 3;
            load_tile((tI + 2) * 64, nb);
            cp_commit();
        }
        uint32_t stage = sb + (uint32_t)(buf * STGB);
        uint32_t aB = stage + (uint32_t)((wm0 + (lane & 15)) * ASTG + (lane >> 4) * 16);
        uint32_t bB = stage + (uint32_t)ABYTES + bLane;

        #pragma unroll
        for (int i = 0; i < MI; i++) ldsm_x4(af[0][i], aB + (uint32_t)(i * 16 * ASTG));
        #pragma unroll
        for (int j = 0; j < NJ; j += 2)
            ldsm_x4t(&bfr[0][j][0], bB + (uint32_t)(j * 16));

        #pragma unroll
        for (int ks = 0; ks < 4; ks++) {
            int cb = ks & 1, nb2 = cb ^ 1;
            if (ks < 3) {
                #pragma unroll
                for (int i = 0; i < MI; i++)
                    ldsm_x4(af[nb2][i], aB + (uint32_t)(i * 16 * ASTG + (ks + 1) * 32));
                #pragma unroll
                for (int j = 0; j < NJ; j += 2)
                    ldsm_x4t(&bfr[nb2][j][0], bB + (uint32_t)((ks + 1) * 16 * BSTG + j * 16));
            }
            #pragma unroll
            for (int i = 0; i < MI; i++)
                #pragma unroll
                for (int j = 0; j < NJ; j++)
                    mma_bf16(acc[i][j], af[cb][i], bfr[cb][j]);
        }
        buf++; if (buf == 3) buf = 0;
    }

    if (MODE == 1) {
        bf16* C = (bf16*)Cb + (size_t)z * strideC;
        bool isv = (n0 + wn0) >= 2 * DM;      // v columns: no rope
        bool isq = (n0 + wn0) < DM;           // q columns: apply 1/8 attn scale
        float qs = isq ? 0.125f : 1.0f;       // power of two: exact in fp32 & bf16
        #pragma unroll
        for (int i = 0; i < MI; i++) {
            int r = m0 + wm0 + i * 16 + g;
            if (isv) {
                #pragma unroll
                for (int j = 0; j < NJ; j++) {
                    int c = n0 + wn0 + j * 8 + 2 * t;
                    *(uint32_t*)(C + (size_t)r * N + c) = packbf(acc[i][j][1], acc[i][j][0]);
                    *(uint32_t*)(C + (size_t)(r + 8) * N + c) = packbf(acc[i][j][3], acc[i][j][2]);
                }
            } else {
                #pragma unroll
                for (int j = 0; j < 4; j++) {
                    int hc = j * 8 + 2 * t;            // [0,32)
                    int c = n0 + wn0 + hc;
                    float2 cl0 = *(const float2*)(cosp + r * HDIM + hc);
                    float2 sl0 = *(const float2*)(sinp + r * HDIM + hc);
                    float2 ch0 = *(const float2*)(cosp + r * HDIM + hc + 32);
                    float2 sh0 = *(const float2*)(sinp + r * HDIM + hc + 32);
                    float2 cl1 = *(const float2*)(cosp + (r + 8) * HDIM + hc);
                    float2 sl1 = *(const float2*)(sinp + (r + 8) * HDIM + hc);
                    float2 ch1 = *(const float2*)(cosp + (r + 8) * HDIM + hc + 32);
                    float2 sh1 = *(const float2*)(sinp + (r + 8) * HDIM + hc + 32);
                    float alo0 = acc[i][j][0], alo1 = acc[i][j][1];
                    float ahi0 = acc[i][j + 4][0], ahi1 = acc[i][j + 4][1];
                    float blo0 = acc[i][j][2], blo1 = acc[i][j][3];
                    float bhi0 = acc[i][j + 4][2], bhi1 = acc[i][j + 4][3];
                    *(uint32_t*)(C + (size_t)r * N + c) =
                        packbf((alo1 * cl0.y - ahi1 * sl0.y) * qs,
                               (alo0 * cl0.x - ahi0 * sl0.x) * qs);
                    *(uint32_t*)(C + (size_t)r * N + c + 32) =
                        packbf((ahi1 * ch0.y + alo1 * sh0.y) * qs,
                               (ahi0 * ch0.x + alo0 * sh0.x) * qs);
                    *(uint32_t*)(C + (size_t)(r + 8) * N + c) =
                        packbf((blo1 * cl1.y - bhi1 * sl1.y) * qs,
                               (blo0 * cl1.x - bhi0 * sl1.x) * qs);
                    *(uint32_t*)(C + (size_t)(r + 8) * N + c + 32) =
                        packbf((bhi1 * ch1.y + blo1 * sh1.y) * qs,
                               (bhi0 * ch1.x + blo0 * sh1.x) * qs);
                }
            }
        }
    } else {
        #pragma unroll
        for (int i = 0; i < MI; i++) {
            int r = m0 + wm0 + i * 16 + g;
            float sc0 = 1.0f, sc1 = 1.0f;
            if (MODE == 3 && useScale) {
                sc0 = g_scale[z * SEQ + r];
                sc1 = g_scale[z * SEQ + r + 8];
            }
            #pragma unroll
            for (int j = 0; j < NJ; j++) {
                int c = n0 + wn0 + j * 8 + 2 * t;
                if (MODE == 2) {
                    bf16* C = (bf16*)Cb + (size_t)z * strideC;
                    int oc = c >> 1;
                    float g0 = acc[i][j][0], u0 = acc[i][j][1];
                    float g1 = acc[i][j][2], u1 = acc[i][j][3];
                    float s0 = g0 / (1.0f + __expf(-g0)) * u0;
                    float s1 = g1 / (1.0f + __expf(-g1)) * u1;
                    C[(size_t)r * (N / 2) + oc]       = __float2bfloat16(s0);
                    C[(size_t)(r + 8) * (N / 2) + oc] = __float2bfloat16(s1);
                } else {  // MODE 3
                    float* C = (float*)Cb + (size_t)z * strideC;
                    const float* R = Res + (size_t)(r_div2 ? (z >> 1) : z) * strideC;
                    float2 r0 = *(const float2*)(R + (size_t)r * N + c);
                    float2 r1 = *(const float2*)(R + (size_t)(r + 8) * N + c);
                    *(float2*)(C + (size_t)r * N + c) =
                        make_float2(acc[i][j][0] + r0.x * sc0, acc[i][j][1] + r0.y * sc0);
                    *(float2*)(C + (size_t)(r + 8) * N + c) =
                        make_float2(acc[i][j][2] + r1.x * sc1, acc[i][j][3] + r1.y * sc1);
                }
            }
        }
    }
}

// ---------------- flash attention (bf16 mma, Q tile 64, 128 thr) ----------------
// Q pre-scaled by 1/8 in QKV epilogue; no scale in the softmax loop.
#define FQ 0
#define FK 9216
#define FV (9216 * 3)
#define FLASH_SMEM (9216 * 5)

__global__ __launch_bounds__(128) void flash_kernel() {
    extern __shared__ char smraw[];
    uint32_t sb = (uint32_t)__cvta_generic_to_shared(smraw);

    int nh = blockIdx.y;
    int n = nh >> 4, h = nh & 15;
    int q0 = blockIdx.x * 64;
    const bf16* qbase = g_qkvb + (size_t)n * SEQ * (3 * DM) + h * HDIM;
    const bf16* kbase = qbase + DM;
    const bf16* vbase = qbase + 2 * DM;

    int tid = threadIdx.x, lane = tid & 31, wid = tid >> 5;
    int g = lane >> 2, t = lane & 3;
    int wm0 = wid * 16;

    // per-lane ldsm address components
    int rowL = (lane & 7) + ((lane >> 4) << 3);
    int colL = ((lane >> 3) & 1) * 16;
    uint32_t kLane = (uint32_t)(rowL * 144 + colL);                    // QK^T (x4)
    uint32_t vLane = (uint32_t)((lane & 15) * 144 + (lane >> 4) * 16); // P@V (x4t)

    #pragma unroll
    for (int p = 0; p < 4; p++) {
        int i = tid + p * 128;
        int row = i >> 3, ch = i & 7;
        cp16(sb + (uint32_t)(FQ + row * 144 + ch * 16),
             qbase + (size_t)(q0 + row) * (3 * DM) + ch * 8);
        cp16(sb + (uint32_t)(FK + row * 144 + ch * 16),
             kbase + (size_t)row * (3 * DM) + ch * 8);
        cp16(sb + (uint32_t)(FV + row * 144 + ch * 16),
             vbase + (size_t)row * (3 * DM) + ch * 8);
    }
    cp_commit();
    cp_wait0();
    __syncthreads();

    uint32_t qf[4][4];
    uint32_t qA = sb + (uint32_t)(FQ + (wm0 + (lane & 15)) * 144 + (lane >> 4) * 16);
    #pragma unroll
    for (int kc = 0; kc < 4; kc++) ldsm_x4(qf[kc], qA + (uint32_t)(kc * 32));

    float m0 = -INFINITY, m1 = -INFINITY, l0 = 0.f, l1 = 0.f;
    float oa[8][4];
    #pragma unroll
    for (int j = 0; j < 8; j++)
        #pragma unroll
        for (int q = 0; q < 4; q++) oa[j][q] = 0.f;

    const int NT = SEQ / 64;
    for (int it = 0; it < NT; it++) {
        int buf = it & 1;
        if (it + 1 < NT) {
            int kv = (it + 1) * 64;
            int ob = buf ^ 1;
            #pragma unroll
            for (int p = 0; p < 4; p++) {
                int i = tid + p * 128;
                int row = i >> 3, ch = i & 7;
                cp16(sb + (uint32_t)(FK + ob * 9216 + row * 144 + ch * 16),
                     kbase + (size_t)(kv + row) * (3 * DM) + ch * 8);
                cp16(sb + (uint32_t)(FV + ob * 9216 + row * 144 + ch * 16),
                     vbase + (size_t)(kv + row) * (3 * DM) + ch * 8);
            }
            cp_commit();
        }
        uint32_t kB = sb + (uint32_t)(FK + buf * 9216) + kLane;
        uint32_t vB = sb + (uint32_t)(FV + buf * 9216) + vLane;

        float sacc[8][4];
        #pragma unroll
        for (int j = 0; j < 8; j++)
            #pragma unroll
            for (int q = 0; q < 4; q++) sacc[j][q] = 0.f;

        #pragma unroll
        for (int kc = 0; kc < 4; kc++) {
            #pragma unroll
            for (int ntp = 0; ntp < 4; ntp++) {
                uint32_t bb[4];
                ldsm_x4(bb, kB + (uint32_t)(ntp * 16 * 144 + kc * 32));
                mma_bf16(sacc[2 * ntp],     qf[kc], bb);
                mma_bf16(sacc[2 * ntp + 1], qf[kc], bb + 2);
            }
        }

        float rm0 = -INFINITY, rm1 = -INFINITY;
        #pragma unroll
        for (int nt = 0; nt < 8; nt++) {
            rm0 = fmaxf(rm0, fmaxf(sacc[nt][0], sacc[nt][1]));
            rm1 = fmaxf(rm1, fmaxf(sacc[nt][2], sacc[nt][3]));
        }
        rm0 = fmaxf(rm0, __shfl_xor_sync(0xFFFFFFFFu, rm0, 1));
        rm0 = fmaxf(rm0, __shfl_xor_sync(0xFFFFFFFFu, rm0, 2));
        rm1 = fmaxf(rm1, __shfl_xor_sync(0xFFFFFFFFu, rm1, 1));
        rm1 = fmaxf(rm1, __shfl_xor_sync(0xFFFFFFFFu, rm1, 2));
        float mn0 = fmaxf(m0, rm0), mn1 = fmaxf(m1, rm1);
        float c0 = __expf(m0 - mn0), c1 = __expf(m1 - mn1);
        float ls0 = 0.f, ls1 = 0.f;
        #pragma unroll
        for (int nt = 0; nt < 8; nt++) {
            sacc[nt][0] = __expf(sacc[nt][0] - mn0);
            sacc[nt][1] = __expf(sacc[nt][1] - mn0);
            sacc[nt][2] = __expf(sacc[nt][2] - mn1);
            sacc[nt][3] = __expf(sacc[nt][3] - mn1);
            ls0 += sacc[nt][0] + sacc[nt][1];
            ls1 += sacc[nt][2] + sacc[nt][3];
        }
        ls0 += __shfl_xor_sync(0xFFFFFFFFu, ls0, 1);
        ls0 += __shfl_xor_sync(0xFFFFFFFFu, ls0, 2);
        ls1 += __shfl_xor_sync(0xFFFFFFFFu, ls1, 1);
        ls1 += __shfl_xor_sync(0xFFFFFFFFu, ls1, 2);
        l0 = l0 * c0 + ls0;
        l1 = l1 * c1 + ls1;
        m0 = mn0; m1 = mn1;
        #pragma unroll
        for (int j = 0; j < 8; j++) {
            oa[j][0] *= c0; oa[j][1] *= c0;
            oa[j][2] *= c1; oa[j][3] *= c1;
        }

        #pragma unroll
        for (int mC = 0; mC < 4; mC++) {
            uint32_t pa[4];
            pa[0] = packbf(sacc[2 * mC][1],     sacc[2 * mC][0]);
            pa[1] = packbf(sacc[2 * mC][3],     sacc[2 * mC][2]);
            pa[2] = packbf(sacc[2 * mC + 1][1], sacc[2 * mC + 1][0]);
            pa[3] = packbf(sacc[2 * mC + 1][3], sacc[2 * mC + 1][2]);
            #pragma unroll
            for (int jn = 0; jn < 8; jn += 2) {
                uint32_t vb4[4];
                ldsm_x4t(vb4, vB + (uint32_t)(mC * 16 * 144 + jn * 16));
                mma_bf16(oa[jn],     pa, vb4);
                mma_bf16(oa[jn + 1], pa, vb4 + 2);
            }
        }

        cp_wait0();
        __syncthreads();
    }

    float inv0 = 1.0f / l0, inv1 = 1.0f / l1;
    int grow0 = q0 + wm0 + g;
    bf16* cbase = g_ctxb + (size_t)n * SEQ * DM + h * HDIM;
    #pragma unroll
    for (int jn = 0; jn < 8; jn++) {
        int col = jn * 8 + 2 * t;
        *(uint32_t*)(cbase + (size_t)grow0 * DM + col) =
            packbf(oa[jn][1] * inv0, oa[jn][0] * inv0);
        *(uint32_t*)(cbase + (size_t)(grow0 + 8) * DM + col) =
            packbf(oa[jn][3] * inv1, oa[jn][2] * inv1);
    }
}

// ---------------- rmsnorm of (x+ao): writes x1b (bf16) + per-row scale ----------
__global__ void resid_rms_kernel() {
    __shared__ float sh[32];
    int ns = blockIdx.x;
    int tid = threadIdx.x;           // 256
    int d0 = tid * 4;
    size_t base = (size_t)ns * DM;
    float4 y = *(const float4*)(g_ao + base + d0);
    float ss = y.x * y.x + y.y * y.y + y.z * y.z + y.w * y.w;
    ss = block_reduce_sum(ss, sh);
    float scale = rsqrtf(ss * (1.0f / (float)DM) + EPS);
    if (tid == 0) g_scale[ns] = scale;
    y.x *= scale; y.y *= scale; y.z *= scale; y.w *= scale;
    uint2 o;
    o.x = packbf(y.y, y.x);
    o.y = packbf(y.w, y.z);
    *(uint2*)(g_x1b + base + d0) = o;
}

// ---------------- final: rmsnorm(x1+mlp) (sum done in Wd epilogue) --------------
__global__ void final_kernel(float* __restrict__ out) {
    __shared__ float sh[32];
    int bs = blockIdx.x;
    int b = bs >> 10, s = bs & 1023;
    int tid = threadIdx.x;
    int n0 = 2 * b, n1 = 2 * b + 1;
    size_t base0 = ((size_t)n0 * SEQ + s) * DM;
    size_t base1 = ((size_t)n1 * SEQ + s) * DM;
    float y0[4], y1[4];
    float ss0 = 0.f, ss1 = 0.f;
    #pragma unroll
    for (int i = 0; i < 4; i++) {
        int d = tid + i * 256;
        y0[i] = g_mlp[base0 + d];
        y1[i] = g_mlp[base1 + d];
        ss0 = fmaf(y0[i], y0[i], ss0);
        ss1 = fmaf(y1[i], y1[i], ss1);
    }
    ss0 = block_reduce_sum(ss0, sh);
    ss1 = block_reduce_sum(ss1, sh);
    float r0 = rsqrtf(ss0 * (1.0f / (float)DM) + EPS) * g_w[n0];
    float r1 = rsqrtf(ss1 * (1.0f / (float)DM) + EPS) * g_w[n1];
    float* orow = out + ((size_t)b * SEQ + s) * DM;
    #pragma unroll
    for (int i = 0; i < 4; i++) {
        int d = tid + i * 256;
        orow[d] = y0[i] * r0 + y1[i] * r1;
    }
}

// ---------------- host launcher --------------------------------------------------
extern "C" void kernel_launch(void* const* d_in, const int* in_sizes, int n_in,
                              void* d_out, int out_size) {
    const float* hidden = (const float*)d_in[0];
    const float* cosb   = (const float*)d_in[1];
    const float* sinb   = (const float*)d_in[2];
    const float* Wr     = (const float*)d_in[3];
    const float* temp   = (const float*)d_in[4];
    const float* Wqkv   = (const float*)d_in[5];
    const float* Wo     = (const float*)d_in[6];
    const float* Wgu    = (const float*)d_in[7];
    const float* Wd     = (const float*)d_in[8];
    float* out = (float*)d_out;

    bf16 *p_hb, *p_qkvb, *p_ctxb, *p_x1b, *p_actb, *p_wb;
    float *p_ao, *p_mlp;
    cudaGetSymbolAddress((void**)&p_hb,   g_hb);
    cudaGetSymbolAddress((void**)&p_qkvb, g_qkvb);
    cudaGetSymbolAddress((void**)&p_ctxb, g_ctxb);
    cudaGetSymbolAddress((void**)&p_x1b,  g_x1b);
    cudaGetSymbolAddress((void**)&p_actb, g_actb);
    cudaGetSymbolAddress((void**)&p_wb,   g_wb);
    cudaGetSymbolAddress((void**)&p_ao,   g_ao);
    cudaGetSymbolAddress((void**)&p_mlp,  g_mlp);

    cudaFuncSetAttribute(flash_kernel,
                         cudaFuncAttributeMaxDynamicSharedMemorySize, FLASH_SMEM);
    cudaFuncSetAttribute((const void*)gemm_bf<1>,
                         cudaFuncAttributeMaxDynamicSharedMemorySize, GEMM_SMEM);
    cudaFuncSetAttribute((const void*)gemm_bf<2>,
                         cudaFuncAttributeMaxDynamicSharedMemorySize, GEMM_SMEM);
    cudaFuncSetAttribute((const void*)gemm_bf<3>,
                         cudaFuncAttributeMaxDynamicSharedMemorySize, GEMM_SMEM);

    // routing first (sets g_need for routed-only weight conversion)
    mean1_kernel<<<dim3(BATCH, 16), 256>>>(hidden);
    mean2_kernel<<<BATCH, 256>>>();
    routing_kernel<<<1, 1024>>>(Wr, temp, out + (size_t)BATCH * SEQ * DM);

    // bf16 conversions (ILP-4)
    {
        int n4 = BATCH * SEQ * DM / 4;
        cvt_bf16<<<(n4 + 1023) / 1024, 256>>>((const float4*)hidden, (uint2*)p_hb, n4);
        n4 = 8 * DM * 3 * DM / 4;
        cvt_w<<<(n4 + 1023) / 1024, 256>>>((const float4*)Wqkv, (uint2*)(p_wb + WB_QKV),
                                           n4, DM * 3 * DM / 4);
        n4 = 8 * DM * DM / 4;
        cvt_w<<<(n4 + 1023) / 1024, 256>>>((const float4*)Wo, (uint2*)(p_wb + WB_WO),
                                           n4, DM * DM / 4);
        int tg = 8 * DM * (INTER / 4);
        cvt_wgu<<<(tg + 511) / 512, 256>>>(Wgu, p_wb + WB_GU, tg);
        n4 = 8 * INTER * DM / 4;
        cvt_w<<<(n4 + 1023) / 1024, 256>>>((const float4*)Wd, (uint2*)(p_wb + WB_WD),
                                           n4, INTER * DM / 4);
    }

    // qkv = x @ Wqkv[e]   (bf16 out, RoPE + q-scale fused)
    gemm_bf<1><<<dim3(3072 / 128, SEQ / 128, NSAMP), 256, GEMM_SMEM>>>(
        p_hb, p_wb + WB_QKV, p_qkvb, 3 * DM, DM, DM,
        (long long)SEQ * DM, 1, (long long)SEQ * 3 * DM, nullptr, 0, 0, cosb, sinb);

    // fused attention -> g_ctxb (bf16), Q tile 64
    flash_kernel<<<dim3(SEQ / 64, NSAMP * HN), 128, FLASH_SMEM>>>();

    // g_ao = hidden + ctx @ Wo[e]   (fp32 out + residual)
    gemm_bf<3><<<dim3(DM / 128, SEQ / 128, NSAMP), 256, GEMM_SMEM>>>(
        p_ctxb, p_wb + WB_WO, p_ao, DM, DM, DM,
        (long long)SEQ * DM, 0, (long long)SEQ * DM, hidden, 1, 0, nullptr, nullptr);

    // x1b + g_scale = rmsnorm(g_ao)
    resid_rms_kernel<<<NSAMP * SEQ, 256>>>();

    // act = silu(gate)*up fused into Wgu GEMM (interleaved weights)
    gemm_bf<2><<<dim3(2 * INTER / 128, SEQ / 128, NSAMP), 256, GEMM_SMEM>>>(
        p_x1b, p_wb + WB_GU, p_actb, 2 * INTER, DM, DM,
        (long long)SEQ * DM, 0, (long long)SEQ * INTER, nullptr, 0, 0, nullptr, nullptr);

    // g_mlp = x1 + act @ Wd[e]   (fp32 out + residual = g_ao * g_scale)
    gemm_bf<3><<<dim3(DM / 128, SEQ / 128, NSAMP), 256, GEMM_SMEM>>>(
        p_actb, p_wb + WB_WD, p_mlp, DM, INTER, INTER,
        (long long)SEQ * INTER, 0, (long long)SEQ * DM, p_ao, 0, 1, nullptr, nullptr);

    // out = sum of weighted rmsnorm(g_mlp)
    final_kernel<<<BATCH * SEQ, 256>>>(out);
}

// round 17
// speedup vs baseline: 1.0673x; 1.0065x over previous
#include <cuda_runtime.h>
#include <cuda_bf16.h>
#include <math.h>
#include <stdint.h>

#define SEQ   1024
#define DM    1024
#define HN    16
#define HDIM  64
#define NSAMP 8
#define INTER 768
#define BATCH 4
#define EPS   1e-5f
#define LOG2E 1.4426950408889634f

typedef __nv_bfloat16 bf16;

// ---------------- scratch (device globals; no allocations allowed) ----------
__device__ float g_hsmean[BATCH * DM];
__device__ float g_partial[BATCH * 16 * DM];
__device__ int   g_expert[NSAMP];
__device__ int   g_need[8];
__device__ float g_w[NSAMP];
__device__ float g_scale[NSAMP * SEQ];
__device__ bf16  g_hb[(size_t)BATCH * SEQ * DM];
__device__ bf16  g_qkvb[(size_t)NSAMP * SEQ * 3 * DM];       // 48 MB (rope+qscale·log2e fused)
__device__ bf16  g_ctxb[(size_t)NSAMP * SEQ * DM];           // 16 MB
__device__ float g_ao[(size_t)NSAMP * SEQ * DM];             // 32 MB (holds x+ao)
__device__ bf16  g_x1b[(size_t)NSAMP * SEQ * DM];            // 16 MB
__device__ bf16  g_actb[(size_t)NSAMP * SEQ * INTER];        // 12 MB
__device__ float g_mlp[(size_t)NSAMP * SEQ * DM];            // 32 MB (holds x1+mlp)
// all-expert bf16 weights (gu stored column-interleaved: 2i=gate_i, 2i+1=up_i)
#define WB_QKV 0LL
#define WB_WO  25165824LL
#define WB_GU  33554432LL
#define WB_WD  46137344LL
#define WB_TOTAL 52428800LL
__device__ bf16 g_wb[WB_TOTAL];                              // 105 MB

// ---------------- small helpers ----------------------------------------------
__device__ __forceinline__ float block_reduce_sum(float v, float* sh) {
    int tid = threadIdx.x;
    #pragma unroll
    for (int o = 16; o; o >>= 1) v += __shfl_down_sync(0xFFFFFFFFu, v, o);
    if ((tid & 31) == 0) sh[tid >> 5] = v;
    __syncthreads();
    float r = 0.f;
    if (tid < 32) {
        float x = (tid < (int)(blockDim.x >> 5)) ? sh[tid] : 0.f;
        #pragma unroll
        for (int o = 16; o; o >>= 1) x += __shfl_down_sync(0xFFFFFFFFu, x, o);
        if (tid == 0) sh[0] = x;
    }
    __syncthreads();
    r = sh[0];
    __syncthreads();
    return r;
}

__device__ __forceinline__ void mma_bf16(float* d, const uint32_t* a, const uint32_t* b) {
    asm volatile(
        "mma.sync.aligned.m16n8k16.row.col.f32.bf16.bf16.f32 "
        "{%0,%1,%2,%3},{%4,%5,%6,%7},{%8,%9},{%0,%1,%2,%3};"
        : "+f"(d[0]), "+f"(d[1]), "+f"(d[2]), "+f"(d[3])
        : "r"(a[0]), "r"(a[1]), "r"(a[2]), "r"(a[3]), "r"(b[0]), "r"(b[1]));
}

__device__ __forceinline__ void ldsm_x4(uint32_t* r, uint32_t addr) {
    asm volatile(
        "ldmatrix.sync.aligned.m8n8.x4.shared.b16 {%0,%1,%2,%3}, [%4];"
        : "=r"(r[0]), "=r"(r[1]), "=r"(r[2]), "=r"(r[3]) : "r"(addr));
}
__device__ __forceinline__ void ldsm_x4t(uint32_t* r, uint32_t addr) {
    asm volatile(
        "ldmatrix.sync.aligned.m8n8.x4.trans.shared.b16 {%0,%1,%2,%3}, [%4];"
        : "=r"(r[0]), "=r"(r[1]), "=r"(r[2]), "=r"(r[3]) : "r"(addr));
}
__device__ __forceinline__ uint32_t packbf(float hi, float lo) {
    uint32_t r;
    asm("cvt.rn.bf16x2.f32 %0, %1, %2;" : "=r"(r) : "f"(hi), "f"(lo));
    return r;
}
__device__ __forceinline__ float ex2(float x) {
    float r;
    asm("ex2.approx.f32 %0, %1;" : "=f"(r) : "f"(x));
    return r;
}

__device__ __forceinline__ void cp16(uint32_t s, const void* g) {
    asm volatile("cp.async.cg.shared.global [%0], [%1], 16;" :: "r"(s), "l"(g));
}
__device__ __forceinline__ void cp_commit() {
    asm volatile("cp.async.commit_group;" ::: "memory");
}
__device__ __forceinline__ void cp_wait0() {
    asm volatile("cp.async.wait_group 0;" ::: "memory");
}
__device__ __forceinline__ void cp_wait1() {
    asm volatile("cp.async.wait_group 1;" ::: "memory");
}

// ---------------- fp32 -> bf16 conversion (ILP-4) ------------------------------
__global__ void cvt_bf16(const float4* __restrict__ s, uint2* __restrict__ d, int n4) {
    int base = blockIdx.x * (blockDim.x * 4) + threadIdx.x;
    float4 v[4];
    bool ok[4];
    #pragma unroll
    for (int u = 0; u < 4; u++) {
        int i = base + u * 256;
        ok[u] = (i < n4);
        if (ok[u]) v[u] = s[i];
    }
    #pragma unroll
    for (int u = 0; u < 4; u++) {
        if (ok[u]) {
            uint2 o;
            o.x = packbf(v[u].y, v[u].x);
            o.y = packbf(v[u].w, v[u].z);
            d[base + u * 256] = o;
        }
    }
}

// convert expert weights only if routed (g_need flag), ILP-4
__global__ void cvt_w(const float4* __restrict__ s, uint2* __restrict__ d,
                      int n4, int perExp4) {
    int base = blockIdx.x * (blockDim.x * 4) + threadIdx.x;
    float4 v[4];
    bool ok[4];
    #pragma unroll
    for (int u = 0; u < 4; u++) {
        int i = base + u * 256;
        ok[u] = (i < n4) && g_need[i / perExp4];
        if (ok[u]) v[u] = s[i];
    }
    #pragma unroll
    for (int u = 0; u < 4; u++) {
        if (ok[u]) {
            uint2 o;
            o.x = packbf(v[u].y, v[u].x);
            o.y = packbf(v[u].w, v[u].z);
            d[base + u * 256] = o;
        }
    }
}

// Wgu: convert + interleave columns (dst col 2i = gate_i, 2i+1 = up_i), ILP-2
__global__ void cvt_wgu(const float* __restrict__ W, bf16* __restrict__ dst, int total) {
    const int perE = DM * (INTER / 4);
    int base = blockIdx.x * (blockDim.x * 2) + threadIdx.x;
    float4 gv[2], uv[2];
    bool ok[2];
    int kk[2], nqq[2], ee[2];
    #pragma unroll
    for (int u = 0; u < 2; u++) {
        int i = base + u * 256;
        ok[u] = false;
        if (i < total) {
            int e = i / perE;
            if (g_need[e]) {
                int rem = i % perE;
                kk[u] = rem / (INTER / 4);
                nqq[u] = rem % (INTER / 4);
                ee[u] = e;
                const float* row = W + ((size_t)e * DM + kk[u]) * (2 * INTER);
                gv[u] = *(const float4*)(row + nqq[u] * 4);
                uv[u] = *(const float4*)(row + INTER + nqq[u] * 4);
                ok[u] = true;
            }
        }
    }
    #pragma unroll
    for (int u = 0; u < 2; u++) {
        if (ok[u]) {
            uint4 o;
            o.x = packbf(uv[u].x, gv[u].x);
            o.y = packbf(uv[u].y, gv[u].y);
            o.z = packbf(uv[u].z, gv[u].z);
            o.w = packbf(uv[u].w, gv[u].w);
            *(uint4*)(dst + ((size_t)ee[u] * DM + kk[u]) * (2 * INTER) + nqq[u] * 8) = o;
        }
    }
}

// ---------------- routing ----------------------------------------------------
__global__ void mean1_kernel(const float* __restrict__ hidden) {
    int b = blockIdx.x, c = blockIdx.y;
    int tid = threadIdx.x;
    float acc[4] = {0.f, 0.f, 0.f, 0.f};
    for (int s = c * 64; s < c * 64 + 64; s++) {
        const float* row = hidden + ((size_t)b * SEQ + s) * DM;
        #pragma unroll
        for (int i = 0; i < 4; i++) acc[i] += row[tid + i * 256];
    }
    #pragma unroll
    for (int i = 0; i < 4; i++)
        g_partial[((size_t)b * 16 + c) * DM + tid + i * 256] = acc[i];
}

__global__ void mean2_kernel() {
    int b = blockIdx.x;
    int tid = threadIdx.x;
    #pragma unroll
    for (int i = 0; i < 4; i++) {
        int d = tid + i * 256;
        float s = 0.f;
        for (int c = 0; c < 16; c++) s += g_partial[((size_t)b * 16 + c) * DM + d];
        g_hsmean[b * DM + d] = s * (1.0f / (float)SEQ);
    }
}

__global__ void routing_kernel(const float* __restrict__ Wr,
                               const float* __restrict__ temperature,
                               float* __restrict__ out_logits) {
    int tid = threadIdx.x;          // 1024
    int w = tid >> 5, lane = tid & 31;
    int b = w >> 3, c = w & 7;
    float s = 0.f;
    for (int d = lane; d < DM; d += 32)
        s += g_hsmean[b * DM + d] * Wr[c * DM + d];
    #pragma unroll
    for (int o = 16; o; o >>= 1) s += __shfl_down_sync(0xFFFFFFFFu, s, o);
    __shared__ float logits[32];
    if (lane == 0) logits[w] = s;
    if (tid < 8) g_need[tid] = 0;
    __syncthreads();
    if (tid < BATCH) {
        float t = fminf(fmaxf(temperature[0], 0.1f), 10.0f);
        float lv[8];
        #pragma unroll
        for (int cc = 0; cc < 8; cc++) {
            lv[cc] = logits[tid * 8 + cc] / t;
            out_logits[tid * 8 + cc] = lv[cc];
        }
        int i0 = 0;
        #pragma unroll
        for (int cc = 1; cc < 8; cc++) if (lv[cc] > lv[i0]) i0 = cc;
        int i1 = -1;
        #pragma unroll
        for (int cc = 0; cc < 8; cc++) {
            if (cc == i0) continue;
            if (i1 < 0 || lv[cc] > lv[i1]) i1 = cc;
        }
        float e = expf(lv[i1] - lv[i0]);
        g_expert[2 * tid]     = i0;
        g_expert[2 * tid + 1] = i1;
        g_w[2 * tid]     = 1.0f / (1.0f + e);
        g_w[2 * tid + 1] = e / (1.0f + e);
        g_need[i0] = 1;
        g_need[i1] = 1;
    }
}

// ---------------- bf16 tensor-core GEMM ----------------------------------------
// BM=BN=128, BK=64, 3-stage cp.async, 2 CTA/SM. B frags via ldsm.x4.trans pairs.
// MODE 1: bf16 out + fused RoPE (q scaled by 0.125*log2e: softmax in exp2 domain).
// MODE 2: fused silu(gate)*up. MODE 3: fp32 out + residual.
#define ASTG 144
#define BSTG 272
#define ABYTES (128 * ASTG)
#define BBYTES (64 * BSTG)
#define STGB (ABYTES + BBYTES)
#define GEMM_SMEM (3 * STGB)

template<int MODE>
__global__ __launch_bounds__(256, 2) void gemm_bf(
    const bf16* __restrict__ Ab, const bf16* __restrict__ Bb, void* __restrict__ Cb,
    int N, int K, int lda, long long strideA, int a_div2, long long strideC,
    const float* __restrict__ Res, int r_div2, int useScale,
    const float* __restrict__ cosp, const float* __restrict__ sinp)
{
    constexpr int MI = (MODE == 1) ? 2 : 4;
    constexpr int NJ = (MODE == 1) ? 8 : 4;

    extern __shared__ char smraw[];
    uint32_t sb = (uint32_t)__cvta_generic_to_shared(smraw);
    int z = blockIdx.z;
    const bf16* A = Ab + (size_t)(a_div2 ? (z >> 1) : z) * strideA;
    const bf16* B = Bb + (long long)g_expert[z] * ((long long)K * N);
    int m0 = blockIdx.y * 128;
    int n0 = blockIdx.x * 128;
    int tid = threadIdx.x, lane = tid & 31, wid = tid >> 5;
    int wm0, wn0;
    if (MODE == 1) { wm0 = (wid & 3) * 32; wn0 = (wid >> 2) * 64; }
    else           { wm0 = (wid & 1) * 64; wn0 = (wid >> 1) * 32; }
    int g = lane >> 2, t = lane & 3;

    auto load_tile = [&](int k0, int buf) {
        uint32_t base = sb + (uint32_t)(buf * STGB);
        #pragma unroll
        for (int p = 0; p < 4; p++) {
            int i = tid + p * 256;
            int row = i >> 3, ch = i & 7;
            cp16(base + (uint32_t)(row * ASTG + ch * 16),
                 A + (size_t)(m0 + row) * lda + k0 + ch * 8);
        }
        #pragma unroll
        for (int p = 0; p < 4; p++) {
            int i = tid + p * 256;
            int row = i >> 4, ch = i & 15;
            cp16(base + (uint32_t)(ABYTES + row * BSTG + ch * 16),
                 B + (size_t)(k0 + row) * N + n0 + ch * 8);
        }
    };

    int NT = K / 64;
    load_tile(0, 0);
    cp_commit();
    load_tile(64, 1);
    cp_commit();

    float acc[MI][NJ][4];
    #pragma unroll
    for (int i = 0; i < MI; i++)
        #pragma unroll
        for (int j = 0; j < NJ; j++)
            #pragma unroll
            for (int q = 0; q < 4; q++) acc[i][j][q] = 0.f;

    uint32_t af[2][MI][4];
    uint32_t bfr[2][NJ][2];

    // B ldsm.x4.trans lane addressing: lanes 0-15 -> n-tile j, 16-31 -> n-tile j+1
    uint32_t bLane = (uint32_t)((lane & 15) * BSTG + (lane >> 4) * 16 + wn0 * 2);

    int buf = 0;
    for (int tI = 0; tI < NT; ++tI) {
        if (tI + 1 < NT) cp_wait1(); else cp_wait0();
        __syncthreads();
        if (tI + 2 < NT) {
            int nb = buf + 2; if (nb >= 3) nb -= 3;
            load_tile((tI + 2) * 64, nb);
            cp_commit();
        }
        uint32_t stage = sb + (uint32_t)(buf * STGB);
        uint32_t aB = stage + (uint32_t)((wm0 + (lane & 15)) * ASTG + (lane >> 4) * 16);
        uint32_t bB = stage + (uint32_t)ABYTES + bLane;

        #pragma unroll
        for (int i = 0; i < MI; i++) ldsm_x4(af[0][i], aB + (uint32_t)(i * 16 * ASTG));
        #pragma unroll
        for (int j = 0; j < NJ; j += 2)
            ldsm_x4t(&bfr[0][j][0], bB + (uint32_t)(j * 16));

        #pragma unroll
        for (int ks = 0; ks < 4; ks++) {
            int cb = ks & 1, nb2 = cb ^ 1;
            if (ks < 3) {
                #pragma unroll
                for (int i = 0; i < MI; i++)
                    ldsm_x4(af[nb2][i], aB + (uint32_t)(i * 16 * ASTG + (ks + 1) * 32));
                #pragma unroll
                for (int j = 0; j < NJ; j += 2)
                    ldsm_x4t(&bfr[nb2][j][0], bB + (uint32_t)((ks + 1) * 16 * BSTG + j * 16));
            }
            #pragma unroll
            for (int i = 0; i < MI; i++)
                #pragma unroll
                for (int j = 0; j < NJ; j++)
                    mma_bf16(acc[i][j], af[cb][i], bfr[cb][j]);
        }
        buf++; if (buf == 3) buf = 0;
    }

    if (MODE == 1) {
        bf16* C = (bf16*)Cb + (size_t)z * strideC;
        bool isv = (n0 + wn0) >= 2 * DM;      // v columns: no rope
        bool isq = (n0 + wn0) < DM;           // q columns: 1/8 attn scale * log2e
        float qs = isq ? (0.125f * LOG2E) : 1.0f;
        #pragma unroll
        for (int i = 0; i < MI; i++) {
            int r = m0 + wm0 + i * 16 + g;
            if (isv) {
                #pragma unroll
                for (int j = 0; j < NJ; j++) {
                    int c = n0 + wn0 + j * 8 + 2 * t;
                    *(uint32_t*)(C + (size_t)r * N + c) = packbf(acc[i][j][1], acc[i][j][0]);
                    *(uint32_t*)(C + (size_t)(r + 8) * N + c) = packbf(acc[i][j][3], acc[i][j][2]);
                }
            } else {
                #pragma unroll
                for (int j = 0; j < 4; j++) {
                    int hc = j * 8 + 2 * t;            // [0,32)
                    int c = n0 + wn0 + hc;
                    float2 cl0 = *(const float2*)(cosp + r * HDIM + hc);
                    float2 sl0 = *(const float2*)(sinp + r * HDIM + hc);
                    float2 ch0 = *(const float2*)(cosp + r * HDIM + hc + 32);
                    float2 sh0 = *(const float2*)(sinp + r * HDIM + hc + 32);
                    float2 cl1 = *(const float2*)(cosp + (r + 8) * HDIM + hc);
                    float2 sl1 = *(const float2*)(sinp + (r + 8) * HDIM + hc);
                    float2 ch1 = *(const float2*)(cosp + (r + 8) * HDIM + hc + 32);
                    float2 sh1 = *(const float2*)(sinp + (r + 8) * HDIM + hc + 32);
                    float alo0 = acc[i][j][0], alo1 = acc[i][j][1];
                    float ahi0 = acc[i][j + 4][0], ahi1 = acc[i][j + 4][1];
                    float blo0 = acc[i][j][2], blo1 = acc[i][j][3];
                    float bhi0 = acc[i][j + 4][2], bhi1 = acc[i][j + 4][3];
                    *(uint32_t*)(C + (size_t)r * N + c) =
                        packbf((alo1 * cl0.y - ahi1 * sl0.y) * qs,
                               (alo0 * cl0.x - ahi0 * sl0.x) * qs);
                    *(uint32_t*)(C + (size_t)r * N + c + 32) =
                        packbf((ahi1 * ch0.y + alo1 * sh0.y) * qs,
                               (ahi0 * ch0.x + alo0 * sh0.x) * qs);
                    *(uint32_t*)(C + (size_t)(r + 8) * N + c) =
                        packbf((blo1 * cl1.y - bhi1 * sl1.y) * qs,
                               (blo0 * cl1.x - bhi0 * sl1.x) * qs);
                    *(uint32_t*)(C + (size_t)(r + 8) * N + c + 32) =
                        packbf((bhi1 * ch1.y + blo1 * sh1.y) * qs,
                               (bhi0 * ch1.x + blo0 * sh1.x) * qs);
                }
            }
        }
    } else {
        #pragma unroll
        for (int i = 0; i < MI; i++) {
            int r = m0 + wm0 + i * 16 + g;
            float sc0 = 1.0f, sc1 = 1.0f;
            if (MODE == 3 && useScale) {
                sc0 = g_scale[z * SEQ + r];
                sc1 = g_scale[z * SEQ + r + 8];
            }
            #pragma unroll
            for (int j = 0; j < NJ; j++) {
                int c = n0 + wn0 + j * 8 + 2 * t;
                if (MODE == 2) {
                    bf16* C = (bf16*)Cb + (size_t)z * strideC;
                    int oc = c >> 1;
                    float g0 = acc[i][j][0], u0 = acc[i][j][1];
                    float g1 = acc[i][j][2], u1 = acc[i][j][3];
                    float s0 = g0 / (1.0f + __expf(-g0)) * u0;
                    float s1 = g1 / (1.0f + __expf(-g1)) * u1;
                    C[(size_t)r * (N / 2) + oc]       = __float2bfloat16(s0);
                    C[(size_t)(r + 8) * (N / 2) + oc] = __float2bfloat16(s1);
                } else {  // MODE 3
                    float* C = (float*)Cb + (size_t)z * strideC;
                    const float* R = Res + (size_t)(r_div2 ? (z >> 1) : z) * strideC;
                    float2 r0 = *(const float2*)(R + (size_t)r * N + c);
                    float2 r1 = *(const float2*)(R + (size_t)(r + 8) * N + c);
                    *(float2*)(C + (size_t)r * N + c) =
                        make_float2(acc[i][j][0] + r0.x * sc0, acc[i][j][1] + r0.y * sc0);
                    *(float2*)(C + (size_t)(r + 8) * N + c) =
                        make_float2(acc[i][j][2] + r1.x * sc1, acc[i][j][3] + r1.y * sc1);
                }
            }
        }
    }
}

// ---------------- flash attention (bf16 mma, Q tile 64, 128 thr) ----------------
// Scores arrive in the exp2 domain (Q pre-scaled by 0.125*log2e): softmax uses
// bare ex2.approx, no per-element multiply.
#define FQ 0
#define FK 9216
#define FV (9216 * 3)
#define FLASH_SMEM (9216 * 5)

__global__ __launch_bounds__(128) void flash_kernel() {
    extern __shared__ char smraw[];
    uint32_t sb = (uint32_t)__cvta_generic_to_shared(smraw);

    int nh = blockIdx.y;
    int n = nh >> 4, h = nh & 15;
    int q0 = blockIdx.x * 64;
    const bf16* qbase = g_qkvb + (size_t)n * SEQ * (3 * DM) + h * HDIM;
    const bf16* kbase = qbase + DM;
    const bf16* vbase = qbase + 2 * DM;

    int tid = threadIdx.x, lane = tid & 31, wid = tid >> 5;
    int g = lane >> 2, t = lane & 3;
    int wm0 = wid * 16;

    // per-lane ldsm address components
    int rowL = (lane & 7) + ((lane >> 4) << 3);
    int colL = ((lane >> 3) & 1) * 16;
    uint32_t kLane = (uint32_t)(rowL * 144 + colL);                    // QK^T (x4)
    uint32_t vLane = (uint32_t)((lane & 15) * 144 + (lane >> 4) * 16); // P@V (x4t)

    #pragma unroll
    for (int p = 0; p < 4; p++) {
        int i = tid + p * 128;
        int row = i >> 3, ch = i & 7;
        cp16(sb + (uint32_t)(FQ + row * 144 + ch * 16),
             qbase + (size_t)(q0 + row) * (3 * DM) + ch * 8);
        cp16(sb + (uint32_t)(FK + row * 144 + ch * 16),
             kbase + (size_t)row * (3 * DM) + ch * 8);
        cp16(sb + (uint32_t)(FV + row * 144 + ch * 16),
             vbase + (size_t)row * (3 * DM) + ch * 8);
    }
    cp_commit();
    cp_wait0();
    __syncthreads();

    uint32_t qf[4][4];
    uint32_t qA = sb + (uint32_t)(FQ + (wm0 + (lane & 15)) * 144 + (lane >> 4) * 16);
    #pragma unroll
    for (int kc = 0; kc < 4; kc++) ldsm_x4(qf[kc], qA + (uint32_t)(kc * 32));

    float m0 = -INFINITY, m1 = -INFINITY, l0 = 0.f, l1 = 0.f;
    float oa[8][4];
    #pragma unroll
    for (int j = 0; j < 8; j++)
        #pragma unroll
        for (int q = 0; q < 4; q++) oa[j][q] = 0.f;

    const int NT = SEQ / 64;
    for (int it = 0; it < NT; it++) {
        int buf = it & 1;
        if (it + 1 < NT) {
            int kv = (it + 1) * 64;
            int ob = buf ^ 1;
            #pragma unroll
            for (int p = 0; p < 4; p++) {
                int i = tid + p * 128;
                int row = i >> 3, ch = i & 7;
                cp16(sb + (uint32_t)(FK + ob * 9216 + row * 144 + ch * 16),
                     kbase + (size_t)(kv + row) * (3 * DM) + ch * 8);
                cp16(sb + (uint32_t)(FV + ob * 9216 + row * 144 + ch * 16),
                     vbase + (size_t)(kv + row) * (3 * DM) + ch * 8);
            }
            cp_commit();
        }
        uint32_t kB = sb + (uint32_t)(FK + buf * 9216) + kLane;
        uint32_t vB = sb + (uint32_t)(FV + buf * 9216) + vLane;

        float sacc[8][4];
        #pragma unroll
        for (int j = 0; j < 8; j++)
            #pragma unroll
            for (int q = 0; q < 4; q++) sacc[j][q] = 0.f;

        #pragma unroll
        for (int kc = 0; kc < 4; kc++) {
            #pragma unroll
            for (int ntp = 0; ntp < 4; ntp++) {
                uint32_t bb[4];
                ldsm_x4(bb, kB + (uint32_t)(ntp * 16 * 144 + kc * 32));
                mma_bf16(sacc[2 * ntp],     qf[kc], bb);
                mma_bf16(sacc[2 * ntp + 1], qf[kc], bb + 2);
            }
        }

        float rm0 = -INFINITY, rm1 = -INFINITY;
        #pragma unroll
        for (int nt = 0; nt < 8; nt++) {
            rm0 = fmaxf(rm0, fmaxf(sacc[nt][0], sacc[nt][1]));
            rm1 = fmaxf(rm1, fmaxf(sacc[nt][2], sacc[nt][3]));
        }
        rm0 = fmaxf(rm0, __shfl_xor_sync(0xFFFFFFFFu, rm0, 1));
        rm0 = fmaxf(rm0, __shfl_xor_sync(0xFFFFFFFFu, rm0, 2));
        rm1 = fmaxf(rm1, __shfl_xor_sync(0xFFFFFFFFu, rm1, 1));
        rm1 = fmaxf(rm1, __shfl_xor_sync(0xFFFFFFFFu, rm1, 2));
        float mn0 = fmaxf(m0, rm0), mn1 = fmaxf(m1, rm1);
        float c0 = ex2(m0 - mn0), c1 = ex2(m1 - mn1);
        float ls0 = 0.f, ls1 = 0.f;
        #pragma unroll
        for (int nt = 0; nt < 8; nt++) {
            sacc[nt][0] = ex2(sacc[nt][0] - mn0);
            sacc[nt][1] = ex2(sacc[nt][1] - mn0);
            sacc[nt][2] = ex2(sacc[nt][2] - mn1);
            sacc[nt][3] = ex2(sacc[nt][3] - mn1);
            ls0 += sacc[nt][0] + sacc[nt][1];
            ls1 += sacc[nt][2] + sacc[nt][3];
        }
        ls0 += __shfl_xor_sync(0xFFFFFFFFu, ls0, 1);
        ls0 += __shfl_xor_sync(0xFFFFFFFFu, ls0, 2);
        ls1 += __shfl_xor_sync(0xFFFFFFFFu, ls1, 1);
        ls1 += __shfl_xor_sync(0xFFFFFFFFu, ls1, 2);
        l0 = l0 * c0 + ls0;
        l1 = l1 * c1 + ls1;
        m0 = mn0; m1 = mn1;
        #pragma unroll
        for (int j = 0; j < 8; j++) {
            oa[j][0] *= c0; oa[j][1] *= c0;
            oa[j][2] *= c1; oa[j][3] *= c1;
        }

        #pragma unroll
        for (int mC = 0; mC < 4; mC++) {
            uint32_t pa[4];
            pa[0] = packbf(sacc[2 * mC][1],     sacc[2 * mC][0]);
            pa[1] = packbf(sacc[2 * mC][3],     sacc[2 * mC][2]);
            pa[2] = packbf(sacc[2 * mC + 1][1], sacc[2 * mC + 1][0]);
            pa[3] = packbf(sacc[2 * mC + 1][3], sacc[2 * mC + 1][2]);
            #pragma unroll
            for (int jn = 0; jn < 8; jn += 2) {
                uint32_t vb4[4];
                ldsm_x4t(vb4, vB + (uint32_t)(mC * 16 * 144 + jn * 16));
                mma_bf16(oa[jn],     pa, vb4);
                mma_bf16(oa[jn + 1], pa, vb4 + 2);
            }
        }

        cp_wait0();
        __syncthreads();
    }

    float inv0 = 1.0f / l0, inv1 = 1.0f / l1;
    int grow0 = q0 + wm0 + g;
    bf16* cbase = g_ctxb + (size_t)n * SEQ * DM + h * HDIM;
    #pragma unroll
    for (int jn = 0; jn < 8; jn++) {
        int col = jn * 8 + 2 * t;
        *(uint32_t*)(cbase + (size_t)grow0 * DM + col) =
            packbf(oa[jn][1] * inv0, oa[jn][0] * inv0);
        *(uint32_t*)(cbase + (size_t)(grow0 + 8) * DM + col) =
            packbf(oa[jn][3] * inv1, oa[jn][2] * inv1);
    }
}

// ---------------- rmsnorm of (x+ao): writes x1b (bf16) + per-row scale ----------
__global__ void resid_rms_kernel() {
    __shared__ float sh[32];
    int ns = blockIdx.x;
    int tid = threadIdx.x;           // 256
    int d0 = tid * 4;
    size_t base = (size_t)ns * DM;
    float4 y = *(const float4*)(g_ao + base + d0);
    float ss = y.x * y.x + y.y * y.y + y.z * y.z + y.w * y.w;
    ss = block_reduce_sum(ss, sh);
    float scale = rsqrtf(ss * (1.0f / (float)DM) + EPS);
    if (tid == 0) g_scale[ns] = scale;
    y.x *= scale; y.y *= scale; y.z *= scale; y.w *= scale;
    uint2 o;
    o.x = packbf(y.y, y.x);
    o.y = packbf(y.w, y.z);
    *(uint2*)(g_x1b + base + d0) = o;
}

// ---------------- final: rmsnorm(x1+mlp) (sum done in Wd epilogue) --------------
__global__ void final_kernel(float* __restrict__ out) {
    __shared__ float sh[32];
    int bs = blockIdx.x;
    int b = bs >> 10, s = bs & 1023;
    int tid = threadIdx.x;
    int n0 = 2 * b, n1 = 2 * b + 1;
    size_t base0 = ((size_t)n0 * SEQ + s) * DM;
    size_t base1 = ((size_t)n1 * SEQ + s) * DM;
    float y0[4], y1[4];
    float ss0 = 0.f, ss1 = 0.f;
    #pragma unroll
    for (int i = 0; i < 4; i++) {
        int d = tid + i * 256;
        y0[i] = g_mlp[base0 + d];
        y1[i] = g_mlp[base1 + d];
        ss0 = fmaf(y0[i], y0[i], ss0);
        ss1 = fmaf(y1[i], y1[i], ss1);
    }
    ss0 = block_reduce_sum(ss0, sh);
    ss1 = block_reduce_sum(ss1, sh);
    float r0 = rsqrtf(ss0 * (1.0f / (float)DM) + EPS) * g_w[n0];
    float r1 = rsqrtf(ss1 * (1.0f / (float)DM) + EPS) * g_w[n1];
    float* orow = out + ((size_t)b * SEQ + s) * DM;
    #pragma unroll
    for (int i = 0; i < 4; i++) {
        int d = tid + i * 256;
        orow[d] = y0[i] * r0 + y1[i] * r1;
    }
}

// ---------------- host launcher --------------------------------------------------
extern "C" void kernel_launch(void* const* d_in, const int* in_sizes, int n_in,
                              void* d_out, int out_size) {
    const float* hidden = (const float*)d_in[0];
    const float* cosb   = (const float*)d_in[1];
    const float* sinb   = (const float*)d_in[2];
    const float* Wr     = (const float*)d_in[3];
    const float* temp   = (const float*)d_in[4];
    const float* Wqkv   = (const float*)d_in[5];
    const float* Wo     = (const float*)d_in[6];
    const float* Wgu    = (const float*)d_in[7];
    const float* Wd     = (const float*)d_in[8];
    float* out = (float*)d_out;

    bf16 *p_hb, *p_qkvb, *p_ctxb, *p_x1b, *p_actb, *p_wb;
    float *p_ao, *p_mlp;
    cudaGetSymbolAddress((void**)&p_hb,   g_hb);
    cudaGetSymbolAddress((void**)&p_qkvb, g_qkvb);
    cudaGetSymbolAddress((void**)&p_ctxb, g_ctxb);
    cudaGetSymbolAddress((void**)&p_x1b,  g_x1b);
    cudaGetSymbolAddress((void**)&p_actb, g_actb);
    cudaGetSymbolAddress((void**)&p_wb,   g_wb);
    cudaGetSymbolAddress((void**)&p_ao,   g_ao);
    cudaGetSymbolAddress((void**)&p_mlp,  g_mlp);

    cudaFuncSetAttribute(flash_kernel,
                         cudaFuncAttributeMaxDynamicSharedMemorySize, FLASH_SMEM);
    cudaFuncSetAttribute((const void*)gemm_bf<1>,
                         cudaFuncAttributeMaxDynamicSharedMemorySize, GEMM_SMEM);
    cudaFuncSetAttribute((const void*)gemm_bf<2>,
                         cudaFuncAttributeMaxDynamicSharedMemorySize, GEMM_SMEM);
    cudaFuncSetAttribute((const void*)gemm_bf<3>,
                         cudaFuncAttributeMaxDynamicSharedMemorySize, GEMM_SMEM);

    // routing first (sets g_need for routed-only weight conversion)
    mean1_kernel<<<dim3(BATCH, 16), 256>>>(hidden);
    mean2_kernel<<<BATCH, 256>>>();
    routing_kernel<<<1, 1024>>>(Wr, temp, out + (size_t)BATCH * SEQ * DM);

    // bf16 conversions (ILP-4)
    {
        int n4 = BATCH * SEQ * DM / 4;
        cvt_bf16<<<(n4 + 1023) / 1024, 256>>>((const float4*)hidden, (uint2*)p_hb, n4);
        n4 = 8 * DM * 3 * DM / 4;
        cvt_w<<<(n4 + 1023) / 1024, 256>>>((const float4*)Wqkv, (uint2*)(p_wb + WB_QKV),
                                           n4, DM * 3 * DM / 4);
        n4 = 8 * DM * DM / 4;
        cvt_w<<<(n4 + 1023) / 1024, 256>>>((const float4*)Wo, (uint2*)(p_wb + WB_WO),
                                           n4, DM * DM / 4);
        int tg = 8 * DM * (INTER / 4);
        cvt_wgu<<<(tg + 511) / 512, 256>>>(Wgu, p_wb + WB_GU, tg);
        n4 = 8 * INTER * DM / 4;
        cvt_w<<<(n4 + 1023) / 1024, 256>>>((const float4*)Wd, (uint2*)(p_wb + WB_WD),
                                           n4, INTER * DM / 4);
    }

    // qkv = x @ Wqkv[e]   (bf16 out, RoPE + q-scale*log2e fused)
    gemm_bf<1><<<dim3(3072 / 128, SEQ / 128, NSAMP), 256, GEMM_SMEM>>>(
        p_hb, p_wb + WB_QKV, p_qkvb, 3 * DM, DM, DM,
        (long long)SEQ * DM, 1, (long long)SEQ * 3 * DM, nullptr, 0, 0, cosb, sinb);

    // fused attention -> g_ctxb (bf16), Q tile 64
    flash_kernel<<<dim3(SEQ / 64, NSAMP * HN), 128, FLASH_SMEM>>>();

    // g_ao = hidden + ctx @ Wo[e]   (fp32 out + residual)
    gemm_bf<3><<<dim3(DM / 128, SEQ / 128, NSAMP), 256, GEMM_SMEM>>>(
        p_ctxb, p_wb + WB_WO, p_ao, DM, DM, DM,
        (long long)SEQ * DM, 0, (long long)SEQ * DM, hidden, 1, 0, nullptr, nullptr);

    // x1b + g_scale = rmsnorm(g_ao)
    resid_rms_kernel<<<NSAMP * SEQ, 256>>>();

    // act = silu(gate)*up fused into Wgu GEMM (interleaved weights)
    gemm_bf<2><<<dim3(2 * INTER / 128, SEQ / 128, NSAMP), 256, GEMM_SMEM>>>(
        p_x1b, p_wb + WB_GU, p_actb, 2 * INTER, DM, DM,
        (long long)SEQ * DM, 0, (long long)SEQ * INTER, nullptr, 0, 0, nullptr, nullptr);

    // g_mlp = x1 + act @ Wd[e]   (fp32 out + residual = g_ao * g_scale)
    gemm_bf<3><<<dim3(DM / 128, SEQ / 128, NSAMP), 256, GEMM_SMEM>>>(
        p_actb, p_wb + WB_WD, p_mlp, DM, INTER, INTER,
        (long long)SEQ * INTER, 0, (long long)SEQ * DM, p_ao, 0, 1, nullptr, nullptr);

    // out = sum of weighted rmsnorm(g_mlp)
    final_kernel<<<BATCH * SEQ, 256>>>(out);
}